// round 2
// baseline (speedup 1.0000x reference)
#include <cuda_runtime.h>
#include <cstdint>

#define B 8
#define C 2048
#define D 128
#define J 128
#define CM2 (C - 2)   // 2046

// ---------------- scratch (device globals; no allocs allowed) ----------------
__device__ __align__(16) float g_v[B * C * D];         // v = ops @ Wv + bv
__device__ __align__(16) float g_seq[B * C * D];       // mixed rows + begin/end rows
__device__ __align__(16) float g_weighted[B * C * D];  // softmax(scores) @ v
__device__ float g_sq[B * C];
__device__ float g_sk[B * C];                          // includes ck + b_score
__device__ float g_uq[D];
__device__ float g_uk[D];
__device__ float g_c[2];                               // cq, ck+b_score
__device__ __align__(16) float g_Wc[D * D];            // W_out @ W_mix2[D:2D]
__device__ float g_bc[D];                              // b_out @ W_mix2[D:2D] + b_mix2

// ---------------- K0: precompute folded weights ----------------
// grid 129, block 128
__global__ void k_pre(const float* __restrict__ W_qkv, const float* __restrict__ b_qkv,
                      const float* __restrict__ w_score, const float* __restrict__ b_score,
                      const float* __restrict__ W_out, const float* __restrict__ b_out,
                      const float* __restrict__ W_mix2, const float* __restrict__ b_mix2) {
    int t = threadIdx.x;
    int blk = blockIdx.x;
    if (blk < D) {
        // Wc[blk][t] = sum_m W_out[blk][m] * W_mix2[D+m][t]
        float acc = 0.f;
        #pragma unroll 8
        for (int m = 0; m < D; m++) acc += W_out[blk * D + m] * W_mix2[(D + m) * D + t];
        g_Wc[blk * D + t] = acc;
    } else {
        float uq = 0.f, uk = 0.f;
        #pragma unroll 8
        for (int c = 0; c < D; c++) {
            uq += W_qkv[t * 3 * D + c] * w_score[c];
            uk += W_qkv[t * 3 * D + D + c] * w_score[D + c];
        }
        g_uq[t] = uq;
        g_uk[t] = uk;
        float bb = b_mix2[t];
        #pragma unroll 8
        for (int m = 0; m < D; m++) bb += b_out[m] * W_mix2[(D + m) * D + t];
        g_bc[t] = bb;
        __shared__ float s1[D], s2[D];
        s1[t] = b_qkv[t] * w_score[t];
        s2[t] = b_qkv[D + t] * w_score[D + t];
        __syncthreads();
        for (int off = 64; off; off >>= 1) {
            if (t < off) { s1[t] += s1[t + off]; s2[t] += s2[t + off]; }
            __syncthreads();
        }
        if (t == 0) { g_c[0] = s1[0]; g_c[1] = s2[0] + b_score[0]; }
    }
}

// ---------------- K1: v rows + sq/sk scalars ----------------
// grid B*C, block 128
__global__ void k_qkv(const float* __restrict__ ops, const float* __restrict__ W_qkv,
                      const float* __restrict__ b_qkv) {
    int row = blockIdx.x;  // b*C + i
    int t = threadIdx.x;
    __shared__ float x[D];
    __shared__ float s1[D], s2[D];
    x[t] = ops[(size_t)row * D + t];
    __syncthreads();
    float v = b_qkv[2 * D + t];
    #pragma unroll 8
    for (int k = 0; k < D; k++) v += x[k] * W_qkv[k * 3 * D + 2 * D + t];
    g_v[(size_t)row * D + t] = v;
    s1[t] = x[t] * g_uq[t];
    s2[t] = x[t] * g_uk[t];
    __syncthreads();
    for (int off = 64; off; off >>= 1) {
        if (t < off) { s1[t] += s1[t + off]; s2[t] += s2[t + off]; }
        __syncthreads();
    }
    if (t == 0) { g_sq[row] = s1[0] + g_c[0]; g_sk[row] = s2[0] + g_c[1]; }
}

// ---------------- K2a: mixed = concat(ops_i, pred, succ) @ W_mix3 + b ----------------
// grid B*512 (4 rows per block), block 128
__global__ void k_mixed(const float* __restrict__ ops, const int* __restrict__ rel,
                        const float* __restrict__ W_mix3, const float* __restrict__ b_mix3) {
    int blk = blockIdx.x;
    int b = blk >> 9;
    int i0 = (blk & 511) * 4;
    int t = threadIdx.x;
    __shared__ float cat[4][3 * D];
    int ng = CM2 - i0; if (ng > 4) ng = 4;
    for (int g = 0; g < ng; g++) {
        int i = i0 + g;
        int r0 = rel[((size_t)b * CM2 + i) * 2 + 0];
        int r1 = rel[((size_t)b * CM2 + i) * 2 + 1];
        cat[g][t]           = ops[((size_t)b * C + i) * D + t];
        cat[g][D + t]       = ops[((size_t)b * C + r0) * D + t];
        cat[g][2 * D + t]   = ops[((size_t)b * C + r1) * D + t];
    }
    __syncthreads();
    float bm = b_mix3[t];
    float a0 = bm, a1 = bm, a2 = bm, a3 = bm;
    #pragma unroll 4
    for (int k = 0; k < 3 * D; k++) {
        float w = W_mix3[k * D + t];
        a0 += cat[0][k] * w;
        a1 += cat[1][k] * w;
        a2 += cat[2][k] * w;
        a3 += cat[3][k] * w;
    }
    float acc[4] = {a0, a1, a2, a3};
    for (int g = 0; g < ng; g++)
        g_seq[((size_t)b * C + i0 + g) * D + t] = acc[g];
}

// ---------------- K2b: begin/end mean rows ----------------
// grid 2*B, block 128
__global__ void k_beginend(const float* __restrict__ ops, const int* __restrict__ bidx,
                           const int* __restrict__ eidx,
                           const float* __restrict__ W_begin, const float* __restrict__ b_begin,
                           const float* __restrict__ W_end, const float* __restrict__ b_end) {
    int b = blockIdx.x >> 1, which = blockIdx.x & 1;
    int t = threadIdx.x;
    const int* idx = which ? eidx : bidx;
    __shared__ float gm[D];
    float s = 0.f;
    for (int j = 0; j < J; j++)
        s += ops[((size_t)b * C + idx[b * J + j]) * D + t];
    gm[t] = s * (1.0f / (float)J);
    __syncthreads();
    const float* W = which ? W_end : W_begin;
    const float* bb = which ? b_end : b_begin;
    float acc = bb[t];
    #pragma unroll 8
    for (int k = 0; k < D; k++) acc += gm[k] * W[k * D + t];
    g_seq[((size_t)b * C + CM2 + which) * D + t] = acc;
}

// ---------------- K3: attention (scores + softmax + attn@v), G=4 rows / block ----------------
// grid B*512, block 128
__global__ void k_attn(const float* __restrict__ mask) {
    __shared__ float sc[4][C];     // 32 KB: scores -> probs -> (reused) partial accs
    __shared__ float red[128];
    __shared__ float stat[4];      // 1/sum per row
    int blk = blockIdx.x;
    int b = blk >> 9;
    int i0 = (blk & 511) * 4;
    int t = threadIdx.x;
    int base = b * C;

    for (int g = 0; g < 4; g++) {
        int i = i0 + g;
        float sq = g_sq[base + i];
        const float* mrow = mask + ((size_t)base + i) * C;
        float lmax = -1e30f;
        #pragma unroll 4
        for (int j = t; j < C; j += 128) {
            float s = sq + g_sk[base + j];
            s = (s >= 0.f) ? s : 0.01f * s;   // leaky_relu, slope 0.01
            s *= mrow[j];
            sc[g][j] = s;
            lmax = fmaxf(lmax, s);
        }
        red[t] = lmax;
        __syncthreads();
        for (int off = 64; off; off >>= 1) {
            if (t < off) red[t] = fmaxf(red[t], red[t + off]);
            __syncthreads();
        }
        float m = red[0];
        __syncthreads();
        float lsum = 0.f;
        #pragma unroll 4
        for (int j = t; j < C; j += 128) {
            float p = __expf(sc[g][j] - m);
            sc[g][j] = p;
            lsum += p;
        }
        red[t] = lsum;
        __syncthreads();
        for (int off = 64; off; off >>= 1) {
            if (t < off) red[t] += red[t + off];
            __syncthreads();
        }
        if (t == 0) stat[g] = 1.0f / red[0];
        __syncthreads();
    }

    // attn @ v : thread = (dq in 0..31 -> 4 d's, jp in 0..3 -> j quarter)
    int dq = t & 31;
    int jp = t >> 5;
    float4 acc[4];
    #pragma unroll
    for (int g = 0; g < 4; g++) acc[g] = make_float4(0.f, 0.f, 0.f, 0.f);
    const float4* v4 = reinterpret_cast<const float4*>(g_v) + (size_t)base * (D / 4);
    int j0 = jp * (C / 4), j1 = j0 + (C / 4);
    for (int j = j0; j < j1; j++) {
        float4 vv = v4[(size_t)j * (D / 4) + dq];
        #pragma unroll
        for (int g = 0; g < 4; g++) {
            float p = sc[g][j];
            acc[g].x += p * vv.x; acc[g].y += p * vv.y;
            acc[g].z += p * vv.z; acc[g].w += p * vv.w;
        }
    }
    __syncthreads();  // done reading sc
    float* P = &sc[0][0];  // partial[jp][g][d] : 4*4*128 floats
    #pragma unroll
    for (int g = 0; g < 4; g++) {
        int o = ((jp * 4 + g) * D) + dq * 4;
        P[o] = acc[g].x; P[o + 1] = acc[g].y; P[o + 2] = acc[g].z; P[o + 3] = acc[g].w;
    }
    __syncthreads();
    for (int idx = t; idx < 4 * D; idx += 128) {
        int g = idx >> 7, d = idx & (D - 1);
        float s = P[(0 * 4 + g) * D + d] + P[(1 * 4 + g) * D + d]
                + P[(2 * 4 + g) * D + d] + P[(3 * 4 + g) * D + d];
        g_weighted[((size_t)base + i0 + g) * D + d] = s * stat[g];
    }
}

// ---------------- K4: out = seq @ W_mix2[:D] + weighted @ Wc + bc ----------------
// grid B*512 (4 rows per block), block 128
__global__ void k_final(const float* __restrict__ W_mix2, float* __restrict__ out) {
    int blk = blockIdx.x;
    int b = blk >> 9;
    int i0 = (blk & 511) * 4;
    int t = threadIdx.x;
    __shared__ float se[4][D], we[4][D];
    for (int g = 0; g < 4; g++) {
        se[g][t] = g_seq[((size_t)b * C + i0 + g) * D + t];
        we[g][t] = g_weighted[((size_t)b * C + i0 + g) * D + t];
    }
    __syncthreads();
    float bc = g_bc[t];
    float a0 = bc, a1 = bc, a2 = bc, a3 = bc;
    #pragma unroll 4
    for (int k = 0; k < D; k++) {
        float w = W_mix2[k * D + t];
        a0 += se[0][k] * w; a1 += se[1][k] * w; a2 += se[2][k] * w; a3 += se[3][k] * w;
    }
    #pragma unroll 4
    for (int k = 0; k < D; k++) {
        float w = g_Wc[k * D + t];
        a0 += we[0][k] * w; a1 += we[1][k] * w; a2 += we[2][k] * w; a3 += we[3][k] * w;
    }
    float acc[4] = {a0, a1, a2, a3};
    for (int g = 0; g < 4; g++)
        out[((size_t)b * C + i0 + g) * D + t] = acc[g];
}

// ---------------- launch ----------------
extern "C" void kernel_launch(void* const* d_in, const int* in_sizes, int n_in,
                              void* d_out, int out_size) {
    const float* ops      = (const float*)d_in[0];
    const int*   rel      = (const int*)d_in[1];
    const int*   bidx     = (const int*)d_in[2];
    const int*   eidx     = (const int*)d_in[3];
    const float* mask     = (const float*)d_in[4];
    const float* W_begin  = (const float*)d_in[5];
    const float* b_begin  = (const float*)d_in[6];
    const float* W_end    = (const float*)d_in[7];
    const float* b_end    = (const float*)d_in[8];
    const float* W_mix3   = (const float*)d_in[9];
    const float* b_mix3   = (const float*)d_in[10];
    const float* W_qkv    = (const float*)d_in[11];
    const float* b_qkv    = (const float*)d_in[12];
    const float* w_score  = (const float*)d_in[13];
    const float* b_score  = (const float*)d_in[14];
    const float* W_out    = (const float*)d_in[15];
    const float* b_out    = (const float*)d_in[16];
    const float* W_mix2   = (const float*)d_in[17];
    const float* b_mix2   = (const float*)d_in[18];
    float* out = (float*)d_out;

    k_pre<<<129, 128>>>(W_qkv, b_qkv, w_score, b_score, W_out, b_out, W_mix2, b_mix2);
    k_qkv<<<B * C, 128>>>(ops, W_qkv, b_qkv);
    k_mixed<<<B * 512, 128>>>(ops, rel, W_mix3, b_mix3);
    k_beginend<<<2 * B, 128>>>(ops, bidx, eidx, W_begin, b_begin, W_end, b_end);
    k_attn<<<B * 512, 128>>>(mask);
    k_final<<<B * 512, 128>>>(W_mix2, out);
}

// round 3
// speedup vs baseline: 1.3506x; 1.3506x over previous
#include <cuda_runtime.h>
#include <cstdint>

#define B 8
#define C 2048
#define D 128
#define J 128
#define CM2 (C - 2)   // 2046
#define G 16          // attention rows per block

// ---------------- scratch (device globals) ----------------
__device__ __align__(16) float g_v[B * C * D];
__device__ __align__(16) float g_seq[B * C * D];
__device__ __align__(16) float g_weighted[B * C * D];
__device__ float g_sq[B * C];
__device__ float g_sk[B * C];
__device__ float g_uq[D];
__device__ float g_uk[D];
__device__ float g_c[2];
__device__ __align__(16) float g_Wc[D * D];
__device__ float g_bc[D];

// ---------------- f32x2 helpers ----------------
__device__ __forceinline__ unsigned long long pk2(float lo, float hi) {
    unsigned long long r;
    asm("mov.b64 %0, {%1, %2};" : "=l"(r) : "f"(lo), "f"(hi));
    return r;
}
__device__ __forceinline__ void fma2(unsigned long long& d, unsigned long long a,
                                     unsigned long long b) {
    asm("fma.rn.f32x2 %0, %1, %2, %0;" : "+l"(d) : "l"(a), "l"(b));
}
__device__ __forceinline__ float2 upk2(unsigned long long v) {
    float2 r;
    asm("mov.b64 {%0, %1}, %2;" : "=f"(r.x), "=f"(r.y) : "l"(v));
    return r;
}

// ---------------- K0: folded weights ----------------
__global__ void k_pre(const float* __restrict__ W_qkv, const float* __restrict__ b_qkv,
                      const float* __restrict__ w_score, const float* __restrict__ b_score,
                      const float* __restrict__ W_out, const float* __restrict__ b_out,
                      const float* __restrict__ W_mix2, const float* __restrict__ b_mix2) {
    int t = threadIdx.x;
    int blk = blockIdx.x;
    if (blk < D) {
        float acc = 0.f;
        #pragma unroll 8
        for (int m = 0; m < D; m++) acc += W_out[blk * D + m] * W_mix2[(D + m) * D + t];
        g_Wc[blk * D + t] = acc;
    } else {
        float uq = 0.f, uk = 0.f;
        #pragma unroll 8
        for (int c = 0; c < D; c++) {
            uq += W_qkv[t * 3 * D + c] * w_score[c];
            uk += W_qkv[t * 3 * D + D + c] * w_score[D + c];
        }
        g_uq[t] = uq;
        g_uk[t] = uk;
        float bb = b_mix2[t];
        #pragma unroll 8
        for (int m = 0; m < D; m++) bb += b_out[m] * W_mix2[(D + m) * D + t];
        g_bc[t] = bb;
        __shared__ float s1[D], s2[D];
        s1[t] = b_qkv[t] * w_score[t];
        s2[t] = b_qkv[D + t] * w_score[D + t];
        __syncthreads();
        for (int off = 64; off; off >>= 1) {
            if (t < off) { s1[t] += s1[t + off]; s2[t] += s2[t + off]; }
            __syncthreads();
        }
        if (t == 0) { g_c[0] = s1[0]; g_c[1] = s2[0] + b_score[0]; }
    }
}

// ---------------- K1: v rows + sq/sk, 8 rows/block ----------------
// grid B*C/8 = 2048, block 128
__global__ void k_qkv(const float* __restrict__ ops, const float* __restrict__ W_qkv,
                      const float* __restrict__ b_qkv) {
    int r0 = blockIdx.x * 8;   // global row base (rows contiguous across batches)
    int t = threadIdx.x;
    __shared__ float xs[D][8];  // transposed: xs[k][r]
    __shared__ float wr1[4][8], wr2[4][8];
    #pragma unroll
    for (int r = 0; r < 8; r++) xs[t][r] = ops[((size_t)(r0 + r)) * D + t];
    __syncthreads();

    float acc[8];
    float bq = b_qkv[2 * D + t];
    #pragma unroll
    for (int r = 0; r < 8; r++) acc[r] = bq;
    #pragma unroll 4
    for (int k = 0; k < D; k++) {
        float w = W_qkv[k * 3 * D + 2 * D + t];
        float4 xa = *(const float4*)&xs[k][0];
        float4 xb = *(const float4*)&xs[k][4];
        acc[0] += xa.x * w; acc[1] += xa.y * w; acc[2] += xa.z * w; acc[3] += xa.w * w;
        acc[4] += xb.x * w; acc[5] += xb.y * w; acc[6] += xb.z * w; acc[7] += xb.w * w;
    }
    #pragma unroll
    for (int r = 0; r < 8; r++) g_v[((size_t)(r0 + r)) * D + t] = acc[r];

    // sq/sk
    float uqv = g_uq[t], ukv = g_uk[t];
    int lane = t & 31, wid = t >> 5;
    #pragma unroll
    for (int r = 0; r < 8; r++) {
        float a = xs[t][r] * uqv;
        float bv = xs[t][r] * ukv;
        #pragma unroll
        for (int off = 16; off; off >>= 1) {
            a += __shfl_down_sync(0xffffffffu, a, off);
            bv += __shfl_down_sync(0xffffffffu, bv, off);
        }
        if (lane == 0) { wr1[wid][r] = a; wr2[wid][r] = bv; }
    }
    __syncthreads();
    if (t < 8) {
        g_sq[r0 + t] = wr1[0][t] + wr1[1][t] + wr1[2][t] + wr1[3][t] + g_c[0];
        g_sk[r0 + t] = wr2[0][t] + wr2[1][t] + wr2[2][t] + wr2[3][t] + g_c[1];
    }
}

// ---------------- K2a: mixed rows, 16 rows/block, packed ----------------
// grid B*128 = 1024, block 128
__global__ void k_mixed(const float* __restrict__ ops, const int* __restrict__ rel,
                        const float* __restrict__ W_mix3, const float* __restrict__ b_mix3) {
    int blk = blockIdx.x;
    int b = blk >> 7;
    int i0 = (blk & 127) * 16;
    int t = threadIdx.x;
    __shared__ float catT[3 * D][16];  // 24 KB
    int ng = CM2 - i0; if (ng > 16) ng = 16;
    for (int g = 0; g < 16; g++) {
        if (g < ng) {
            int i = i0 + g;
            int r0 = rel[((size_t)b * CM2 + i) * 2 + 0];
            int r1 = rel[((size_t)b * CM2 + i) * 2 + 1];
            catT[t][g]         = ops[((size_t)b * C + i) * D + t];
            catT[D + t][g]     = ops[((size_t)b * C + r0) * D + t];
            catT[2 * D + t][g] = ops[((size_t)b * C + r1) * D + t];
        } else {
            catT[t][g] = 0.f; catT[D + t][g] = 0.f; catT[2 * D + t][g] = 0.f;
        }
    }
    __syncthreads();
    float bm = b_mix3[t];
    unsigned long long acc[8];
    #pragma unroll
    for (int h = 0; h < 8; h++) acc[h] = pk2(bm, bm);
    #pragma unroll 2
    for (int k = 0; k < 3 * D; k++) {
        float w = W_mix3[k * D + t];
        unsigned long long ww = pk2(w, w);
        #pragma unroll
        for (int h = 0; h < 8; h++) {
            unsigned long long xp = *(const unsigned long long*)&catT[k][2 * h];
            fma2(acc[h], xp, ww);
        }
    }
    #pragma unroll
    for (int h = 0; h < 8; h++) {
        float2 u = upk2(acc[h]);
        int ra = i0 + 2 * h, rb = ra + 1;
        if (ra < CM2) g_seq[((size_t)b * C + ra) * D + t] = u.x;
        if (rb < CM2) g_seq[((size_t)b * C + rb) * D + t] = u.y;
    }
}

// ---------------- K2b: begin/end mean rows ----------------
// grid 2*B, block 512
__global__ void k_beginend(const float* __restrict__ ops, const int* __restrict__ bidx,
                           const int* __restrict__ eidx,
                           const float* __restrict__ W_begin, const float* __restrict__ b_begin,
                           const float* __restrict__ W_end, const float* __restrict__ b_end) {
    int b = blockIdx.x >> 1, which = blockIdx.x & 1;
    int t = threadIdx.x;
    int d = t & 127, jq = t >> 7;
    const int* idx = which ? eidx : bidx;
    __shared__ float part[4][D];
    __shared__ float gm[D];
    float s = 0.f;
    for (int j = jq * 32; j < jq * 32 + 32; j++)
        s += ops[((size_t)b * C + idx[b * J + j]) * D + d];
    part[jq][d] = s;
    __syncthreads();
    if (t < D) gm[t] = (part[0][t] + part[1][t] + part[2][t] + part[3][t]) * (1.0f / (float)J);
    __syncthreads();
    if (t < D) {
        const float* W = which ? W_end : W_begin;
        const float* bb = which ? b_end : b_begin;
        float acc = bb[t];
        #pragma unroll 8
        for (int k = 0; k < D; k++) acc += gm[k] * W[k * D + t];
        g_seq[((size_t)b * C + CM2 + which) * D + t] = acc;
    }
}

// ---------------- K3: attention, G=16 rows/block ----------------
// grid B*C/G = 1024, block 256, dyn smem G*C*4 = 128 KB
__global__ void __launch_bounds__(256, 1) k_attn(const float* __restrict__ mask) {
    extern __shared__ float sp[];      // [G][C] probs
    __shared__ float wsum[8][G];
    __shared__ float stat[G];
    int blk = blockIdx.x;
    int b = blk >> 7;
    int i0 = (blk & 127) * G;
    int t = threadIdx.x;
    int base = b * C;

    // ---- scores + exp + sums (no max pass; scores are tiny by construction) ----
    float sqv[G];
    #pragma unroll
    for (int g = 0; g < G; g++) sqv[g] = g_sq[base + i0 + g];
    float psum[G];
    #pragma unroll
    for (int g = 0; g < G; g++) psum[g] = 0.f;
    const float* mrow = mask + (size_t)(base + i0) * C;
    for (int j = t; j < C; j += 256) {
        float skj = g_sk[base + j];
        #pragma unroll
        for (int g = 0; g < G; g++) {
            float x = sqv[g] + skj;
            x = (x >= 0.f) ? x : 0.01f * x;
            x *= mrow[(size_t)g * C + j];
            float p = __expf(x);
            sp[g * C + j] = p;
            psum[g] += p;
        }
    }
    int lane = t & 31, wid = t >> 5;
    #pragma unroll
    for (int g = 0; g < G; g++) {
        float a = psum[g];
        #pragma unroll
        for (int off = 16; off; off >>= 1) a += __shfl_down_sync(0xffffffffu, a, off);
        if (lane == 0) wsum[wid][g] = a;
    }
    __syncthreads();
    if (t < G) {
        float s = 0.f;
        #pragma unroll
        for (int w = 0; w < 8; w++) s += wsum[w][t];
        stat[t] = 1.0f / s;
    }
    __syncthreads();

    // ---- attn @ v : j-packed f32x2 ----
    int d2 = t & 63;     // covers dims 2*d2, 2*d2+1
    int jp = t >> 6;     // j quarter
    unsigned long long acc[2 * G];
    #pragma unroll
    for (int i = 0; i < 2 * G; i++) acc[i] = 0ull;
    const float* vb = g_v + (size_t)base * D;
    int j0 = jp * (C / 4), je = j0 + (C / 4);
    #pragma unroll 2
    for (int j = j0; j < je; j += 2) {
        float2 fa = *(const float2*)&vb[(size_t)j * D + 2 * d2];
        float2 fb = *(const float2*)&vb[(size_t)(j + 1) * D + 2 * d2];
        unsigned long long xx = pk2(fa.x, fb.x);
        unsigned long long yy = pk2(fa.y, fb.y);
        #pragma unroll
        for (int g = 0; g < G; g++) {
            unsigned long long pj = *(const unsigned long long*)&sp[g * C + j];
            fma2(acc[2 * g + 0], pj, xx);
            fma2(acc[2 * g + 1], pj, yy);
        }
    }
    __syncthreads();   // all warps done reading sp
    #pragma unroll
    for (int g = 0; g < G; g++) {
        float2 u0 = upk2(acc[2 * g + 0]);
        float2 u1 = upk2(acc[2 * g + 1]);
        *(float2*)&sp[(jp * G + g) * D + 2 * d2] = make_float2(u0.x + u0.y, u1.x + u1.y);
    }
    __syncthreads();
    for (int idx = t; idx < G * D; idx += 256) {
        int g = idx >> 7, d = idx & 127;
        float s = sp[(0 * G + g) * D + d] + sp[(1 * G + g) * D + d]
                + sp[(2 * G + g) * D + d] + sp[(3 * G + g) * D + d];
        g_weighted[((size_t)base + i0 + g) * D + d] = s * stat[g];
    }
}

// ---------------- K4: final mix, 16 rows/block, packed ----------------
// grid 1024, block 128
__global__ void k_final(const float* __restrict__ W_mix2, float* __restrict__ out) {
    int blk = blockIdx.x;
    int b = blk >> 7;
    int i0 = (blk & 127) * 16;
    int t = threadIdx.x;
    __shared__ float seT[D][16], weT[D][16];
    for (int g = 0; g < 16; g++) {
        seT[t][g] = g_seq[((size_t)b * C + i0 + g) * D + t];
        weT[t][g] = g_weighted[((size_t)b * C + i0 + g) * D + t];
    }
    __syncthreads();
    float bc = g_bc[t];
    unsigned long long acc[8];
    #pragma unroll
    for (int h = 0; h < 8; h++) acc[h] = pk2(bc, bc);
    #pragma unroll 2
    for (int k = 0; k < D; k++) {
        float w1 = W_mix2[k * D + t];
        float w2 = g_Wc[k * D + t];
        unsigned long long w1p = pk2(w1, w1);
        unsigned long long w2p = pk2(w2, w2);
        #pragma unroll
        for (int h = 0; h < 8; h++) {
            fma2(acc[h], *(const unsigned long long*)&seT[k][2 * h], w1p);
            fma2(acc[h], *(const unsigned long long*)&weT[k][2 * h], w2p);
        }
    }
    #pragma unroll
    for (int h = 0; h < 8; h++) {
        float2 u = upk2(acc[h]);
        out[((size_t)b * C + i0 + 2 * h) * D + t] = u.x;
        out[((size_t)b * C + i0 + 2 * h + 1) * D + t] = u.y;
    }
}

// ---------------- launch ----------------
extern "C" void kernel_launch(void* const* d_in, const int* in_sizes, int n_in,
                              void* d_out, int out_size) {
    const float* ops      = (const float*)d_in[0];
    const int*   rel      = (const int*)d_in[1];
    const int*   bidx     = (const int*)d_in[2];
    const int*   eidx     = (const int*)d_in[3];
    const float* mask     = (const float*)d_in[4];
    const float* W_begin  = (const float*)d_in[5];
    const float* b_begin  = (const float*)d_in[6];
    const float* W_end    = (const float*)d_in[7];
    const float* b_end    = (const float*)d_in[8];
    const float* W_mix3   = (const float*)d_in[9];
    const float* b_mix3   = (const float*)d_in[10];
    const float* W_qkv    = (const float*)d_in[11];
    const float* b_qkv    = (const float*)d_in[12];
    const float* w_score  = (const float*)d_in[13];
    const float* b_score  = (const float*)d_in[14];
    const float* W_out    = (const float*)d_in[15];
    const float* b_out    = (const float*)d_in[16];
    const float* W_mix2   = (const float*)d_in[17];
    const float* b_mix2   = (const float*)d_in[18];
    float* out = (float*)d_out;

    static bool attr_set = false;
    if (!attr_set) {
        cudaFuncSetAttribute(k_attn, cudaFuncAttributeMaxDynamicSharedMemorySize,
                             G * C * sizeof(float));
        attr_set = true;
    }

    k_pre<<<129, 128>>>(W_qkv, b_qkv, w_score, b_score, W_out, b_out, W_mix2, b_mix2);
    k_qkv<<<B * C / 8, 128>>>(ops, W_qkv, b_qkv);
    k_mixed<<<B * 128, 128>>>(ops, rel, W_mix3, b_mix3);
    k_beginend<<<2 * B, 512>>>(ops, bidx, eidx, W_begin, b_begin, W_end, b_end);
    k_attn<<<B * C / G, 256, G * C * sizeof(float)>>>(mask);
    k_final<<<1024, 128>>>(W_mix2, out);
}

// round 4
// speedup vs baseline: 1.4358x; 1.0631x over previous
#include <cuda_runtime.h>
#include <cstdint>

#define B 8
#define C 2048
#define D 128
#define J 128
#define CM2 (C - 2)   // 2046
#define G 64          // attention rows per block
#define JT 64         // attention j tile

typedef unsigned long long ull;

// ---------------- scratch (device globals) ----------------
__device__ __align__(16) float g_v[B * C * D];
__device__ __align__(16) float g_seq[B * C * D];
__device__ __align__(16) float g_weighted[B * C * D];
__device__ float g_sq[B * C];
__device__ float g_sk[B * C];
__device__ float g_uq[D];
__device__ float g_uk[D];
__device__ float g_c[2];
__device__ __align__(16) float g_Wc[D * D];
__device__ float g_bc[D];

// ---------------- f32x2 helpers ----------------
__device__ __forceinline__ ull pk2(float lo, float hi) {
    ull r;
    asm("mov.b64 %0, {%1, %2};" : "=l"(r) : "f"(lo), "f"(hi));
    return r;
}
__device__ __forceinline__ void fma2(ull& d, ull a, ull b) {
    asm("fma.rn.f32x2 %0, %1, %2, %0;" : "+l"(d) : "l"(a), "l"(b));
}
__device__ __forceinline__ float2 upk2(ull v) {
    float2 r;
    asm("mov.b64 {%0, %1}, %2;" : "=f"(r.x), "=f"(r.y) : "l"(v));
    return r;
}

// ---------------- K0: folded weights ----------------
__global__ void k_pre(const float* __restrict__ W_qkv, const float* __restrict__ b_qkv,
                      const float* __restrict__ w_score, const float* __restrict__ b_score,
                      const float* __restrict__ W_out, const float* __restrict__ b_out,
                      const float* __restrict__ W_mix2, const float* __restrict__ b_mix2) {
    int t = threadIdx.x;
    int blk = blockIdx.x;
    if (blk < D) {
        float acc = 0.f;
        #pragma unroll 8
        for (int m = 0; m < D; m++) acc += W_out[blk * D + m] * W_mix2[(D + m) * D + t];
        g_Wc[blk * D + t] = acc;
    } else {
        float uq = 0.f, uk = 0.f;
        #pragma unroll 8
        for (int c = 0; c < D; c++) {
            uq += W_qkv[t * 3 * D + c] * w_score[c];
            uk += W_qkv[t * 3 * D + D + c] * w_score[D + c];
        }
        g_uq[t] = uq;
        g_uk[t] = uk;
        float bb = b_mix2[t];
        #pragma unroll 8
        for (int m = 0; m < D; m++) bb += b_out[m] * W_mix2[(D + m) * D + t];
        g_bc[t] = bb;
        __shared__ float s1[D], s2[D];
        s1[t] = b_qkv[t] * w_score[t];
        s2[t] = b_qkv[D + t] * w_score[D + t];
        __syncthreads();
        for (int off = 64; off; off >>= 1) {
            if (t < off) { s1[t] += s1[t + off]; s2[t] += s2[t + off]; }
            __syncthreads();
        }
        if (t == 0) { g_c[0] = s1[0]; g_c[1] = s2[0] + b_score[0]; }
    }
}

// ---------------- K1: v rows + sq/sk, 8 rows/block, f32x2 ----------------
// grid B*C/8 = 2048, block 128
__global__ void k_qkv(const float* __restrict__ ops, const float* __restrict__ W_qkv,
                      const float* __restrict__ b_qkv) {
    int r0 = blockIdx.x * 8;
    int t = threadIdx.x;
    __shared__ __align__(16) float xs[D][8];   // xs[k][r]
    __shared__ float wr1[4][8], wr2[4][8];
    #pragma unroll
    for (int r = 0; r < 8; r++) xs[t][r] = ops[((size_t)(r0 + r)) * D + t];
    __syncthreads();

    float bq = b_qkv[2 * D + t];
    ull acc[4];
    #pragma unroll
    for (int h = 0; h < 4; h++) acc[h] = pk2(bq, bq);
    #pragma unroll 4
    for (int k = 0; k < D; k++) {
        float w = W_qkv[k * 3 * D + 2 * D + t];
        ull wp = pk2(w, w);
        ulonglong2 xa = *(const ulonglong2*)&xs[k][0];
        ulonglong2 xb = *(const ulonglong2*)&xs[k][4];
        fma2(acc[0], xa.x, wp);
        fma2(acc[1], xa.y, wp);
        fma2(acc[2], xb.x, wp);
        fma2(acc[3], xb.y, wp);
    }
    #pragma unroll
    for (int h = 0; h < 4; h++) {
        float2 u = upk2(acc[h]);
        g_v[((size_t)(r0 + 2 * h)) * D + t] = u.x;
        g_v[((size_t)(r0 + 2 * h + 1)) * D + t] = u.y;
    }

    float uqv = g_uq[t], ukv = g_uk[t];
    int lane = t & 31, wid = t >> 5;
    #pragma unroll
    for (int r = 0; r < 8; r++) {
        float a = xs[t][r] * uqv;
        float bv = xs[t][r] * ukv;
        #pragma unroll
        for (int off = 16; off; off >>= 1) {
            a += __shfl_down_sync(0xffffffffu, a, off);
            bv += __shfl_down_sync(0xffffffffu, bv, off);
        }
        if (lane == 0) { wr1[wid][r] = a; wr2[wid][r] = bv; }
    }
    __syncthreads();
    if (t < 8) {
        g_sq[r0 + t] = wr1[0][t] + wr1[1][t] + wr1[2][t] + wr1[3][t] + g_c[0];
        g_sk[r0 + t] = wr2[0][t] + wr2[1][t] + wr2[2][t] + wr2[3][t] + g_c[1];
    }
}

// ---------------- K2: mixed rows (16/block) + begin/end rows merged ----------------
// grid 1024 + 16, block 128
__global__ void k_mixed(const float* __restrict__ ops, const int* __restrict__ rel,
                        const float* __restrict__ W_mix3, const float* __restrict__ b_mix3,
                        const int* __restrict__ bidx, const int* __restrict__ eidx,
                        const float* __restrict__ W_begin, const float* __restrict__ b_begin,
                        const float* __restrict__ W_end, const float* __restrict__ b_end) {
    int blk = blockIdx.x;
    int t = threadIdx.x;
    if (blk >= 1024) {
        // ---- begin/end path ----
        int e = blk - 1024;
        int b = e >> 1, which = e & 1;
        const int* idx = which ? eidx : bidx;
        __shared__ float gm[D];
        float s = 0.f;
        for (int j = 0; j < J; j++)
            s += ops[((size_t)b * C + idx[b * J + j]) * D + t];
        gm[t] = s * (1.0f / (float)J);
        __syncthreads();
        const float* W = which ? W_end : W_begin;
        const float* bb = which ? b_end : b_begin;
        float acc = bb[t];
        #pragma unroll 8
        for (int k = 0; k < D; k++) acc += gm[k] * W[k * D + t];
        g_seq[((size_t)b * C + CM2 + which) * D + t] = acc;
        return;
    }
    int b = blk >> 7;
    int i0 = (blk & 127) * 16;
    __shared__ __align__(16) float catT[3 * D][16];  // 24 KB
    int ng = CM2 - i0; if (ng > 16) ng = 16;
    for (int g = 0; g < 16; g++) {
        if (g < ng) {
            int i = i0 + g;
            int r0 = rel[((size_t)b * CM2 + i) * 2 + 0];
            int r1 = rel[((size_t)b * CM2 + i) * 2 + 1];
            catT[t][g]         = ops[((size_t)b * C + i) * D + t];
            catT[D + t][g]     = ops[((size_t)b * C + r0) * D + t];
            catT[2 * D + t][g] = ops[((size_t)b * C + r1) * D + t];
        } else {
            catT[t][g] = 0.f; catT[D + t][g] = 0.f; catT[2 * D + t][g] = 0.f;
        }
    }
    __syncthreads();
    float bm = b_mix3[t];
    ull acc[8];
    #pragma unroll
    for (int h = 0; h < 8; h++) acc[h] = pk2(bm, bm);
    #pragma unroll 2
    for (int k = 0; k < 3 * D; k++) {
        float w = W_mix3[k * D + t];
        ull ww = pk2(w, w);
        #pragma unroll
        for (int h = 0; h < 8; h++) {
            ull xp = *(const ull*)&catT[k][2 * h];
            fma2(acc[h], xp, ww);
        }
    }
    #pragma unroll
    for (int h = 0; h < 8; h++) {
        float2 u = upk2(acc[h]);
        int ra = i0 + 2 * h, rb = ra + 1;
        if (ra < CM2) g_seq[((size_t)b * C + ra) * D + t] = u.x;
        if (rb < CM2) g_seq[((size_t)b * C + rb) * D + t] = u.y;
    }
}

// ---------------- K3: attention, G=64 rows, JT=64 tiles via smem ----------------
// grid B*C/G = 256, block 256, dyn smem = (G*2*JT + JT*D)*4 = 64 KB
__global__ void __launch_bounds__(256, 2) k_attn(const float* __restrict__ mask) {
    extern __shared__ __align__(16) float sm[];
    float* sp2 = sm;                 // [G][2*JT] splatted probs: sp2[g*128 + 2*j] = {p,p}
    float* sv  = sm + G * 2 * JT;    // [JT][D] v tile
    __shared__ float ssq[G];
    __shared__ float stat[G];
    __shared__ float red[8][16];

    int blk = blockIdx.x;
    int b = blk >> 5;                // 32 blocks per batch (C/G = 32)
    int i0 = (blk & 31) * G;
    int t = threadIdx.x;
    int base = b * C;

    // phase-1 thread map: jloc = t&63 (fixed), rows g = gh + 4k, gh = t>>6
    int jloc = t & 63;
    int gh = t >> 6;
    // phase-2 thread map: dims (2*d2, 2*d2+1), rows gq*16 + r
    int d2 = t & 63;
    int gq = t >> 6;

    if (t < G) ssq[t] = g_sq[base + i0 + t];

    float rowsum[16];
    #pragma unroll
    for (int k = 0; k < 16; k++) rowsum[k] = 0.f;

    ull acc[16];
    #pragma unroll
    for (int r = 0; r < 16; r++) acc[r] = 0ull;

    const float* vsrc = g_v + (size_t)base * D;

    for (int jb = 0; jb < C; jb += JT) {
        __syncthreads();   // previous phase-2 done reading sp2/sv
        // ---- load v tile ----
        {
            const float4* src = (const float4*)(vsrc + (size_t)jb * D);
            float4* dst = (float4*)sv;
            #pragma unroll
            for (int i = 0; i < JT * D / 4 / 256; i++)
                dst[t + i * 256] = src[t + i * 256];
        }
        // ---- probs for this tile ----
        {
            float skj = g_sk[base + jb + jloc];
            #pragma unroll 4
            for (int k = 0; k < 16; k++) {
                int g = gh + 4 * k;
                float x = ssq[g] + skj;
                x = (x >= 0.f) ? x : 0.01f * x;
                x *= mask[(size_t)(base + i0 + g) * C + jb + jloc];
                float p = __expf(x);
                rowsum[k] += p;
                *(float2*)&sp2[g * (2 * JT) + 2 * jloc] = make_float2(p, p);
            }
        }
        __syncthreads();
        // ---- accumulate: acc[r] += p[g][j] * v[j][dims] ----
        const float* prow = sp2 + (gq * 16) * (2 * JT);
        #pragma unroll 2
        for (int j = 0; j < JT; j += 2) {
            ull va = *(const ull*)&sv[j * D + 2 * d2];
            ull vb = *(const ull*)&sv[(j + 1) * D + 2 * d2];
            #pragma unroll
            for (int r = 0; r < 16; r++) {
                ulonglong2 pq = *(const ulonglong2*)&prow[r * (2 * JT) + 2 * j];
                fma2(acc[r], pq.x, va);
                fma2(acc[r], pq.y, vb);
            }
        }
    }

    // ---- row-sum reduction: rows of thread t live at g = gh + 4k ----
    int lane = t & 31, wid = t >> 5;
    #pragma unroll
    for (int k = 0; k < 16; k++) {
        float a = rowsum[k];
        #pragma unroll
        for (int off = 16; off; off >>= 1) a += __shfl_down_sync(0xffffffffu, a, off);
        if (lane == 0) red[wid][k] = a;
    }
    __syncthreads();
    if (t < G) {
        int ghh = t & 3, k = t >> 2;
        stat[t] = 1.0f / (red[2 * ghh][k] + red[2 * ghh + 1][k]);
    }
    __syncthreads();

    // ---- write out ----
    #pragma unroll
    for (int r = 0; r < 16; r++) {
        int g = gq * 16 + r;
        float s = stat[g];
        float2 u = upk2(acc[r]);
        *(float2*)&g_weighted[((size_t)base + i0 + g) * D + 2 * d2] =
            make_float2(u.x * s, u.y * s);
    }
}

// ---------------- K4: final mix, 16 rows/block, packed ----------------
// grid 1024, block 128
__global__ void k_final(const float* __restrict__ W_mix2, float* __restrict__ out) {
    int blk = blockIdx.x;
    int b = blk >> 7;
    int i0 = (blk & 127) * 16;
    int t = threadIdx.x;
    __shared__ __align__(16) float seT[D][16], weT[D][16];
    for (int g = 0; g < 16; g++) {
        seT[t][g] = g_seq[((size_t)b * C + i0 + g) * D + t];
        weT[t][g] = g_weighted[((size_t)b * C + i0 + g) * D + t];
    }
    __syncthreads();
    float bc = g_bc[t];
    ull acc[8];
    #pragma unroll
    for (int h = 0; h < 8; h++) acc[h] = pk2(bc, bc);
    #pragma unroll 2
    for (int k = 0; k < D; k++) {
        float w1 = W_mix2[k * D + t];
        float w2 = g_Wc[k * D + t];
        ull w1p = pk2(w1, w1);
        ull w2p = pk2(w2, w2);
        #pragma unroll
        for (int h = 0; h < 8; h++) {
            fma2(acc[h], *(const ull*)&seT[k][2 * h], w1p);
            fma2(acc[h], *(const ull*)&weT[k][2 * h], w2p);
        }
    }
    #pragma unroll
    for (int h = 0; h < 8; h++) {
        float2 u = upk2(acc[h]);
        out[((size_t)b * C + i0 + 2 * h) * D + t] = u.x;
        out[((size_t)b * C + i0 + 2 * h + 1) * D + t] = u.y;
    }
}

// ---------------- launch ----------------
extern "C" void kernel_launch(void* const* d_in, const int* in_sizes, int n_in,
                              void* d_out, int out_size) {
    const float* ops      = (const float*)d_in[0];
    const int*   rel      = (const int*)d_in[1];
    const int*   bidx     = (const int*)d_in[2];
    const int*   eidx     = (const int*)d_in[3];
    const float* mask     = (const float*)d_in[4];
    const float* W_begin  = (const float*)d_in[5];
    const float* b_begin  = (const float*)d_in[6];
    const float* W_end    = (const float*)d_in[7];
    const float* b_end    = (const float*)d_in[8];
    const float* W_mix3   = (const float*)d_in[9];
    const float* b_mix3   = (const float*)d_in[10];
    const float* W_qkv    = (const float*)d_in[11];
    const float* b_qkv    = (const float*)d_in[12];
    const float* w_score  = (const float*)d_in[13];
    const float* b_score  = (const float*)d_in[14];
    const float* W_out    = (const float*)d_in[15];
    const float* b_out    = (const float*)d_in[16];
    const float* W_mix2   = (const float*)d_in[17];
    const float* b_mix2   = (const float*)d_in[18];
    float* out = (float*)d_out;

    const int attn_smem = (G * 2 * JT + JT * D) * sizeof(float);  // 64 KB
    static bool attr_set = false;
    if (!attr_set) {
        cudaFuncSetAttribute(k_attn, cudaFuncAttributeMaxDynamicSharedMemorySize, attn_smem);
        attr_set = true;
    }

    k_pre<<<129, 128>>>(W_qkv, b_qkv, w_score, b_score, W_out, b_out, W_mix2, b_mix2);
    k_qkv<<<B * C / 8, 128>>>(ops, W_qkv, b_qkv);
    k_mixed<<<1024 + 2 * B, 128>>>(ops, rel, W_mix3, b_mix3,
                                   bidx, eidx, W_begin, b_begin, W_end, b_end);
    k_attn<<<B * C / G, 256, attn_smem>>>(mask);
    k_final<<<1024, 128>>>(W_mix2, out);
}

// round 6
// speedup vs baseline: 2.2268x; 1.5509x over previous
#include <cuda_runtime.h>
#include <cuda_bf16.h>
#include <cstdint>

#define B 8
#define C 2048
#define D 128
#define J 128
#define CM2 (C - 2)   // 2046

typedef unsigned long long ull;

// ---------------- scratch (device globals) ----------------
__device__ __align__(16) __nv_bfloat16 g_vT[B * D * C];   // v transposed, bf16: [b][d][j]
__device__ __align__(16) float g_seq[B * C * D];
__device__ __align__(16) float g_weighted[B * C * D];
__device__ float g_colsum[B * D];                         // sum_j v_bf16[b][j][d]
__device__ float g_sq[B * C];
__device__ float g_sk[B * C];
__device__ float g_uq[D];
__device__ float g_uk[D];
__device__ float g_c[2];
__device__ __align__(16) float g_Wc[D * D];
__device__ float g_bc[D];

// ---------------- f32x2 helpers ----------------
__device__ __forceinline__ ull pk2(float lo, float hi) {
    ull r;
    asm("mov.b64 %0, {%1, %2};" : "=l"(r) : "f"(lo), "f"(hi));
    return r;
}
__device__ __forceinline__ void fma2(ull& d, ull a, ull b) {
    asm("fma.rn.f32x2 %0, %1, %2, %0;" : "+l"(d) : "l"(a), "l"(b));
}
__device__ __forceinline__ float2 upk2(ull v) {
    float2 r;
    asm("mov.b64 {%0, %1}, %2;" : "=f"(r.x), "=f"(r.y) : "l"(v));
    return r;
}
__device__ __forceinline__ uint32_t smem_u32(const void* p) {
    uint32_t a;
    asm("{ .reg .u64 tmp; cvta.to.shared.u64 tmp, %1; cvt.u32.u64 %0, tmp; }"
        : "=r"(a) : "l"(p));
    return a;
}
// pack {lo=a, hi=b} as bf16x2
#define CVT_BF16X2(res, a, b) \
    asm("cvt.rn.satfinite.bf16x2.f32 %0, %1, %2;" : "=r"(res) : "f"(b), "f"(a))
#define SWZ(x) ((x) ^ (((x) >> 3) & 0x70))

__device__ __forceinline__ void ldm_x4(uint32_t& r0, uint32_t& r1, uint32_t& r2,
                                       uint32_t& r3, uint32_t addr) {
    asm volatile("ldmatrix.sync.aligned.m8n8.x4.shared.b16 {%0,%1,%2,%3}, [%4];"
                 : "=r"(r0), "=r"(r1), "=r"(r2), "=r"(r3) : "r"(addr));
}
__device__ __forceinline__ void mma16816(float* c, uint32_t a0, uint32_t a1,
                                         uint32_t a2, uint32_t a3,
                                         uint32_t b0, uint32_t b1) {
    asm volatile(
        "mma.sync.aligned.m16n8k16.row.col.f32.bf16.bf16.f32 "
        "{%0,%1,%2,%3}, {%4,%5,%6,%7}, {%8,%9}, {%0,%1,%2,%3};"
        : "+f"(c[0]), "+f"(c[1]), "+f"(c[2]), "+f"(c[3])
        : "r"(a0), "r"(a1), "r"(a2), "r"(a3), "r"(b0), "r"(b1));
}

// ---------------- K0: folded weights ----------------
__global__ void k_pre(const float* __restrict__ W_qkv, const float* __restrict__ b_qkv,
                      const float* __restrict__ w_score, const float* __restrict__ b_score,
                      const float* __restrict__ W_out, const float* __restrict__ b_out,
                      const float* __restrict__ W_mix2, const float* __restrict__ b_mix2) {
    int t = threadIdx.x;
    int blk = blockIdx.x;
    if (blk < D) {
        float acc = 0.f;
        #pragma unroll 8
        for (int m = 0; m < D; m++) acc += W_out[blk * D + m] * W_mix2[(D + m) * D + t];
        g_Wc[blk * D + t] = acc;
    } else {
        float uq = 0.f, uk = 0.f;
        #pragma unroll 8
        for (int c = 0; c < D; c++) {
            uq += W_qkv[t * 3 * D + c] * w_score[c];
            uk += W_qkv[t * 3 * D + D + c] * w_score[D + c];
        }
        g_uq[t] = uq;
        g_uk[t] = uk;
        float bb = b_mix2[t];
        #pragma unroll 8
        for (int m = 0; m < D; m++) bb += b_out[m] * W_mix2[(D + m) * D + t];
        g_bc[t] = bb;
        __shared__ float s1[D], s2[D];
        s1[t] = b_qkv[t] * w_score[t];
        s2[t] = b_qkv[D + t] * w_score[D + t];
        __syncthreads();
        for (int off = 64; off; off >>= 1) {
            if (t < off) { s1[t] += s1[t + off]; s2[t] += s2[t + off]; }
            __syncthreads();
        }
        if (t == 0) { g_c[0] = s1[0]; g_c[1] = s2[0] + b_score[0]; }
    }
}

// ---------------- K1: v rows (bf16, transposed) + sq/sk, 8 rows/block ----------------
// grid B*C/8 = 2048, block 128
__global__ void k_qkv(const float* __restrict__ ops, const float* __restrict__ W_qkv,
                      const float* __restrict__ b_qkv) {
    int r0 = blockIdx.x * 8;
    int t = threadIdx.x;
    __shared__ __align__(16) float xs[D][8];
    __shared__ __align__(16) __nv_bfloat16 vsm[D][8];
    __shared__ float wr1[4][8], wr2[4][8];
    #pragma unroll
    for (int r = 0; r < 8; r++) xs[t][r] = ops[((size_t)(r0 + r)) * D + t];
    __syncthreads();

    float bq = b_qkv[2 * D + t];
    ull acc[4];
    #pragma unroll
    for (int h = 0; h < 4; h++) acc[h] = pk2(bq, bq);
    #pragma unroll 4
    for (int k = 0; k < D; k++) {
        float w = W_qkv[k * 3 * D + 2 * D + t];
        ull wp = pk2(w, w);
        ulonglong2 xa = *(const ulonglong2*)&xs[k][0];
        ulonglong2 xb = *(const ulonglong2*)&xs[k][4];
        fma2(acc[0], xa.x, wp);
        fma2(acc[1], xa.y, wp);
        fma2(acc[2], xb.x, wp);
        fma2(acc[3], xb.y, wp);
    }
    #pragma unroll
    for (int h = 0; h < 4; h++) {
        float2 u = upk2(acc[h]);
        vsm[t][2 * h]     = __float2bfloat16(u.x);
        vsm[t][2 * h + 1] = __float2bfloat16(u.y);
    }

    float uqv = g_uq[t], ukv = g_uk[t];
    int lane = t & 31, wid = t >> 5;
    #pragma unroll
    for (int r = 0; r < 8; r++) {
        float a = xs[t][r] * uqv;
        float bv = xs[t][r] * ukv;
        #pragma unroll
        for (int off = 16; off; off >>= 1) {
            a += __shfl_down_sync(0xffffffffu, a, off);
            bv += __shfl_down_sync(0xffffffffu, bv, off);
        }
        if (lane == 0) { wr1[wid][r] = a; wr2[wid][r] = bv; }
    }
    __syncthreads();
    int bb = r0 >> 11;
    int jl = r0 & (C - 1);
    *(uint4*)&g_vT[((size_t)bb * D + t) * C + jl] = *(const uint4*)&vsm[t][0];
    if (t < 8) {
        g_sq[r0 + t] = wr1[0][t] + wr1[1][t] + wr1[2][t] + wr1[3][t] + g_c[0];
        g_sk[r0 + t] = wr2[0][t] + wr2[1][t] + wr2[2][t] + wr2[3][t] + g_c[1];
    }
}

// ---------------- K1b: colsum of bf16 v per (batch, d) ----------------
// grid B, block 512
__global__ void k_colsum() {
    int b = blockIdx.x;
    int t = threadIdx.x;
    int d = t & 127, q = t >> 7;
    __shared__ float part[4][D];
    const __nv_bfloat162* row = (const __nv_bfloat162*)
        (g_vT + ((size_t)b * D + d) * C + q * 512);
    float s = 0.f;
    #pragma unroll 8
    for (int j = 0; j < 256; j++) {
        float2 f = __bfloat1622float2(row[j]);
        s += f.x + f.y;
    }
    part[q][d] = s;
    __syncthreads();
    if (t < D) g_colsum[b * D + t] = part[0][t] + part[1][t] + part[2][t] + part[3][t];
}

// ---------------- K2: mixed rows (16/block) + begin/end rows merged ----------------
// grid 1024 + 16, block 128
__global__ void k_mixed(const float* __restrict__ ops, const int* __restrict__ rel,
                        const float* __restrict__ W_mix3, const float* __restrict__ b_mix3,
                        const int* __restrict__ bidx, const int* __restrict__ eidx,
                        const float* __restrict__ W_begin, const float* __restrict__ b_begin,
                        const float* __restrict__ W_end, const float* __restrict__ b_end) {
    int blk = blockIdx.x;
    int t = threadIdx.x;
    if (blk >= 1024) {
        int e = blk - 1024;
        int b = e >> 1, which = e & 1;
        const int* idx = which ? eidx : bidx;
        __shared__ float gm[D];
        float s = 0.f;
        for (int j = 0; j < J; j++)
            s += ops[((size_t)b * C + idx[b * J + j]) * D + t];
        gm[t] = s * (1.0f / (float)J);
        __syncthreads();
        const float* W = which ? W_end : W_begin;
        const float* bb = which ? b_end : b_begin;
        float acc = bb[t];
        #pragma unroll 8
        for (int k = 0; k < D; k++) acc += gm[k] * W[k * D + t];
        g_seq[((size_t)b * C + CM2 + which) * D + t] = acc;
        return;
    }
    int b = blk >> 7;
    int i0 = (blk & 127) * 16;
    __shared__ __align__(16) float catT[3 * D][16];
    int ng = CM2 - i0; if (ng > 16) ng = 16;
    for (int g = 0; g < 16; g++) {
        if (g < ng) {
            int i = i0 + g;
            int r0 = rel[((size_t)b * CM2 + i) * 2 + 0];
            int r1 = rel[((size_t)b * CM2 + i) * 2 + 1];
            catT[t][g]         = ops[((size_t)b * C + i) * D + t];
            catT[D + t][g]     = ops[((size_t)b * C + r0) * D + t];
            catT[2 * D + t][g] = ops[((size_t)b * C + r1) * D + t];
        } else {
            catT[t][g] = 0.f; catT[D + t][g] = 0.f; catT[2 * D + t][g] = 0.f;
        }
    }
    __syncthreads();
    float bm = b_mix3[t];
    ull acc[8];
    #pragma unroll
    for (int h = 0; h < 8; h++) acc[h] = pk2(bm, bm);
    #pragma unroll 2
    for (int k = 0; k < 3 * D; k++) {
        float w = W_mix3[k * D + t];
        ull ww = pk2(w, w);
        #pragma unroll
        for (int h = 0; h < 8; h++) {
            ull xp = *(const ull*)&catT[k][2 * h];
            fma2(acc[h], xp, ww);
        }
    }
    #pragma unroll
    for (int h = 0; h < 8; h++) {
        float2 u = upk2(acc[h]);
        int ra = i0 + 2 * h, rb = ra + 1;
        if (ra < CM2) g_seq[((size_t)b * C + ra) * D + t] = u.x;
        if (rb < CM2) g_seq[((size_t)b * C + rb) * D + t] = u.y;
    }
}

// ---------------- K3: attention via mma.sync bf16 (HMMA) ----------------
// grid 128 (16 M-tiles of 128 rows x 8 batches), block 256 (8 warps)
// A = (p-1) probs [128m x 64k] bf16 SW128; Bv = vT [128n x 64k] bf16 SW128.
// Each warp: 16 m-rows x all 128 n, acc in registers (16 n-tiles x 4 f32).
#define KT 64
__global__ void __launch_bounds__(256) k_attn(const float* __restrict__ mask) {
    __shared__ __align__(128) char smA[128 * 128];   // 16 KB
    __shared__ __align__(128) char smB[128 * 128];   // 16 KB
    __shared__ float ssq[128];
    __shared__ float srow[128];
    __shared__ float scol[128];

    int t = threadIdx.x;
    int w = t >> 5, lane = t & 31;
    int blk = blockIdx.x;
    int b = blk >> 4;
    int i0 = (blk & 15) * 128;
    int base = b * C;

    uint32_t suA = smem_u32(smA);
    uint32_t suB = smem_u32(smB);

    if (t < 128) { ssq[t] = g_sq[base + i0 + t]; scol[t] = g_colsum[b * D + t]; }

    float rowsum[16];
    #pragma unroll
    for (int s = 0; s < 16; s++) rowsum[s] = 0.f;

    float cc[16][4];
    #pragma unroll
    for (int nt = 0; nt < 16; nt++)
        #pragma unroll
        for (int r = 0; r < 4; r++) cc[nt][r] = 0.f;

    const __nv_bfloat16* vTb = g_vT + (size_t)b * D * C;

    // ldmatrix lane-address precomputes
    int l8 = lane & 7, grp = lane >> 3;
    int rowA = (w << 4) + l8 + ((grp & 1) << 3);
    int colAg = (grp >> 1) << 4;
    int rowBoff = l8 + ((grp >> 1) << 3);
    int colBg = (grp & 1) << 4;
    int mbase = w << 4;

    for (int i = 0; i < C / KT; i++) {
        int jb = i * KT;
        __syncthreads();   // previous phase-2 done reading smA/smB

        // ---- phase 1: A tile = bf16(p-1), rows w+8s, j = jb+2*lane(+1) ----
        {
            float2 sk2 = *(const float2*)&g_sk[base + jb + 2 * lane];
            const float* mrow0 = mask + (size_t)(base + i0 + w) * C + jb + 2 * lane;
            #pragma unroll
            for (int s = 0; s < 16; s++) {
                int row = w + 8 * s;
                float2 mk = *(const float2*)(mrow0 + (size_t)(8 * s) * C);
                float q = ssq[row];
                float x0 = q + sk2.x; x0 = (x0 >= 0.f) ? x0 : 0.01f * x0; x0 *= mk.x;
                float x1 = q + sk2.y; x1 = (x1 >= 0.f) ? x1 : 0.01f * x1; x1 *= mk.y;
                float p0 = __expf(x0), p1 = __expf(x1);
                rowsum[s] += p0 + p1;
                uint32_t pr; CVT_BF16X2(pr, p0 - 1.f, p1 - 1.f);
                uint32_t off = row * 128 + lane * 4;
                *(uint32_t*)(smA + SWZ(off)) = pr;
            }
        }
        // ---- B tile: vT [128 d][64 j] ----
        #pragma unroll
        for (int c = 0; c < 4; c++) {
            int idx = t + c * 256;
            int dd = idx >> 3, ccx = idx & 7;
            uint4 val = *(const uint4*)(vTb + (size_t)dd * C + jb + ccx * 8);
            uint32_t off = dd * 128 + ccx * 16;
            *(uint4*)(smB + SWZ(off)) = val;
        }
        __syncthreads();

        // ---- phase 2: ldmatrix + mma ----
        #pragma unroll
        for (int ks = 0; ks < 4; ks++) {
            uint32_t a0, a1, a2, a3;
            ldm_x4(a0, a1, a2, a3, suA + SWZ(rowA * 128 + ks * 32 + colAg));
            #pragma unroll
            for (int nt = 0; nt < 16; nt += 2) {
                uint32_t b0, b1, b2, b3;
                int rowB = nt * 8 + rowBoff;
                ldm_x4(b0, b1, b2, b3, suB + SWZ(rowB * 128 + ks * 32 + colBg));
                mma16816(cc[nt],     a0, a1, a2, a3, b0, b1);
                mma16816(cc[nt + 1], a0, a1, a2, a3, b2, b3);
            }
        }
    }

    // ---- rowsum reduce ----
    #pragma unroll
    for (int s = 0; s < 16; s++) {
        float r = rowsum[s];
        #pragma unroll
        for (int off = 16; off; off >>= 1) r += __shfl_down_sync(0xffffffffu, r, off);
        if (lane == 0) srow[w + 8 * s] = r;
    }
    __syncthreads();

    // ---- epilogue: weighted = (colsum + S) / rowsum ----
    int quad = lane >> 2, qt = lane & 3;
    float inv0 = 1.0f / srow[mbase + quad];
    float inv8 = 1.0f / srow[mbase + quad + 8];
    float* o0 = g_weighted + (size_t)(base + i0 + mbase + quad) * D;
    float* o8 = o0 + 8 * D;
    #pragma unroll
    for (int nt = 0; nt < 16; nt++) {
        int n0 = nt * 8 + 2 * qt;
        float cs0 = scol[n0], cs1 = scol[n0 + 1];
        *(float2*)(o0 + n0) = make_float2((cs0 + cc[nt][0]) * inv0,
                                          (cs1 + cc[nt][1]) * inv0);
        *(float2*)(o8 + n0) = make_float2((cs0 + cc[nt][2]) * inv8,
                                          (cs1 + cc[nt][3]) * inv8);
    }
}

// ---------------- K4: final mix, 16 rows/block, packed ----------------
// grid 1024, block 128
__global__ void k_final(const float* __restrict__ W_mix2, float* __restrict__ out) {
    int blk = blockIdx.x;
    int b = blk >> 7;
    int i0 = (blk & 127) * 16;
    int t = threadIdx.x;
    __shared__ __align__(16) float seT[D][16], weT[D][16];
    for (int g = 0; g < 16; g++) {
        seT[t][g] = g_seq[((size_t)b * C + i0 + g) * D + t];
        weT[t][g] = g_weighted[((size_t)b * C + i0 + g) * D + t];
    }
    __syncthreads();
    float bc = g_bc[t];
    ull acc[8];
    #pragma unroll
    for (int h = 0; h < 8; h++) acc[h] = pk2(bc, bc);
    #pragma unroll 2
    for (int k = 0; k < D; k++) {
        float w1 = W_mix2[k * D + t];
        float w2 = g_Wc[k * D + t];
        ull w1p = pk2(w1, w1);
        ull w2p = pk2(w2, w2);
        #pragma unroll
        for (int h = 0; h < 8; h++) {
            fma2(acc[h], *(const ull*)&seT[k][2 * h], w1p);
            fma2(acc[h], *(const ull*)&weT[k][2 * h], w2p);
        }
    }
    #pragma unroll
    for (int h = 0; h < 8; h++) {
        float2 u = upk2(acc[h]);
        out[((size_t)b * C + i0 + 2 * h) * D + t] = u.x;
        out[((size_t)b * C + i0 + 2 * h + 1) * D + t] = u.y;
    }
}

// ---------------- launch ----------------
extern "C" void kernel_launch(void* const* d_in, const int* in_sizes, int n_in,
                              void* d_out, int out_size) {
    const float* ops      = (const float*)d_in[0];
    const int*   rel      = (const int*)d_in[1];
    const int*   bidx     = (const int*)d_in[2];
    const int*   eidx     = (const int*)d_in[3];
    const float* mask     = (const float*)d_in[4];
    const float* W_begin  = (const float*)d_in[5];
    const float* b_begin  = (const float*)d_in[6];
    const float* W_end    = (const float*)d_in[7];
    const float* b_end    = (const float*)d_in[8];
    const float* W_mix3   = (const float*)d_in[9];
    const float* b_mix3   = (const float*)d_in[10];
    const float* W_qkv    = (const float*)d_in[11];
    const float* b_qkv    = (const float*)d_in[12];
    const float* w_score  = (const float*)d_in[13];
    const float* b_score  = (const float*)d_in[14];
    const float* W_out    = (const float*)d_in[15];
    const float* b_out    = (const float*)d_in[16];
    const float* W_mix2   = (const float*)d_in[17];
    const float* b_mix2   = (const float*)d_in[18];
    float* out = (float*)d_out;

    k_pre<<<129, 128>>>(W_qkv, b_qkv, w_score, b_score, W_out, b_out, W_mix2, b_mix2);
    k_qkv<<<B * C / 8, 128>>>(ops, W_qkv, b_qkv);
    k_colsum<<<B, 512>>>();
    k_mixed<<<1024 + 2 * B, 128>>>(ops, rel, W_mix3, b_mix3,
                                   bidx, eidx, W_begin, b_begin, W_end, b_end);
    k_attn<<<128, 256>>>(mask);
    k_final<<<1024, 128>>>(W_mix2, out);
}

// round 7
// speedup vs baseline: 2.7698x; 1.2438x over previous
#include <cuda_runtime.h>
#include <cuda_bf16.h>
#include <cstdint>

#define B 8
#define C 2048
#define D 128
#define J 128
#define CM2 (C - 2)   // 2046

typedef unsigned long long ull;

// ---------------- scratch (device globals) ----------------
__device__ __align__(16) __nv_bfloat16 g_vT[B * D * C];   // v transposed, bf16: [b][d][j]
__device__ __align__(16) float g_seq[B * C * D];
__device__ __align__(16) float g_weighted[B * C * D];
__device__ float g_colsum[B * D];
__device__ float g_sq[B * C];
__device__ float g_sk[B * C];
__device__ float g_uq[D];
__device__ float g_uk[D];
__device__ float g_c[2];
__device__ __align__(16) float g_Wc[D * D];
__device__ float g_bc[D];
// split-bf16 transposed weights: W3t[n][k] (k=384), W2t[n][k] (k=256: mix2 | Wc)
__device__ __align__(16) __nv_bfloat16 g_W3h[D * 3 * D];
__device__ __align__(16) __nv_bfloat16 g_W3l[D * 3 * D];
__device__ __align__(16) __nv_bfloat16 g_W2h[D * 2 * D];
__device__ __align__(16) __nv_bfloat16 g_W2l[D * 2 * D];

// ---------------- helpers ----------------
__device__ __forceinline__ ull pk2(float lo, float hi) {
    ull r;
    asm("mov.b64 %0, {%1, %2};" : "=l"(r) : "f"(lo), "f"(hi));
    return r;
}
__device__ __forceinline__ void fma2(ull& d, ull a, ull b) {
    asm("fma.rn.f32x2 %0, %1, %2, %0;" : "+l"(d) : "l"(a), "l"(b));
}
__device__ __forceinline__ float2 upk2(ull v) {
    float2 r;
    asm("mov.b64 {%0, %1}, %2;" : "=f"(r.x), "=f"(r.y) : "l"(v));
    return r;
}
__device__ __forceinline__ uint32_t smem_u32(const void* p) {
    uint32_t a;
    asm("{ .reg .u64 tmp; cvta.to.shared.u64 tmp, %1; cvt.u32.u64 %0, tmp; }"
        : "=r"(a) : "l"(p));
    return a;
}
// pack {lo=a, hi=b} as bf16x2
#define CVT_BF16X2(res, a, b) \
    asm("cvt.rn.satfinite.bf16x2.f32 %0, %1, %2;" : "=r"(res) : "f"(b), "f"(a))
#define SWZ(x) ((x) ^ (((x) >> 3) & 0x70))

__device__ __forceinline__ void ldm_x4(uint32_t& r0, uint32_t& r1, uint32_t& r2,
                                       uint32_t& r3, uint32_t addr) {
    asm volatile("ldmatrix.sync.aligned.m8n8.x4.shared.b16 {%0,%1,%2,%3}, [%4];"
                 : "=r"(r0), "=r"(r1), "=r"(r2), "=r"(r3) : "r"(addr));
}
__device__ __forceinline__ void mma16816(float* c, uint32_t a0, uint32_t a1,
                                         uint32_t a2, uint32_t a3,
                                         uint32_t b0, uint32_t b1) {
    asm volatile(
        "mma.sync.aligned.m16n8k16.row.col.f32.bf16.bf16.f32 "
        "{%0,%1,%2,%3}, {%4,%5,%6,%7}, {%8,%9}, {%0,%1,%2,%3};"
        : "+f"(c[0]), "+f"(c[1]), "+f"(c[2]), "+f"(c[3])
        : "r"(a0), "r"(a1), "r"(a2), "r"(a3), "r"(b0), "r"(b1));
}
// split pair (x0,x1) into bf16 hi pack + bf16 lo pack
__device__ __forceinline__ void split2(float x0, float x1, uint32_t& hp, uint32_t& lp) {
    CVT_BF16X2(hp, x0, x1);
    __nv_bfloat162 hv = *reinterpret_cast<__nv_bfloat162*>(&hp);
    float f0 = __bfloat162float(hv.x), f1 = __bfloat162float(hv.y);
    CVT_BF16X2(lp, x0 - f0, x1 - f1);
}
// one K=64 GEMM pass: warp computes 16m x 128n
__device__ __forceinline__ void mma_pass(uint32_t suA, uint32_t suB, float cc[16][4],
                                         int rowA, int colAg, int rowBoff, int colBg) {
    #pragma unroll
    for (int ks = 0; ks < 4; ks++) {
        uint32_t a0, a1, a2, a3;
        ldm_x4(a0, a1, a2, a3, suA + SWZ(rowA * 128 + ks * 32 + colAg));
        #pragma unroll
        for (int nt = 0; nt < 16; nt += 2) {
            uint32_t b0, b1, b2, b3;
            ldm_x4(b0, b1, b2, b3, suB + SWZ((nt * 8 + rowBoff) * 128 + ks * 32 + colBg));
            mma16816(cc[nt],     a0, a1, a2, a3, b0, b1);
            mma16816(cc[nt + 1], a0, a1, a2, a3, b2, b3);
        }
    }
}

#define SMEM_MMA (65536 + 1024)

// ---------------- K0: folded + split/transposed weights ----------------
// grid 641, block 128
__global__ void k_pre(const float* __restrict__ W_qkv, const float* __restrict__ b_qkv,
                      const float* __restrict__ w_score, const float* __restrict__ b_score,
                      const float* __restrict__ W_out, const float* __restrict__ b_out,
                      const float* __restrict__ W_mix2, const float* __restrict__ b_mix2,
                      const float* __restrict__ W_mix3) {
    int t = threadIdx.x;
    int blk = blockIdx.x;
    if (blk < D) {
        // Wc[blk][t] = sum_m W_out[blk][m] * W_mix2[D+m][t]
        float acc = 0.f;
        #pragma unroll 8
        for (int m = 0; m < D; m++) acc += W_out[blk * D + m] * W_mix2[(D + m) * D + t];
        g_Wc[blk * D + t] = acc;
        __nv_bfloat16 h = __float2bfloat16(acc);
        g_W2h[t * 256 + 128 + blk] = h;
        g_W2l[t * 256 + 128 + blk] = __float2bfloat16(acc - __bfloat162float(h));
    } else if (blk == D) {
        float uq = 0.f, uk = 0.f;
        #pragma unroll 8
        for (int c = 0; c < D; c++) {
            uq += W_qkv[t * 3 * D + c] * w_score[c];
            uk += W_qkv[t * 3 * D + D + c] * w_score[D + c];
        }
        g_uq[t] = uq;
        g_uk[t] = uk;
        float bb = b_mix2[t];
        #pragma unroll 8
        for (int m = 0; m < D; m++) bb += b_out[m] * W_mix2[(D + m) * D + t];
        g_bc[t] = bb;
        __shared__ float s1[D], s2[D];
        s1[t] = b_qkv[t] * w_score[t];
        s2[t] = b_qkv[D + t] * w_score[D + t];
        __syncthreads();
        for (int off = 64; off; off >>= 1) {
            if (t < off) { s1[t] += s1[t + off]; s2[t] += s2[t + off]; }
            __syncthreads();
        }
        if (t == 0) { g_c[0] = s1[0]; g_c[1] = s2[0] + b_score[0]; }
    } else if (blk < 129 + 3 * D) {
        int k = blk - 129;                 // 0..383
        float w = W_mix3[k * D + t];
        __nv_bfloat16 h = __float2bfloat16(w);
        g_W3h[t * 384 + k] = h;
        g_W3l[t * 384 + k] = __float2bfloat16(w - __bfloat162float(h));
    } else {
        int k = blk - (129 + 3 * D);       // 0..127
        float w = W_mix2[k * D + t];
        __nv_bfloat16 h = __float2bfloat16(w);
        g_W2h[t * 256 + k] = h;
        g_W2l[t * 256 + k] = __float2bfloat16(w - __bfloat162float(h));
    }
}

// ---------------- K1: v rows (bf16, transposed) + sq/sk, 8 rows/block ----------------
// grid B*C/8 = 2048, block 128
__global__ void k_qkv(const float* __restrict__ ops, const float* __restrict__ W_qkv,
                      const float* __restrict__ b_qkv) {
    int r0 = blockIdx.x * 8;
    int t = threadIdx.x;
    __shared__ __align__(16) float xs[D][8];
    __shared__ __align__(16) __nv_bfloat16 vsm[D][8];
    __shared__ float wr1[4][8], wr2[4][8];
    #pragma unroll
    for (int r = 0; r < 8; r++) xs[t][r] = ops[((size_t)(r0 + r)) * D + t];
    __syncthreads();

    float bq = b_qkv[2 * D + t];
    ull acc[4];
    #pragma unroll
    for (int h = 0; h < 4; h++) acc[h] = pk2(bq, bq);
    #pragma unroll 4
    for (int k = 0; k < D; k++) {
        float w = W_qkv[k * 3 * D + 2 * D + t];
        ull wp = pk2(w, w);
        ulonglong2 xa = *(const ulonglong2*)&xs[k][0];
        ulonglong2 xb = *(const ulonglong2*)&xs[k][4];
        fma2(acc[0], xa.x, wp);
        fma2(acc[1], xa.y, wp);
        fma2(acc[2], xb.x, wp);
        fma2(acc[3], xb.y, wp);
    }
    #pragma unroll
    for (int h = 0; h < 4; h++) {
        float2 u = upk2(acc[h]);
        vsm[t][2 * h]     = __float2bfloat16(u.x);
        vsm[t][2 * h + 1] = __float2bfloat16(u.y);
    }

    float uqv = g_uq[t], ukv = g_uk[t];
    int lane = t & 31, wid = t >> 5;
    #pragma unroll
    for (int r = 0; r < 8; r++) {
        float a = xs[t][r] * uqv;
        float bv = xs[t][r] * ukv;
        #pragma unroll
        for (int off = 16; off; off >>= 1) {
            a += __shfl_down_sync(0xffffffffu, a, off);
            bv += __shfl_down_sync(0xffffffffu, bv, off);
        }
        if (lane == 0) { wr1[wid][r] = a; wr2[wid][r] = bv; }
    }
    __syncthreads();
    int bb = r0 >> 11;
    int jl = r0 & (C - 1);
    *(uint4*)&g_vT[((size_t)bb * D + t) * C + jl] = *(const uint4*)&vsm[t][0];
    if (t < 8) {
        g_sq[r0 + t] = wr1[0][t] + wr1[1][t] + wr1[2][t] + wr1[3][t] + g_c[0];
        g_sk[r0 + t] = wr2[0][t] + wr2[1][t] + wr2[2][t] + wr2[3][t] + g_c[1];
    }
}

// ---------------- K1b: colsum of bf16 v per (batch, d) ----------------
// grid B, block 512
__global__ void k_colsum() {
    int b = blockIdx.x;
    int t = threadIdx.x;
    int d = t & 127, q = t >> 7;
    __shared__ float part[4][D];
    const __nv_bfloat162* row = (const __nv_bfloat162*)
        (g_vT + ((size_t)b * D + d) * C + q * 512);
    float s = 0.f;
    #pragma unroll 8
    for (int j = 0; j < 256; j++) {
        float2 f = __bfloat1622float2(row[j]);
        s += f.x + f.y;
    }
    part[q][d] = s;
    __syncthreads();
    if (t < D) g_colsum[b * D + t] = part[0][t] + part[1][t] + part[2][t] + part[3][t];
}

// ---------------- K2: mixed rows via split-bf16 HMMA + begin/end blocks ----------------
// grid 128 + 16, block 256, dyn smem 65KB
__global__ void __launch_bounds__(256) k_mixed(
    const float* __restrict__ ops, const int* __restrict__ rel,
    const float* __restrict__ b_mix3,
    const int* __restrict__ bidx, const int* __restrict__ eidx,
    const float* __restrict__ W_begin, const float* __restrict__ b_begin,
    const float* __restrict__ W_end, const float* __restrict__ b_end) {
    __shared__ float gm[D];
    __shared__ int sp[128], ss[128];
    __shared__ float sb[128];

    int blk = blockIdx.x;
    int t = threadIdx.x;

    if (blk >= 128) {
        // ---- begin/end path ----
        int e = blk - 128;
        int b = e >> 1, which = e & 1;
        const int* idx = which ? eidx : bidx;
        if (t < 128) {
            float s = 0.f;
            for (int j = 0; j < J; j++)
                s += ops[((size_t)b * C + idx[b * J + j]) * D + t];
            gm[t] = s * (1.0f / (float)J);
        }
        __syncthreads();
        if (t < 128) {
            const float* W = which ? W_end : W_begin;
            const float* bbp = which ? b_end : b_begin;
            float acc = bbp[t];
            #pragma unroll 8
            for (int k = 0; k < D; k++) acc += gm[k] * W[k * D + t];
            g_seq[((size_t)b * C + CM2 + which) * D + t] = acc;
        }
        return;
    }

    extern __shared__ __align__(16) char dsm[];
    char* smb = (char*)((((uintptr_t)dsm) + 1023) & ~(uintptr_t)1023);
    char* smAh = smb;
    char* smAl = smb + 16384;
    char* smBh = smb + 32768;
    char* smBl = smb + 49152;
    uint32_t suAh = smem_u32(smAh), suAl = smem_u32(smAl);
    uint32_t suBh = smem_u32(smBh), suBl = smem_u32(smBl);

    int b = blk >> 4;
    int i0 = (blk & 15) * 128;
    int w = t >> 5, lane = t & 31;

    if (t < 128) {
        int ig = i0 + t;
        sb[t] = b_mix3[t];
        if (ig < CM2) {
            int2 rr = *(const int2*)&rel[((size_t)b * CM2 + ig) * 2];
            sp[t] = rr.x; ss[t] = rr.y;
        } else { sp[t] = 0; ss[t] = 0; }
    }

    float cc[16][4];
    #pragma unroll
    for (int nt = 0; nt < 16; nt++)
        #pragma unroll
        for (int r = 0; r < 4; r++) cc[nt][r] = 0.f;

    int l8 = lane & 7, grp = lane >> 3;
    int rowA = (w << 4) + l8 + ((grp & 1) << 3);
    int colAg = (grp >> 1) << 4;
    int rowBoff = l8 + ((grp >> 1) << 3);
    int colBg = (grp & 1) << 4;

    int r = t >> 1, h = t & 1;
    int rowoff = r * 128 + h * 64;
    const float* opsb = ops + (size_t)b * C * D;

    __syncthreads();   // sp/ss ready

    #pragma unroll 1
    for (int c = 0; c < 6; c++) {
        if (c) __syncthreads();  // previous phase-2 done
        // ---- A chunk: gather + split ----
        int src_row = (c < 2) ? (i0 + r) : ((c < 4) ? sp[r] : ss[r]);
        int col0 = (c & 1) * 64;
        const float4* src = (const float4*)(opsb + (size_t)src_row * D + col0 + h * 32);
        #pragma unroll
        for (int q = 0; q < 8; q++) {
            float4 v = src[q];
            uint32_t h0, h1, l0, l1;
            split2(v.x, v.y, h0, l0);
            split2(v.z, v.w, h1, l1);
            uint32_t off = rowoff + q * 8;
            *(uint2*)(smAh + SWZ(off)) = make_uint2(h0, h1);
            *(uint2*)(smAl + SWZ(off)) = make_uint2(l0, l1);
        }
        // ---- B chunk: transposed split weights ----
        #pragma unroll
        for (int c2 = 0; c2 < 4; c2++) {
            int idx = t + c2 * 256;
            int dd = idx >> 3, ccx = idx & 7;
            uint32_t off = dd * 128 + ccx * 16;
            *(uint4*)(smBh + SWZ(off)) = *(const uint4*)&g_W3h[dd * 384 + c * 64 + ccx * 8];
            *(uint4*)(smBl + SWZ(off)) = *(const uint4*)&g_W3l[dd * 384 + c * 64 + ccx * 8];
        }
        __syncthreads();
        mma_pass(suAh, suBh, cc, rowA, colAg, rowBoff, colBg);
        mma_pass(suAh, suBl, cc, rowA, colAg, rowBoff, colBg);
        mma_pass(suAl, suBh, cc, rowA, colAg, rowBoff, colBg);
    }

    // ---- epilogue ----
    int quad = lane >> 2, qt = lane & 3;
    int r0g = i0 + (w << 4) + quad;
    int r8g = r0g + 8;
    float* ob = g_seq + (size_t)b * C * D;
    #pragma unroll
    for (int nt = 0; nt < 16; nt++) {
        int n0 = nt * 8 + 2 * qt;
        float b0v = sb[n0], b1v = sb[n0 + 1];
        if (r0g < CM2)
            *(float2*)&ob[(size_t)r0g * D + n0] =
                make_float2(cc[nt][0] + b0v, cc[nt][1] + b1v);
        if (r8g < CM2)
            *(float2*)&ob[(size_t)r8g * D + n0] =
                make_float2(cc[nt][2] + b0v, cc[nt][3] + b1v);
    }
}

// ---------------- K3: attention via mma.sync bf16 (HMMA) ----------------
// grid 128, block 256 (8 warps)
#define KT 64
__global__ void __launch_bounds__(256) k_attn(const float* __restrict__ mask) {
    __shared__ __align__(128) char smA[128 * 128];
    __shared__ __align__(128) char smB[128 * 128];
    __shared__ float ssq[128];
    __shared__ float srow[128];
    __shared__ float scol[128];

    int t = threadIdx.x;
    int w = t >> 5, lane = t & 31;
    int blk = blockIdx.x;
    int b = blk >> 4;
    int i0 = (blk & 15) * 128;
    int base = b * C;

    uint32_t suA = smem_u32(smA);
    uint32_t suB = smem_u32(smB);

    if (t < 128) { ssq[t] = g_sq[base + i0 + t]; scol[t] = g_colsum[b * D + t]; }

    float rowsum[16];
    #pragma unroll
    for (int s = 0; s < 16; s++) rowsum[s] = 0.f;

    float cc[16][4];
    #pragma unroll
    for (int nt = 0; nt < 16; nt++)
        #pragma unroll
        for (int r = 0; r < 4; r++) cc[nt][r] = 0.f;

    const __nv_bfloat16* vTb = g_vT + (size_t)b * D * C;

    int l8 = lane & 7, grp = lane >> 3;
    int rowA = (w << 4) + l8 + ((grp & 1) << 3);
    int colAg = (grp >> 1) << 4;
    int rowBoff = l8 + ((grp >> 1) << 3);
    int colBg = (grp & 1) << 4;
    int mbase = w << 4;

    for (int i = 0; i < C / KT; i++) {
        int jb = i * KT;
        __syncthreads();

        {
            float2 sk2 = *(const float2*)&g_sk[base + jb + 2 * lane];
            const float* mrow0 = mask + (size_t)(base + i0 + w) * C + jb + 2 * lane;
            #pragma unroll
            for (int s = 0; s < 16; s++) {
                int row = w + 8 * s;
                float2 mk = *(const float2*)(mrow0 + (size_t)(8 * s) * C);
                float q = ssq[row];
                float x0 = q + sk2.x; x0 = (x0 >= 0.f) ? x0 : 0.01f * x0; x0 *= mk.x;
                float x1 = q + sk2.y; x1 = (x1 >= 0.f) ? x1 : 0.01f * x1; x1 *= mk.y;
                float p0 = __expf(x0), p1 = __expf(x1);
                rowsum[s] += p0 + p1;
                uint32_t pr; CVT_BF16X2(pr, p0 - 1.f, p1 - 1.f);
                uint32_t off = row * 128 + lane * 4;
                *(uint32_t*)(smA + SWZ(off)) = pr;
            }
        }
        #pragma unroll
        for (int c = 0; c < 4; c++) {
            int idx = t + c * 256;
            int dd = idx >> 3, ccx = idx & 7;
            uint4 val = *(const uint4*)(vTb + (size_t)dd * C + jb + ccx * 8);
            uint32_t off = dd * 128 + ccx * 16;
            *(uint4*)(smB + SWZ(off)) = val;
        }
        __syncthreads();

        mma_pass(suA, suB, cc, rowA, colAg, rowBoff, colBg);
    }

    #pragma unroll
    for (int s = 0; s < 16; s++) {
        float r = rowsum[s];
        #pragma unroll
        for (int off = 16; off; off >>= 1) r += __shfl_down_sync(0xffffffffu, r, off);
        if (lane == 0) srow[w + 8 * s] = r;
    }
    __syncthreads();

    int quad = lane >> 2, qt = lane & 3;
    float inv0 = 1.0f / srow[mbase + quad];
    float inv8 = 1.0f / srow[mbase + quad + 8];
    float* o0 = g_weighted + (size_t)(base + i0 + mbase + quad) * D;
    float* o8 = o0 + 8 * D;
    #pragma unroll
    for (int nt = 0; nt < 16; nt++) {
        int n0 = nt * 8 + 2 * qt;
        float cs0 = scol[n0], cs1 = scol[n0 + 1];
        *(float2*)(o0 + n0) = make_float2((cs0 + cc[nt][0]) * inv0,
                                          (cs1 + cc[nt][1]) * inv0);
        *(float2*)(o8 + n0) = make_float2((cs0 + cc[nt][2]) * inv8,
                                          (cs1 + cc[nt][3]) * inv8);
    }
}

// ---------------- K4: final mix via split-bf16 HMMA ----------------
// grid 128, block 256, dyn smem 65KB
__global__ void __launch_bounds__(256) k_final(float* __restrict__ out) {
    __shared__ float sb[128];
    extern __shared__ __align__(16) char dsm[];
    char* smb = (char*)((((uintptr_t)dsm) + 1023) & ~(uintptr_t)1023);
    char* smAh = smb;
    char* smAl = smb + 16384;
    char* smBh = smb + 32768;
    char* smBl = smb + 49152;
    uint32_t suAh = smem_u32(smAh), suAl = smem_u32(smAl);
    uint32_t suBh = smem_u32(smBh), suBl = smem_u32(smBl);

    int blk = blockIdx.x;
    int t = threadIdx.x;
    int b = blk >> 4;
    int i0 = (blk & 15) * 128;
    int w = t >> 5, lane = t & 31;

    if (t < 128) sb[t] = g_bc[t];

    float cc[16][4];
    #pragma unroll
    for (int nt = 0; nt < 16; nt++)
        #pragma unroll
        for (int r = 0; r < 4; r++) cc[nt][r] = 0.f;

    int l8 = lane & 7, grp = lane >> 3;
    int rowA = (w << 4) + l8 + ((grp & 1) << 3);
    int colAg = (grp >> 1) << 4;
    int rowBoff = l8 + ((grp >> 1) << 3);
    int colBg = (grp & 1) << 4;

    int r = t >> 1, h = t & 1;
    int rowoff = r * 128 + h * 64;

    #pragma unroll 1
    for (int c = 0; c < 4; c++) {
        if (c) __syncthreads();
        const float* srcb = (c < 2) ? g_seq : g_weighted;
        int col0 = (c & 1) * 64;
        const float4* src = (const float4*)
            (srcb + ((size_t)b * C + i0 + r) * D + col0 + h * 32);
        #pragma unroll
        for (int q = 0; q < 8; q++) {
            float4 v = src[q];
            uint32_t h0, h1, l0, l1;
            split2(v.x, v.y, h0, l0);
            split2(v.z, v.w, h1, l1);
            uint32_t off = rowoff + q * 8;
            *(uint2*)(smAh + SWZ(off)) = make_uint2(h0, h1);
            *(uint2*)(smAl + SWZ(off)) = make_uint2(l0, l1);
        }
        #pragma unroll
        for (int c2 = 0; c2 < 4; c2++) {
            int idx = t + c2 * 256;
            int dd = idx >> 3, ccx = idx & 7;
            uint32_t off = dd * 128 + ccx * 16;
            *(uint4*)(smBh + SWZ(off)) = *(const uint4*)&g_W2h[dd * 256 + c * 64 + ccx * 8];
            *(uint4*)(smBl + SWZ(off)) = *(const uint4*)&g_W2l[dd * 256 + c * 64 + ccx * 8];
        }
        __syncthreads();
        mma_pass(suAh, suBh, cc, rowA, colAg, rowBoff, colBg);
        mma_pass(suAh, suBl, cc, rowA, colAg, rowBoff, colBg);
        mma_pass(suAl, suBh, cc, rowA, colAg, rowBoff, colBg);
    }

    int quad = lane >> 2, qt = lane & 3;
    int r0g = i0 + (w << 4) + quad;
    float* ob = out + (size_t)b * C * D;
    #pragma unroll
    for (int nt = 0; nt < 16; nt++) {
        int n0 = nt * 8 + 2 * qt;
        float b0v = sb[n0], b1v = sb[n0 + 1];
        *(float2*)&ob[(size_t)r0g * D + n0] =
            make_float2(cc[nt][0] + b0v, cc[nt][1] + b1v);
        *(float2*)&ob[(size_t)(r0g + 8) * D + n0] =
            make_float2(cc[nt][2] + b0v, cc[nt][3] + b1v);
    }
}

// ---------------- launch ----------------
extern "C" void kernel_launch(void* const* d_in, const int* in_sizes, int n_in,
                              void* d_out, int out_size) {
    const float* ops      = (const float*)d_in[0];
    const int*   rel      = (const int*)d_in[1];
    const int*   bidx     = (const int*)d_in[2];
    const int*   eidx     = (const int*)d_in[3];
    const float* mask     = (const float*)d_in[4];
    const float* W_begin  = (const float*)d_in[5];
    const float* b_begin  = (const float*)d_in[6];
    const float* W_end    = (const float*)d_in[7];
    const float* b_end    = (const float*)d_in[8];
    const float* W_mix3   = (const float*)d_in[9];
    const float* b_mix3   = (const float*)d_in[10];
    const float* W_qkv    = (const float*)d_in[11];
    const float* b_qkv    = (const float*)d_in[12];
    const float* w_score  = (const float*)d_in[13];
    const float* b_score  = (const float*)d_in[14];
    const float* W_out    = (const float*)d_in[15];
    const float* b_out    = (const float*)d_in[16];
    const float* W_mix2   = (const float*)d_in[17];
    const float* b_mix2   = (const float*)d_in[18];
    float* out = (float*)d_out;

    static bool attr_set = false;
    if (!attr_set) {
        cudaFuncSetAttribute(k_mixed, cudaFuncAttributeMaxDynamicSharedMemorySize, SMEM_MMA);
        cudaFuncSetAttribute(k_final, cudaFuncAttributeMaxDynamicSharedMemorySize, SMEM_MMA);
        attr_set = true;
    }

    k_pre<<<129 + 3 * D + D, 128>>>(W_qkv, b_qkv, w_score, b_score, W_out, b_out,
                                    W_mix2, b_mix2, W_mix3);
    k_qkv<<<B * C / 8, 128>>>(ops, W_qkv, b_qkv);
    k_colsum<<<B, 512>>>();
    k_mixed<<<128 + 2 * B, 256, SMEM_MMA>>>(ops, rel, b_mix3,
                                            bidx, eidx, W_begin, b_begin, W_end, b_end);
    k_attn<<<128, 256>>>(mask);
    k_final<<<128, 256, SMEM_MMA>>>(out);
}

// round 8
// speedup vs baseline: 3.7507x; 1.3542x over previous
#include <cuda_runtime.h>
#include <cuda_bf16.h>
#include <cstdint>

#define B 8
#define C 2048
#define D 128
#define J 128
#define CM2 (C - 2)   // 2046
#define BCD (B * C * D)

// ---------------- scratch (device globals) ----------------
__device__ __align__(16) __nv_bfloat16 g_vT[B * D * C];   // v bf16 transposed [b][d][j]
__device__ __align__(16) float g_seq[BCD];
__device__ __align__(16) float g_weighted[BCD];
__device__ __align__(16) float g_mx[3 * BCD];             // ops@W3a / @W3b / @W3c
__device__ float g_colsum[B * D];
__device__ float g_sq[B * C];
__device__ float g_sk[B * C];
__device__ float g_uq[D];
__device__ float g_uk[D];
__device__ float g_c[2];
__device__ float g_bc[D];
// split-bf16 transposed weights
__device__ __align__(16) __nv_bfloat16 g_Wbh[512 * D];    // [W3a|W3b|W3c|Wv] as [n][k]
__device__ __align__(16) __nv_bfloat16 g_Wbl[512 * D];
__device__ __align__(16) __nv_bfloat16 g_W2h[D * 2 * D];  // [mix2 | Wc] as [n][k]
__device__ __align__(16) __nv_bfloat16 g_W2l[D * 2 * D];

// ---------------- helpers ----------------
__device__ __forceinline__ uint32_t smem_u32(const void* p) {
    uint32_t a;
    asm("{ .reg .u64 tmp; cvta.to.shared.u64 tmp, %1; cvt.u32.u64 %0, tmp; }"
        : "=r"(a) : "l"(p));
    return a;
}
#define CVT_BF16X2(res, a, b) \
    asm("cvt.rn.satfinite.bf16x2.f32 %0, %1, %2;" : "=r"(res) : "f"(b), "f"(a))
#define SWZ(x) ((x) ^ (((x) >> 3) & 0x70))

__device__ __forceinline__ void ldm_x4(uint32_t& r0, uint32_t& r1, uint32_t& r2,
                                       uint32_t& r3, uint32_t addr) {
    asm volatile("ldmatrix.sync.aligned.m8n8.x4.shared.b16 {%0,%1,%2,%3}, [%4];"
                 : "=r"(r0), "=r"(r1), "=r"(r2), "=r"(r3) : "r"(addr));
}
__device__ __forceinline__ void mma16816(float* c, uint32_t a0, uint32_t a1,
                                         uint32_t a2, uint32_t a3,
                                         uint32_t b0, uint32_t b1) {
    asm volatile(
        "mma.sync.aligned.m16n8k16.row.col.f32.bf16.bf16.f32 "
        "{%0,%1,%2,%3}, {%4,%5,%6,%7}, {%8,%9}, {%0,%1,%2,%3};"
        : "+f"(c[0]), "+f"(c[1]), "+f"(c[2]), "+f"(c[3])
        : "r"(a0), "r"(a1), "r"(a2), "r"(a3), "r"(b0), "r"(b1));
}
__device__ __forceinline__ void split2(float x0, float x1, uint32_t& hp, uint32_t& lp) {
    CVT_BF16X2(hp, x0, x1);
    __nv_bfloat162 hv = *reinterpret_cast<__nv_bfloat162*>(&hp);
    float f0 = __bfloat162float(hv.x), f1 = __bfloat162float(hv.y);
    CVT_BF16X2(lp, x0 - f0, x1 - f1);
}
// one K=64 pass: warp computes 16m x 128n
__device__ __forceinline__ void mma_pass(uint32_t suA, uint32_t suB, float cc[16][4],
                                         int rowA, int colAg, int rowBoff, int colBg) {
    #pragma unroll
    for (int ks = 0; ks < 4; ks++) {
        uint32_t a0, a1, a2, a3;
        ldm_x4(a0, a1, a2, a3, suA + SWZ(rowA * 128 + ks * 32 + colAg));
        #pragma unroll
        for (int nt = 0; nt < 16; nt += 2) {
            uint32_t b0, b1, b2, b3;
            ldm_x4(b0, b1, b2, b3, suB + SWZ((nt * 8 + rowBoff) * 128 + ks * 32 + colBg));
            mma16816(cc[nt],     a0, a1, a2, a3, b0, b1);
            mma16816(cc[nt + 1], a0, a1, a2, a3, b2, b3);
        }
    }
}

#define SMEM_MMA (65536 + 1024)

// ---------------- K0: folded + split/transposed weights ----------------
// grid 769, block 128
__global__ void k_pre(const float* __restrict__ W_qkv, const float* __restrict__ b_qkv,
                      const float* __restrict__ w_score, const float* __restrict__ b_score,
                      const float* __restrict__ W_out, const float* __restrict__ b_out,
                      const float* __restrict__ W_mix2, const float* __restrict__ b_mix2,
                      const float* __restrict__ W_mix3) {
    int t = threadIdx.x;
    int blk = blockIdx.x;
    if (blk < D) {
        // Wc[blk][t] -> g_W2 col group 1 (transposed)
        float acc = 0.f;
        #pragma unroll 8
        for (int m = 0; m < D; m++) acc += W_out[blk * D + m] * W_mix2[(D + m) * D + t];
        __nv_bfloat16 h = __float2bfloat16(acc);
        g_W2h[t * 256 + 128 + blk] = h;
        g_W2l[t * 256 + 128 + blk] = __float2bfloat16(acc - __bfloat162float(h));
    } else if (blk == D) {
        float uq = 0.f, uk = 0.f;
        #pragma unroll 8
        for (int c = 0; c < D; c++) {
            uq += W_qkv[t * 3 * D + c] * w_score[c];
            uk += W_qkv[t * 3 * D + D + c] * w_score[D + c];
        }
        g_uq[t] = uq;
        g_uk[t] = uk;
        float bb = b_mix2[t];
        #pragma unroll 8
        for (int m = 0; m < D; m++) bb += b_out[m] * W_mix2[(D + m) * D + t];
        g_bc[t] = bb;
        #pragma unroll
        for (int i = t; i < B * D; i += 128) g_colsum[i] = 0.f;
        __shared__ float s1[D], s2[D];
        s1[t] = b_qkv[t] * w_score[t];
        s2[t] = b_qkv[D + t] * w_score[D + t];
        __syncthreads();
        for (int off = 64; off; off >>= 1) {
            if (t < off) { s1[t] += s1[t + off]; s2[t] += s2[t + off]; }
            __syncthreads();
        }
        if (t == 0) { g_c[0] = s1[0]; g_c[1] = s2[0] + b_score[0]; }
    } else if (blk < 129 + 128) {
        int k = blk - 129;  // mix2 part: g_W2 col group 0
        float w = W_mix2[k * D + t];
        __nv_bfloat16 h = __float2bfloat16(w);
        g_W2h[t * 256 + k] = h;
        g_W2l[t * 256 + k] = __float2bfloat16(w - __bfloat162float(h));
    } else {
        int n = blk - 257;  // 0..511
        int ng = n >> 7, nl = n & 127;
        float w = (ng < 3) ? W_mix3[(ng * 128 + t) * D + nl]
                           : W_qkv[t * 3 * D + 2 * D + nl];
        __nv_bfloat16 h = __float2bfloat16(w);
        g_Wbh[n * 128 + t] = h;
        g_Wbl[n * 128 + t] = __float2bfloat16(w - __bfloat162float(h));
    }
}

// ---------------- K1: big GEMM ops @ [W3a|W3b|W3c|Wv] ----------------
// grid 512 (128 Mtiles x 4 Ngroups, ng fastest), block 256, dyn smem 65KB
__global__ void __launch_bounds__(256) k_gemm(const float* __restrict__ ops,
                                              const float* __restrict__ b_qkv) {
    __shared__ float sbv[128];
    extern __shared__ __align__(16) char dsm[];
    char* smb = (char*)((((uintptr_t)dsm) + 1023) & ~(uintptr_t)1023);
    char* smAh = smb;
    char* smAl = smb + 16384;
    char* smBh = smb + 32768;
    char* smBl = smb + 49152;
    uint32_t suAh = smem_u32(smAh), suAl = smem_u32(smAl);
    uint32_t suBh = smem_u32(smBh), suBl = smem_u32(smBl);

    int blk = blockIdx.x;
    int mt = blk >> 2, ng = blk & 3;
    int b = mt >> 4;
    int i0 = (mt & 15) * 128;
    int t = threadIdx.x;
    int w = t >> 5, lane = t & 31;

    if (ng == 3 && t < 128) sbv[t] = b_qkv[2 * D + t];

    float cc[16][4];
    #pragma unroll
    for (int nt = 0; nt < 16; nt++)
        #pragma unroll
        for (int r = 0; r < 4; r++) cc[nt][r] = 0.f;

    int l8 = lane & 7, grp = lane >> 3;
    int rowA = (w << 4) + l8 + ((grp & 1) << 3);
    int colAg = (grp >> 1) << 4;
    int rowBoff = l8 + ((grp >> 1) << 3);
    int colBg = (grp & 1) << 4;

    int r = t >> 1, h = t & 1;
    int rowoff = r * 128 + h * 64;

    #pragma unroll 1
    for (int c = 0; c < 2; c++) {
        if (c) __syncthreads();
        // A: dense ops rows
        const float4* src = (const float4*)
            (ops + ((size_t)b * C + i0 + r) * D + c * 64 + h * 32);
        #pragma unroll
        for (int q = 0; q < 8; q++) {
            float4 v = src[q];
            uint32_t h0, h1, l0, l1;
            split2(v.x, v.y, h0, l0);
            split2(v.z, v.w, h1, l1);
            uint32_t off = rowoff + q * 8;
            *(uint2*)(smAh + SWZ(off)) = make_uint2(h0, h1);
            *(uint2*)(smAl + SWZ(off)) = make_uint2(l0, l1);
        }
        // B: split weights for this n-group
        #pragma unroll
        for (int c2 = 0; c2 < 4; c2++) {
            int idx = t + c2 * 256;
            int dd = idx >> 3, ccx = idx & 7;
            uint32_t off = dd * 128 + ccx * 16;
            int gsrc = (ng * 128 + dd) * 128 + c * 64 + ccx * 8;
            *(uint4*)(smBh + SWZ(off)) = *(const uint4*)&g_Wbh[gsrc];
            *(uint4*)(smBl + SWZ(off)) = *(const uint4*)&g_Wbl[gsrc];
        }
        __syncthreads();
        mma_pass(suAh, suBh, cc, rowA, colAg, rowBoff, colBg);
        mma_pass(suAh, suBl, cc, rowA, colAg, rowBoff, colBg);
        mma_pass(suAl, suBh, cc, rowA, colAg, rowBoff, colBg);
    }

    int quad = lane >> 2, qt = lane & 3;
    if (ng < 3) {
        float* ob = g_mx + (size_t)ng * BCD + (size_t)b * C * D;
        int r0g = i0 + (w << 4) + quad;
        #pragma unroll
        for (int nt = 0; nt < 16; nt++) {
            int n0 = nt * 8 + 2 * qt;
            *(float2*)&ob[(size_t)r0g * D + n0] = make_float2(cc[nt][0], cc[nt][1]);
            *(float2*)&ob[(size_t)(r0g + 8) * D + n0] = make_float2(cc[nt][2], cc[nt][3]);
        }
    } else {
        // v: bias, bf16, transpose-stage in smem, write g_vT + colsum
        __syncthreads();   // all warps done with smA
        __nv_bfloat16* vst = (__nv_bfloat16*)smb;   // [128 n][128 m]
        int m0 = (w << 4) + quad, m8 = m0 + 8;
        #pragma unroll
        for (int nt = 0; nt < 16; nt++) {
            int n0 = nt * 8 + 2 * qt;
            float vb0 = sbv[n0], vb1 = sbv[n0 + 1];
            vst[n0 * 128 + m0]       = __float2bfloat16(cc[nt][0] + vb0);
            vst[(n0 + 1) * 128 + m0] = __float2bfloat16(cc[nt][1] + vb1);
            vst[n0 * 128 + m8]       = __float2bfloat16(cc[nt][2] + vb0);
            vst[(n0 + 1) * 128 + m8] = __float2bfloat16(cc[nt][3] + vb1);
        }
        __syncthreads();
        int n = t >> 1, hh = t & 1;
        const uint4* srcv = (const uint4*)(vst + n * 128 + hh * 64);
        uint4* dstv = (uint4*)(g_vT + ((size_t)b * D + n) * C + i0 + hh * 64);
        #pragma unroll
        for (int q = 0; q < 8; q++) dstv[q] = srcv[q];
        if (t < 128) {
            float s = 0.f;
            #pragma unroll 16
            for (int m = 0; m < 128; m++) s += __bfloat162float(vst[t * 128 + m]);
            atomicAdd(&g_colsum[b * D + t], s);
        }
    }
}

// ---------------- K2: sq/sk (warp per row) ----------------
// grid 512, block 128
__global__ void k_sqsk(const float* __restrict__ ops) {
    int t = threadIdx.x;
    int wi = t >> 5, lane = t & 31;
    float4 uq4 = ((const float4*)g_uq)[lane];
    float4 uk4 = ((const float4*)g_uk)[lane];
    float c0 = g_c[0], c1 = g_c[1];
    int rbase = blockIdx.x * 32 + wi * 8;
    #pragma unroll
    for (int r = 0; r < 8; r++) {
        int row = rbase + r;
        float4 x = ((const float4*)(ops + (size_t)row * D))[lane];
        float a = x.x * uq4.x + x.y * uq4.y + x.z * uq4.z + x.w * uq4.w;
        float b2 = x.x * uk4.x + x.y * uk4.y + x.z * uk4.z + x.w * uk4.w;
        #pragma unroll
        for (int off = 16; off; off >>= 1) {
            a += __shfl_down_sync(0xffffffffu, a, off);
            b2 += __shfl_down_sync(0xffffffffu, b2, off);
        }
        if (lane == 0) { g_sq[row] = a + c0; g_sk[row] = b2 + c1; }
    }
}

// ---------------- K3: gather-add mixed rows + begin/end ----------------
// grid 1024+16, block 128
__global__ void k_gather(const float* __restrict__ ops, const int* __restrict__ rel,
                         const float* __restrict__ b_mix3,
                         const int* __restrict__ bidx, const int* __restrict__ eidx,
                         const float* __restrict__ W_begin, const float* __restrict__ b_begin,
                         const float* __restrict__ W_end, const float* __restrict__ b_end) {
    int blk = blockIdx.x;
    int t = threadIdx.x;
    if (blk >= 1024) {
        int e = blk - 1024;
        int b = e >> 1, which = e & 1;
        const int* idx = which ? eidx : bidx;
        __shared__ float gm[D];
        float s = 0.f;
        for (int j = 0; j < J; j++)
            s += ops[((size_t)b * C + idx[b * J + j]) * D + t];
        gm[t] = s * (1.0f / (float)J);
        __syncthreads();
        const float* W = which ? W_end : W_begin;
        const float* bbp = which ? b_end : b_begin;
        float acc = bbp[t];
        #pragma unroll 8
        for (int k = 0; k < D; k++) acc += gm[k] * W[k * D + t];
        g_seq[((size_t)b * C + CM2 + which) * D + t] = acc;
        return;
    }
    int b = blk >> 7;
    int i0 = (blk & 127) * 16;
    float b3 = b_mix3[t];
    size_t base = (size_t)b * C;
    const float* m1 = g_mx;
    const float* m2 = g_mx + BCD;
    const float* m3 = g_mx + 2 * BCD;
    #pragma unroll
    for (int r = 0; r < 16; r++) {
        int i = i0 + r;
        if (i >= CM2) continue;
        int2 rr = *(const int2*)&rel[((size_t)b * CM2 + i) * 2];
        float v = m1[(base + i) * D + t] + m2[(base + rr.x) * D + t]
                + m3[(base + rr.y) * D + t] + b3;
        g_seq[(base + i) * D + t] = v;
    }
}

// ---------------- K4: attention HMMA, 64-row tiles ----------------
// grid 256, block 256, occ 2
__global__ void __launch_bounds__(256, 2) k_attn(const float* __restrict__ mask) {
    __shared__ __align__(128) char smA[64 * 128];
    __shared__ __align__(128) char smB[128 * 128];
    __shared__ float ssq[64];
    __shared__ float srow[64];
    __shared__ float scol[128];

    int t = threadIdx.x;
    int w = t >> 5, lane = t & 31;
    int blk = blockIdx.x;
    int b = blk >> 5;
    int i0 = (blk & 31) * 64;
    int base = b * C;

    uint32_t suA = smem_u32(smA);
    uint32_t suB = smem_u32(smB);

    if (t < 64) ssq[t] = g_sq[base + i0 + t];
    if (t < 128) scol[t] = g_colsum[b * D + t];

    float rowsum[8];
    #pragma unroll
    for (int s = 0; s < 8; s++) rowsum[s] = 0.f;

    float cc[8][4];
    #pragma unroll
    for (int nt = 0; nt < 8; nt++)
        #pragma unroll
        for (int r = 0; r < 4; r++) cc[nt][r] = 0.f;

    const __nv_bfloat16* vTb = g_vT + (size_t)b * D * C;

    int l8 = lane & 7, grp = lane >> 3;
    int mg = w >> 1, nh = w & 1;
    int rowA = (mg << 4) + l8 + ((grp & 1) << 3);
    int colAg = (grp >> 1) << 4;
    int rowBoff = l8 + ((grp >> 1) << 3);
    int colBg = (grp & 1) << 4;

    for (int i = 0; i < C / 64; i++) {
        int jb = i * 64;
        __syncthreads();
        // probs for rows w+8s
        {
            float2 sk2 = *(const float2*)&g_sk[base + jb + 2 * lane];
            const float* mrow0 = mask + (size_t)(base + i0 + w) * C + jb + 2 * lane;
            #pragma unroll
            for (int s = 0; s < 8; s++) {
                int row = w + 8 * s;
                float2 mk = *(const float2*)(mrow0 + (size_t)(8 * s) * C);
                float q = ssq[row];
                float x0 = q + sk2.x; x0 = (x0 >= 0.f) ? x0 : 0.01f * x0; x0 *= mk.x;
                float x1 = q + sk2.y; x1 = (x1 >= 0.f) ? x1 : 0.01f * x1; x1 *= mk.y;
                float p0 = __expf(x0), p1 = __expf(x1);
                rowsum[s] += p0 + p1;
                uint32_t pr; CVT_BF16X2(pr, p0 - 1.f, p1 - 1.f);
                uint32_t off = row * 128 + lane * 4;
                *(uint32_t*)(smA + SWZ(off)) = pr;
            }
        }
        // B tile: vT [128 d][64 j]
        #pragma unroll
        for (int c = 0; c < 4; c++) {
            int idx = t + c * 256;
            int dd = idx >> 3, ccx = idx & 7;
            uint4 val = *(const uint4*)(vTb + (size_t)dd * C + jb + ccx * 8);
            uint32_t off = dd * 128 + ccx * 16;
            *(uint4*)(smB + SWZ(off)) = val;
        }
        __syncthreads();
        // mma: warp (mg, nh): 16m x 64n
        #pragma unroll
        for (int ks = 0; ks < 4; ks++) {
            uint32_t a0, a1, a2, a3;
            ldm_x4(a0, a1, a2, a3, suA + SWZ(rowA * 128 + ks * 32 + colAg));
            #pragma unroll
            for (int nt = 0; nt < 8; nt += 2) {
                uint32_t b0, b1, b2, b3;
                int rowB = (nh << 6) + nt * 8 + rowBoff;
                ldm_x4(b0, b1, b2, b3, suB + SWZ(rowB * 128 + ks * 32 + colBg));
                mma16816(cc[nt],     a0, a1, a2, a3, b0, b1);
                mma16816(cc[nt + 1], a0, a1, a2, a3, b2, b3);
            }
        }
    }

    #pragma unroll
    for (int s = 0; s < 8; s++) {
        float r = rowsum[s];
        #pragma unroll
        for (int off = 16; off; off >>= 1) r += __shfl_down_sync(0xffffffffu, r, off);
        if (lane == 0) srow[w + 8 * s] = r;
    }
    __syncthreads();

    int quad = lane >> 2, qt = lane & 3;
    int m0 = (mg << 4) + quad;
    float inv0 = 1.0f / srow[m0];
    float inv8 = 1.0f / srow[m0 + 8];
    float* o0 = g_weighted + (size_t)(base + i0 + m0) * D;
    float* o8 = o0 + 8 * D;
    #pragma unroll
    for (int nt = 0; nt < 8; nt++) {
        int n0 = (nh << 6) + nt * 8 + 2 * qt;
        float cs0 = scol[n0], cs1 = scol[n0 + 1];
        *(float2*)(o0 + n0) = make_float2((cs0 + cc[nt][0]) * inv0,
                                          (cs1 + cc[nt][1]) * inv0);
        *(float2*)(o8 + n0) = make_float2((cs0 + cc[nt][2]) * inv8,
                                          (cs1 + cc[nt][3]) * inv8);
    }
}

// ---------------- K5: final mix via split-bf16 HMMA ----------------
// grid 128, block 256, dyn smem 65KB
__global__ void __launch_bounds__(256) k_final(float* __restrict__ out) {
    __shared__ float sb[128];
    extern __shared__ __align__(16) char dsm[];
    char* smb = (char*)((((uintptr_t)dsm) + 1023) & ~(uintptr_t)1023);
    char* smAh = smb;
    char* smAl = smb + 16384;
    char* smBh = smb + 32768;
    char* smBl = smb + 49152;
    uint32_t suAh = smem_u32(smAh), suAl = smem_u32(smAl);
    uint32_t suBh = smem_u32(smBh), suBl = smem_u32(smBl);

    int blk = blockIdx.x;
    int t = threadIdx.x;
    int b = blk >> 4;
    int i0 = (blk & 15) * 128;
    int w = t >> 5, lane = t & 31;

    if (t < 128) sb[t] = g_bc[t];

    float cc[16][4];
    #pragma unroll
    for (int nt = 0; nt < 16; nt++)
        #pragma unroll
        for (int r = 0; r < 4; r++) cc[nt][r] = 0.f;

    int l8 = lane & 7, grp = lane >> 3;
    int rowA = (w << 4) + l8 + ((grp & 1) << 3);
    int colAg = (grp >> 1) << 4;
    int rowBoff = l8 + ((grp >> 1) << 3);
    int colBg = (grp & 1) << 4;

    int r = t >> 1, h = t & 1;
    int rowoff = r * 128 + h * 64;

    #pragma unroll 1
    for (int c = 0; c < 4; c++) {
        if (c) __syncthreads();
        const float* srcb = (c < 2) ? g_seq : g_weighted;
        int col0 = (c & 1) * 64;
        const float4* src = (const float4*)
            (srcb + ((size_t)b * C + i0 + r) * D + col0 + h * 32);
        #pragma unroll
        for (int q = 0; q < 8; q++) {
            float4 v = src[q];
            uint32_t h0, h1, l0, l1;
            split2(v.x, v.y, h0, l0);
            split2(v.z, v.w, h1, l1);
            uint32_t off = rowoff + q * 8;
            *(uint2*)(smAh + SWZ(off)) = make_uint2(h0, h1);
            *(uint2*)(smAl + SWZ(off)) = make_uint2(l0, l1);
        }
        #pragma unroll
        for (int c2 = 0; c2 < 4; c2++) {
            int idx = t + c2 * 256;
            int dd = idx >> 3, ccx = idx & 7;
            uint32_t off = dd * 128 + ccx * 16;
            *(uint4*)(smBh + SWZ(off)) = *(const uint4*)&g_W2h[dd * 256 + c * 64 + ccx * 8];
            *(uint4*)(smBl + SWZ(off)) = *(const uint4*)&g_W2l[dd * 256 + c * 64 + ccx * 8];
        }
        __syncthreads();
        mma_pass(suAh, suBh, cc, rowA, colAg, rowBoff, colBg);
        mma_pass(suAh, suBl, cc, rowA, colAg, rowBoff, colBg);
        mma_pass(suAl, suBh, cc, rowA, colAg, rowBoff, colBg);
    }

    int quad = lane >> 2, qt = lane & 3;
    int r0g = i0 + (w << 4) + quad;
    float* ob = out + (size_t)b * C * D;
    #pragma unroll
    for (int nt = 0; nt < 16; nt++) {
        int n0 = nt * 8 + 2 * qt;
        float b0v = sb[n0], b1v = sb[n0 + 1];
        *(float2*)&ob[(size_t)r0g * D + n0] =
            make_float2(cc[nt][0] + b0v, cc[nt][1] + b1v);
        *(float2*)&ob[(size_t)(r0g + 8) * D + n0] =
            make_float2(cc[nt][2] + b0v, cc[nt][3] + b1v);
    }
}

// ---------------- launch ----------------
extern "C" void kernel_launch(void* const* d_in, const int* in_sizes, int n_in,
                              void* d_out, int out_size) {
    const float* ops      = (const float*)d_in[0];
    const int*   rel      = (const int*)d_in[1];
    const int*   bidx     = (const int*)d_in[2];
    const int*   eidx     = (const int*)d_in[3];
    const float* mask     = (const float*)d_in[4];
    const float* W_begin  = (const float*)d_in[5];
    const float* b_begin  = (const float*)d_in[6];
    const float* W_end    = (const float*)d_in[7];
    const float* b_end    = (const float*)d_in[8];
    const float* W_mix3   = (const float*)d_in[9];
    const float* b_mix3   = (const float*)d_in[10];
    const float* W_qkv    = (const float*)d_in[11];
    const float* b_qkv    = (const float*)d_in[12];
    const float* w_score  = (const float*)d_in[13];
    const float* b_score  = (const float*)d_in[14];
    const float* W_out    = (const float*)d_in[15];
    const float* b_out    = (const float*)d_in[16];
    const float* W_mix2   = (const float*)d_in[17];
    const float* b_mix2   = (const float*)d_in[18];
    float* out = (float*)d_out;

    static bool attr_set = false;
    if (!attr_set) {
        cudaFuncSetAttribute(k_gemm, cudaFuncAttributeMaxDynamicSharedMemorySize, SMEM_MMA);
        cudaFuncSetAttribute(k_final, cudaFuncAttributeMaxDynamicSharedMemorySize, SMEM_MMA);
        attr_set = true;
    }

    k_pre<<<769, 128>>>(W_qkv, b_qkv, w_score, b_score, W_out, b_out,
                        W_mix2, b_mix2, W_mix3);
    k_gemm<<<512, 256, SMEM_MMA>>>(ops, b_qkv);
    k_sqsk<<<512, 128>>>(ops);
    k_gather<<<1024 + 2 * B, 128>>>(ops, rel, b_mix3,
                                    bidx, eidx, W_begin, b_begin, W_end, b_end);
    k_attn<<<256, 256>>>(mask);
    k_final<<<128, 256, SMEM_MMA>>>(out);
}

// round 9
// speedup vs baseline: 4.0683x; 1.0847x over previous
#include <cuda_runtime.h>
#include <cuda_bf16.h>
#include <cstdint>

#define B 8
#define C 2048
#define D 128
#define J 128
#define CM2 (C - 2)   // 2046
#define BCD (B * C * D)

// ---------------- scratch (device globals) ----------------
__device__ __align__(16) __nv_bfloat16 g_vT[B * D * C];   // v bf16 transposed [b][d][j]
__device__ __align__(16) float g_weighted[BCD];
__device__ __align__(16) float g_mx[3 * BCD];             // ops@W3a / @W3b / @W3c
__device__ __align__(16) float g_be[B * 2 * D];           // begin/end rows (with bias)
__device__ float g_colsum[B * D];
__device__ float g_sq[B * C];
__device__ float g_sk[B * C];
__device__ float g_uq[D];
__device__ float g_uk[D];
__device__ float g_c[2];
__device__ float g_bc[D];
// split-bf16 transposed weights
__device__ __align__(16) __nv_bfloat16 g_Wbh[512 * D];    // [W3a|W3b|W3c|Wv] as [n][k]
__device__ __align__(16) __nv_bfloat16 g_Wbl[512 * D];
__device__ __align__(16) __nv_bfloat16 g_W2h[D * 2 * D];  // [mix2 | Wc] as [n][k]
__device__ __align__(16) __nv_bfloat16 g_W2l[D * 2 * D];

// ---------------- helpers ----------------
__device__ __forceinline__ uint32_t smem_u32(const void* p) {
    uint32_t a;
    asm("{ .reg .u64 tmp; cvta.to.shared.u64 tmp, %1; cvt.u32.u64 %0, tmp; }"
        : "=r"(a) : "l"(p));
    return a;
}
#define CVT_BF16X2(res, a, b) \
    asm("cvt.rn.satfinite.bf16x2.f32 %0, %1, %2;" : "=r"(res) : "f"(b), "f"(a))
#define SWZ(x) ((x) ^ (((x) >> 3) & 0x70))

__device__ __forceinline__ void ldm_x4(uint32_t& r0, uint32_t& r1, uint32_t& r2,
                                       uint32_t& r3, uint32_t addr) {
    asm volatile("ldmatrix.sync.aligned.m8n8.x4.shared.b16 {%0,%1,%2,%3}, [%4];"
                 : "=r"(r0), "=r"(r1), "=r"(r2), "=r"(r3) : "r"(addr));
}
__device__ __forceinline__ void mma16816(float* c, uint32_t a0, uint32_t a1,
                                         uint32_t a2, uint32_t a3,
                                         uint32_t b0, uint32_t b1) {
    asm volatile(
        "mma.sync.aligned.m16n8k16.row.col.f32.bf16.bf16.f32 "
        "{%0,%1,%2,%3}, {%4,%5,%6,%7}, {%8,%9}, {%0,%1,%2,%3};"
        : "+f"(c[0]), "+f"(c[1]), "+f"(c[2]), "+f"(c[3])
        : "r"(a0), "r"(a1), "r"(a2), "r"(a3), "r"(b0), "r"(b1));
}
__device__ __forceinline__ void split2(float x0, float x1, uint32_t& hp, uint32_t& lp) {
    CVT_BF16X2(hp, x0, x1);
    __nv_bfloat162 hv = *reinterpret_cast<__nv_bfloat162*>(&hp);
    float f0 = __bfloat162float(hv.x), f1 = __bfloat162float(hv.y);
    CVT_BF16X2(lp, x0 - f0, x1 - f1);
}
// one K=64 pass: warp computes 16m x 128n
__device__ __forceinline__ void mma_pass(uint32_t suA, uint32_t suB, float cc[16][4],
                                         int rowA, int colAg, int rowBoff, int colBg) {
    #pragma unroll
    for (int ks = 0; ks < 4; ks++) {
        uint32_t a0, a1, a2, a3;
        ldm_x4(a0, a1, a2, a3, suA + SWZ(rowA * 128 + ks * 32 + colAg));
        #pragma unroll
        for (int nt = 0; nt < 16; nt += 2) {
            uint32_t b0, b1, b2, b3;
            ldm_x4(b0, b1, b2, b3, suB + SWZ((nt * 8 + rowBoff) * 128 + ks * 32 + colBg));
            mma16816(cc[nt],     a0, a1, a2, a3, b0, b1);
            mma16816(cc[nt + 1], a0, a1, a2, a3, b2, b3);
        }
    }
}

#define SMEM_MMA (65536 + 1024)

// ---------------- K0: folded + split/transposed weights ----------------
// grid 769, block 128
__global__ void k_pre(const float* __restrict__ W_qkv, const float* __restrict__ b_qkv,
                      const float* __restrict__ w_score, const float* __restrict__ b_score,
                      const float* __restrict__ W_out, const float* __restrict__ b_out,
                      const float* __restrict__ W_mix2, const float* __restrict__ b_mix2,
                      const float* __restrict__ W_mix3) {
    int t = threadIdx.x;
    int blk = blockIdx.x;
    if (blk < D) {
        float acc = 0.f;
        #pragma unroll 8
        for (int m = 0; m < D; m++) acc += W_out[blk * D + m] * W_mix2[(D + m) * D + t];
        __nv_bfloat16 h = __float2bfloat16(acc);
        g_W2h[t * 256 + 128 + blk] = h;
        g_W2l[t * 256 + 128 + blk] = __float2bfloat16(acc - __bfloat162float(h));
    } else if (blk == D) {
        float uq = 0.f, uk = 0.f;
        #pragma unroll 8
        for (int c = 0; c < D; c++) {
            uq += W_qkv[t * 3 * D + c] * w_score[c];
            uk += W_qkv[t * 3 * D + D + c] * w_score[D + c];
        }
        g_uq[t] = uq;
        g_uk[t] = uk;
        float bb = b_mix2[t];
        #pragma unroll 8
        for (int m = 0; m < D; m++) bb += b_out[m] * W_mix2[(D + m) * D + t];
        g_bc[t] = bb;
        #pragma unroll
        for (int i = t; i < B * D; i += 128) g_colsum[i] = 0.f;
        __shared__ float s1[D], s2[D];
        s1[t] = b_qkv[t] * w_score[t];
        s2[t] = b_qkv[D + t] * w_score[D + t];
        __syncthreads();
        for (int off = 64; off; off >>= 1) {
            if (t < off) { s1[t] += s1[t + off]; s2[t] += s2[t + off]; }
            __syncthreads();
        }
        if (t == 0) { g_c[0] = s1[0]; g_c[1] = s2[0] + b_score[0]; }
    } else if (blk < 129 + 128) {
        int k = blk - 129;
        float w = W_mix2[k * D + t];
        __nv_bfloat16 h = __float2bfloat16(w);
        g_W2h[t * 256 + k] = h;
        g_W2l[t * 256 + k] = __float2bfloat16(w - __bfloat162float(h));
    } else {
        int n = blk - 257;  // 0..511
        int ng = n >> 7, nl = n & 127;
        float w = (ng < 3) ? W_mix3[(ng * 128 + t) * D + nl]
                           : W_qkv[t * 3 * D + 2 * D + nl];
        __nv_bfloat16 h = __float2bfloat16(w);
        g_Wbh[n * 128 + t] = h;
        g_Wbl[n * 128 + t] = __float2bfloat16(w - __bfloat162float(h));
    }
}

// ---------------- K1: big GEMM ops @ [W3a|W3b|W3c|Wv] (+ sq/sk in ng==0) ----------------
// grid 512 (128 Mtiles x 4 Ngroups, ng fastest), block 256, dyn smem 65KB
__global__ void __launch_bounds__(256) k_gemm(const float* __restrict__ ops,
                                              const float* __restrict__ b_qkv) {
    __shared__ float sbv[128];
    __shared__ float suq[128], suk[128];
    extern __shared__ __align__(16) char dsm[];
    char* smb = (char*)((((uintptr_t)dsm) + 1023) & ~(uintptr_t)1023);
    char* smAh = smb;
    char* smAl = smb + 16384;
    char* smBh = smb + 32768;
    char* smBl = smb + 49152;
    uint32_t suAh = smem_u32(smAh), suAl = smem_u32(smAl);
    uint32_t suBh = smem_u32(smBh), suBl = smem_u32(smBl);

    int blk = blockIdx.x;
    int mt = blk >> 2, ng = blk & 3;
    int b = mt >> 4;
    int i0 = (mt & 15) * 128;
    int t = threadIdx.x;
    int w = t >> 5, lane = t & 31;

    if (ng == 3 && t < 128) sbv[t] = b_qkv[2 * D + t];
    if (ng == 0 && t < 128) { suq[t] = g_uq[t]; suk[t] = g_uk[t]; }
    __syncthreads();

    float cc[16][4];
    #pragma unroll
    for (int nt = 0; nt < 16; nt++)
        #pragma unroll
        for (int r = 0; r < 4; r++) cc[nt][r] = 0.f;

    int l8 = lane & 7, grp = lane >> 3;
    int rowA = (w << 4) + l8 + ((grp & 1) << 3);
    int colAg = (grp >> 1) << 4;
    int rowBoff = l8 + ((grp >> 1) << 3);
    int colBg = (grp & 1) << 4;

    int r = t >> 1, h = t & 1;
    int rowoff = r * 128 + h * 64;
    float dq = 0.f, dk = 0.f;

    #pragma unroll 1
    for (int c = 0; c < 2; c++) {
        if (c) __syncthreads();
        const float4* src = (const float4*)
            (ops + ((size_t)b * C + i0 + r) * D + c * 64 + h * 32);
        #pragma unroll
        for (int q = 0; q < 8; q++) {
            float4 v = src[q];
            if (ng == 0) {
                float4 u4 = *(const float4*)&suq[c * 64 + h * 32 + q * 4];
                float4 k4 = *(const float4*)&suk[c * 64 + h * 32 + q * 4];
                dq += v.x * u4.x + v.y * u4.y + v.z * u4.z + v.w * u4.w;
                dk += v.x * k4.x + v.y * k4.y + v.z * k4.z + v.w * k4.w;
            }
            uint32_t h0, h1, l0, l1;
            split2(v.x, v.y, h0, l0);
            split2(v.z, v.w, h1, l1);
            uint32_t off = rowoff + q * 8;
            *(uint2*)(smAh + SWZ(off)) = make_uint2(h0, h1);
            *(uint2*)(smAl + SWZ(off)) = make_uint2(l0, l1);
        }
        #pragma unroll
        for (int c2 = 0; c2 < 4; c2++) {
            int idx = t + c2 * 256;
            int dd = idx >> 3, ccx = idx & 7;
            uint32_t off = dd * 128 + ccx * 16;
            int gsrc = (ng * 128 + dd) * 128 + c * 64 + ccx * 8;
            *(uint4*)(smBh + SWZ(off)) = *(const uint4*)&g_Wbh[gsrc];
            *(uint4*)(smBl + SWZ(off)) = *(const uint4*)&g_Wbl[gsrc];
        }
        __syncthreads();
        mma_pass(suAh, suBh, cc, rowA, colAg, rowBoff, colBg);
        mma_pass(suAh, suBl, cc, rowA, colAg, rowBoff, colBg);
        mma_pass(suAl, suBh, cc, rowA, colAg, rowBoff, colBg);
    }

    if (ng == 0) {
        dq += __shfl_xor_sync(0xffffffffu, dq, 1);
        dk += __shfl_xor_sync(0xffffffffu, dk, 1);
        if (h == 0) {
            int row = b * C + i0 + r;
            g_sq[row] = dq + g_c[0];
            g_sk[row] = dk + g_c[1];
        }
    }

    int quad = lane >> 2, qt = lane & 3;
    if (ng < 3) {
        float* ob = g_mx + (size_t)ng * BCD + (size_t)b * C * D;
        int r0g = i0 + (w << 4) + quad;
        #pragma unroll
        for (int nt = 0; nt < 16; nt++) {
            int n0 = nt * 8 + 2 * qt;
            *(float2*)&ob[(size_t)r0g * D + n0] = make_float2(cc[nt][0], cc[nt][1]);
            *(float2*)&ob[(size_t)(r0g + 8) * D + n0] = make_float2(cc[nt][2], cc[nt][3]);
        }
    } else {
        __syncthreads();
        __nv_bfloat16* vst = (__nv_bfloat16*)smb;   // [128 n][128 m]
        int m0 = (w << 4) + quad, m8 = m0 + 8;
        #pragma unroll
        for (int nt = 0; nt < 16; nt++) {
            int n0 = nt * 8 + 2 * qt;
            float vb0 = sbv[n0], vb1 = sbv[n0 + 1];
            vst[n0 * 128 + m0]       = __float2bfloat16(cc[nt][0] + vb0);
            vst[(n0 + 1) * 128 + m0] = __float2bfloat16(cc[nt][1] + vb1);
            vst[n0 * 128 + m8]       = __float2bfloat16(cc[nt][2] + vb0);
            vst[(n0 + 1) * 128 + m8] = __float2bfloat16(cc[nt][3] + vb1);
        }
        __syncthreads();
        int n = t >> 1, hh = t & 1;
        const uint4* srcv = (const uint4*)(vst + n * 128 + hh * 64);
        uint4* dstv = (uint4*)(g_vT + ((size_t)b * D + n) * C + i0 + hh * 64);
        #pragma unroll
        for (int q = 0; q < 8; q++) dstv[q] = srcv[q];
        if (t < 128) {
            float s = 0.f;
            #pragma unroll 16
            for (int m = 0; m < 128; m++) s += __bfloat162float(vst[t * 128 + m]);
            atomicAdd(&g_colsum[b * D + t], s);
        }
    }
}

// ---------------- K2: attention HMMA (64-row tiles) + begin/end side blocks ----------------
// grid 256+16, block 256, occ 2
__global__ void __launch_bounds__(256, 2) k_attn(
    const float* __restrict__ mask, const float* __restrict__ ops,
    const int* __restrict__ bidx, const int* __restrict__ eidx,
    const float* __restrict__ W_begin, const float* __restrict__ b_begin,
    const float* __restrict__ W_end, const float* __restrict__ b_end) {
    __shared__ __align__(128) char smA[64 * 128];
    __shared__ __align__(128) char smB[128 * 128];
    __shared__ float ssq[64];
    __shared__ float srow[64];
    __shared__ float scol[128];

    int t = threadIdx.x;
    int blk = blockIdx.x;

    if (blk >= 256) {
        // ---- begin/end rows -> g_be ----
        int e = blk - 256;
        int b = e >> 1, which = e & 1;
        const int* idx = which ? eidx : bidx;
        if (t < 128) {
            float s = 0.f;
            for (int j = 0; j < J; j++)
                s += ops[((size_t)b * C + idx[b * J + j]) * D + t];
            scol[t] = s * (1.0f / (float)J);
        }
        __syncthreads();
        if (t < 128) {
            const float* W = which ? W_end : W_begin;
            const float* bbp = which ? b_end : b_begin;
            float acc = bbp[t];
            #pragma unroll 8
            for (int k = 0; k < D; k++) acc += scol[k] * W[k * D + t];
            g_be[((size_t)b * 2 + which) * D + t] = acc;
        }
        return;
    }

    int w = t >> 5, lane = t & 31;
    int b = blk >> 5;
    int i0 = (blk & 31) * 64;
    int base = b * C;

    uint32_t suA = smem_u32(smA);
    uint32_t suB = smem_u32(smB);

    if (t < 64) ssq[t] = g_sq[base + i0 + t];
    if (t < 128) scol[t] = g_colsum[b * D + t];

    float rowsum[8];
    #pragma unroll
    for (int s = 0; s < 8; s++) rowsum[s] = 0.f;

    float cc[8][4];
    #pragma unroll
    for (int nt = 0; nt < 8; nt++)
        #pragma unroll
        for (int r = 0; r < 4; r++) cc[nt][r] = 0.f;

    const __nv_bfloat16* vTb = g_vT + (size_t)b * D * C;

    int l8 = lane & 7, grp = lane >> 3;
    int mg = w >> 1, nh = w & 1;
    int rowA = (mg << 4) + l8 + ((grp & 1) << 3);
    int colAg = (grp >> 1) << 4;
    int rowBoff = l8 + ((grp >> 1) << 3);
    int colBg = (grp & 1) << 4;

    for (int i = 0; i < C / 64; i++) {
        int jb = i * 64;
        __syncthreads();
        {
            float2 sk2 = *(const float2*)&g_sk[base + jb + 2 * lane];
            const float* mrow0 = mask + (size_t)(base + i0 + w) * C + jb + 2 * lane;
            #pragma unroll
            for (int s = 0; s < 8; s++) {
                int row = w + 8 * s;
                float2 mk = *(const float2*)(mrow0 + (size_t)(8 * s) * C);
                float q = ssq[row];
                float x0 = q + sk2.x; x0 = (x0 >= 0.f) ? x0 : 0.01f * x0; x0 *= mk.x;
                float x1 = q + sk2.y; x1 = (x1 >= 0.f) ? x1 : 0.01f * x1; x1 *= mk.y;
                float p0 = __expf(x0), p1 = __expf(x1);
                rowsum[s] += p0 + p1;
                uint32_t pr; CVT_BF16X2(pr, p0 - 1.f, p1 - 1.f);
                uint32_t off = row * 128 + lane * 4;
                *(uint32_t*)(smA + SWZ(off)) = pr;
            }
        }
        #pragma unroll
        for (int c = 0; c < 4; c++) {
            int idx = t + c * 256;
            int dd = idx >> 3, ccx = idx & 7;
            uint4 val = *(const uint4*)(vTb + (size_t)dd * C + jb + ccx * 8);
            uint32_t off = dd * 128 + ccx * 16;
            *(uint4*)(smB + SWZ(off)) = val;
        }
        __syncthreads();
        #pragma unroll
        for (int ks = 0; ks < 4; ks++) {
            uint32_t a0, a1, a2, a3;
            ldm_x4(a0, a1, a2, a3, suA + SWZ(rowA * 128 + ks * 32 + colAg));
            #pragma unroll
            for (int nt = 0; nt < 8; nt += 2) {
                uint32_t b0, b1, b2, b3;
                int rowB = (nh << 6) + nt * 8 + rowBoff;
                ldm_x4(b0, b1, b2, b3, suB + SWZ(rowB * 128 + ks * 32 + colBg));
                mma16816(cc[nt],     a0, a1, a2, a3, b0, b1);
                mma16816(cc[nt + 1], a0, a1, a2, a3, b2, b3);
            }
        }
    }

    #pragma unroll
    for (int s = 0; s < 8; s++) {
        float r = rowsum[s];
        #pragma unroll
        for (int off = 16; off; off >>= 1) r += __shfl_down_sync(0xffffffffu, r, off);
        if (lane == 0) srow[w + 8 * s] = r;
    }
    __syncthreads();

    int quad = lane >> 2, qt = lane & 3;
    int m0 = (mg << 4) + quad;
    float inv0 = 1.0f / srow[m0];
    float inv8 = 1.0f / srow[m0 + 8];
    float* o0 = g_weighted + (size_t)(base + i0 + m0) * D;
    float* o8 = o0 + 8 * D;
    #pragma unroll
    for (int nt = 0; nt < 8; nt++) {
        int n0 = (nh << 6) + nt * 8 + 2 * qt;
        float cs0 = scol[n0], cs1 = scol[n0 + 1];
        *(float2*)(o0 + n0) = make_float2((cs0 + cc[nt][0]) * inv0,
                                          (cs1 + cc[nt][1]) * inv0);
        *(float2*)(o8 + n0) = make_float2((cs0 + cc[nt][2]) * inv8,
                                          (cs1 + cc[nt][3]) * inv8);
    }
}

// ---------------- K3: final mix via split-bf16 HMMA, A = gather-composed ----------------
// grid 128, block 256, dyn smem 65KB
__global__ void __launch_bounds__(256) k_final(const int* __restrict__ rel,
                                               const float* __restrict__ b_mix3,
                                               float* __restrict__ out) {
    __shared__ float sb[128];
    __shared__ float sb3[128];
    __shared__ int2 srel[128];
    extern __shared__ __align__(16) char dsm[];
    char* smb = (char*)((((uintptr_t)dsm) + 1023) & ~(uintptr_t)1023);
    char* smAh = smb;
    char* smAl = smb + 16384;
    char* smBh = smb + 32768;
    char* smBl = smb + 49152;
    uint32_t suAh = smem_u32(smAh), suAl = smem_u32(smAl);
    uint32_t suBh = smem_u32(smBh), suBl = smem_u32(smBl);

    int blk = blockIdx.x;
    int t = threadIdx.x;
    int b = blk >> 4;
    int i0 = (blk & 15) * 128;
    int w = t >> 5, lane = t & 31;

    if (t < 128) {
        sb[t] = g_bc[t];
        sb3[t] = b_mix3[t];
        int ig = i0 + t;
        if (ig < CM2) srel[t] = *(const int2*)&rel[((size_t)b * CM2 + ig) * 2];
        else srel[t] = make_int2(0, 0);
    }
    __syncthreads();

    float cc[16][4];
    #pragma unroll
    for (int nt = 0; nt < 16; nt++)
        #pragma unroll
        for (int r = 0; r < 4; r++) cc[nt][r] = 0.f;

    int l8 = lane & 7, grp = lane >> 3;
    int rowA = (w << 4) + l8 + ((grp & 1) << 3);
    int colAg = (grp >> 1) << 4;
    int rowBoff = l8 + ((grp >> 1) << 3);
    int colBg = (grp & 1) << 4;

    int r = t >> 1, h = t & 1;
    int rowoff = r * 128 + h * 64;
    size_t bbase = (size_t)b * C * D;
    const float* m1 = g_mx + bbase;
    const float* m2 = g_mx + BCD + bbase;
    const float* m3 = g_mx + 2 * BCD + bbase;

    #pragma unroll 1
    for (int c = 0; c < 4; c++) {
        if (c) __syncthreads();
        int col0 = (c & 1) * 64 + h * 32;
        if (c < 2) {
            // A = seq rows composed on the fly
            int i = i0 + r;
            if (i < CM2) {
                int2 rr = srel[r];
                const float4* p1 = (const float4*)(m1 + (size_t)i * D + col0);
                const float4* p2 = (const float4*)(m2 + (size_t)rr.x * D + col0);
                const float4* p3 = (const float4*)(m3 + (size_t)rr.y * D + col0);
                const float4* pb = (const float4*)(sb3 + col0);
                #pragma unroll
                for (int q = 0; q < 8; q++) {
                    float4 v = p1[q], v2 = p2[q], v3 = p3[q], vb = pb[q];
                    v.x += v2.x + v3.x + vb.x;
                    v.y += v2.y + v3.y + vb.y;
                    v.z += v2.z + v3.z + vb.z;
                    v.w += v2.w + v3.w + vb.w;
                    uint32_t h0, h1, l0, l1;
                    split2(v.x, v.y, h0, l0);
                    split2(v.z, v.w, h1, l1);
                    uint32_t off = rowoff + q * 8;
                    *(uint2*)(smAh + SWZ(off)) = make_uint2(h0, h1);
                    *(uint2*)(smAl + SWZ(off)) = make_uint2(l0, l1);
                }
            } else {
                const float4* pe = (const float4*)
                    (g_be + ((size_t)b * 2 + (i - CM2)) * D + col0);
                #pragma unroll
                for (int q = 0; q < 8; q++) {
                    float4 v = pe[q];
                    uint32_t h0, h1, l0, l1;
                    split2(v.x, v.y, h0, l0);
                    split2(v.z, v.w, h1, l1);
                    uint32_t off = rowoff + q * 8;
                    *(uint2*)(smAh + SWZ(off)) = make_uint2(h0, h1);
                    *(uint2*)(smAl + SWZ(off)) = make_uint2(l0, l1);
                }
            }
        } else {
            const float4* src = (const float4*)
                (g_weighted + ((size_t)b * C + i0 + r) * D + col0);
            #pragma unroll
            for (int q = 0; q < 8; q++) {
                float4 v = src[q];
                uint32_t h0, h1, l0, l1;
                split2(v.x, v.y, h0, l0);
                split2(v.z, v.w, h1, l1);
                uint32_t off = rowoff + q * 8;
                *(uint2*)(smAh + SWZ(off)) = make_uint2(h0, h1);
                *(uint2*)(smAl + SWZ(off)) = make_uint2(l0, l1);
            }
        }
        #pragma unroll
        for (int c2 = 0; c2 < 4; c2++) {
            int idx = t + c2 * 256;
            int dd = idx >> 3, ccx = idx & 7;
            uint32_t off = dd * 128 + ccx * 16;
            *(uint4*)(smBh + SWZ(off)) = *(const uint4*)&g_W2h[dd * 256 + c * 64 + ccx * 8];
            *(uint4*)(smBl + SWZ(off)) = *(const uint4*)&g_W2l[dd * 256 + c * 64 + ccx * 8];
        }
        __syncthreads();
        mma_pass(suAh, suBh, cc, rowA, colAg, rowBoff, colBg);
        mma_pass(suAh, suBl, cc, rowA, colAg, rowBoff, colBg);
        mma_pass(suAl, suBh, cc, rowA, colAg, rowBoff, colBg);
    }

    int quad = lane >> 2, qt = lane & 3;
    int r0g = i0 + (w << 4) + quad;
    float* ob = out + (size_t)b * C * D;
    #pragma unroll
    for (int nt = 0; nt < 16; nt++) {
        int n0 = nt * 8 + 2 * qt;
        float b0v = sb[n0], b1v = sb[n0 + 1];
        *(float2*)&ob[(size_t)r0g * D + n0] =
            make_float2(cc[nt][0] + b0v, cc[nt][1] + b1v);
        *(float2*)&ob[(size_t)(r0g + 8) * D + n0] =
            make_float2(cc[nt][2] + b0v, cc[nt][3] + b1v);
    }
}

// ---------------- launch ----------------
extern "C" void kernel_launch(void* const* d_in, const int* in_sizes, int n_in,
                              void* d_out, int out_size) {
    const float* ops      = (const float*)d_in[0];
    const int*   rel      = (const int*)d_in[1];
    const int*   bidx     = (const int*)d_in[2];
    const int*   eidx     = (const int*)d_in[3];
    const float* mask     = (const float*)d_in[4];
    const float* W_begin  = (const float*)d_in[5];
    const float* b_begin  = (const float*)d_in[6];
    const float* W_end    = (const float*)d_in[7];
    const float* b_end    = (const float*)d_in[8];
    const float* W_mix3   = (const float*)d_in[9];
    const float* b_mix3   = (const float*)d_in[10];
    const float* W_qkv    = (const float*)d_in[11];
    const float* b_qkv    = (const float*)d_in[12];
    const float* w_score  = (const float*)d_in[13];
    const float* b_score  = (const float*)d_in[14];
    const float* W_out    = (const float*)d_in[15];
    const float* b_out    = (const float*)d_in[16];
    const float* W_mix2   = (const float*)d_in[17];
    const float* b_mix2   = (const float*)d_in[18];
    float* out = (float*)d_out;

    static bool attr_set = false;
    if (!attr_set) {
        cudaFuncSetAttribute(k_gemm, cudaFuncAttributeMaxDynamicSharedMemorySize, SMEM_MMA);
        cudaFuncSetAttribute(k_final, cudaFuncAttributeMaxDynamicSharedMemorySize, SMEM_MMA);
        attr_set = true;
    }

    k_pre<<<769, 128>>>(W_qkv, b_qkv, w_score, b_score, W_out, b_out,
                        W_mix2, b_mix2, W_mix3);
    k_gemm<<<512, 256, SMEM_MMA>>>(ops, b_qkv);
    k_attn<<<256 + 2 * B, 256>>>(mask, ops, bidx, eidx,
                                 W_begin, b_begin, W_end, b_end);
    k_final<<<128, 256, SMEM_MMA>>>(rel, b_mix3, out);
}

// round 10
// speedup vs baseline: 4.3470x; 1.0685x over previous
#include <cuda_runtime.h>
#include <cuda_bf16.h>
#include <cstdint>

#define B 8
#define C 2048
#define D 128
#define J 128
#define CM2 (C - 2)   // 2046
#define BCD (B * C * D)

// ---------------- scratch (device globals) ----------------
__device__ __align__(16) __nv_bfloat16 g_vT[B * D * C];   // v bf16 transposed [b][d][j]
__device__ __align__(16) float g_weighted[BCD];
__device__ __align__(16) float g_mx[3 * BCD];             // ops@W3a / @W3b / @W3c
__device__ __align__(16) float g_be[B * 2 * D];           // begin/end rows (with bias)
__device__ float g_colsum[B * D];
__device__ float g_sq[B * C];
__device__ float g_sk[B * C];
__device__ float g_uq[D];
__device__ float g_uk[D];
__device__ float g_c[2];
__device__ float g_bc[D];
// split-bf16 transposed weights
__device__ __align__(16) __nv_bfloat16 g_Wbh[512 * D];    // [W3a|W3b|W3c|Wv] as [n][k]
__device__ __align__(16) __nv_bfloat16 g_Wbl[512 * D];
__device__ __align__(16) __nv_bfloat16 g_W2h[D * 2 * D];  // [mix2 | Wc] as [n][k]
__device__ __align__(16) __nv_bfloat16 g_W2l[D * 2 * D];

// ---------------- helpers ----------------
__device__ __forceinline__ uint32_t smem_u32(const void* p) {
    uint32_t a;
    asm("{ .reg .u64 tmp; cvta.to.shared.u64 tmp, %1; cvt.u32.u64 %0, tmp; }"
        : "=r"(a) : "l"(p));
    return a;
}
#define CVT_BF16X2(res, a, b) \
    asm("cvt.rn.satfinite.bf16x2.f32 %0, %1, %2;" : "=r"(res) : "f"(b), "f"(a))
#define SWZ(x) ((x) ^ (((x) >> 3) & 0x70))

__device__ __forceinline__ void ldm_x4(uint32_t& r0, uint32_t& r1, uint32_t& r2,
                                       uint32_t& r3, uint32_t addr) {
    asm volatile("ldmatrix.sync.aligned.m8n8.x4.shared.b16 {%0,%1,%2,%3}, [%4];"
                 : "=r"(r0), "=r"(r1), "=r"(r2), "=r"(r3) : "r"(addr));
}
__device__ __forceinline__ void mma16816(float* c, uint32_t a0, uint32_t a1,
                                         uint32_t a2, uint32_t a3,
                                         uint32_t b0, uint32_t b1) {
    asm volatile(
        "mma.sync.aligned.m16n8k16.row.col.f32.bf16.bf16.f32 "
        "{%0,%1,%2,%3}, {%4,%5,%6,%7}, {%8,%9}, {%0,%1,%2,%3};"
        : "+f"(c[0]), "+f"(c[1]), "+f"(c[2]), "+f"(c[3])
        : "r"(a0), "r"(a1), "r"(a2), "r"(a3), "r"(b0), "r"(b1));
}
__device__ __forceinline__ void split2(float x0, float x1, uint32_t& hp, uint32_t& lp) {
    CVT_BF16X2(hp, x0, x1);
    __nv_bfloat162 hv = *reinterpret_cast<__nv_bfloat162*>(&hp);
    float f0 = __bfloat162float(hv.x), f1 = __bfloat162float(hv.y);
    CVT_BF16X2(lp, x0 - f0, x1 - f1);
}
// one K=64 pass: warp (mg, nh) computes 16m x 64n, A tile 64 rows
__device__ __forceinline__ void mma_pass64(uint32_t suA, uint32_t suB, float cc[8][4],
                                           int rowA, int colAg, int nh,
                                           int rowBoff, int colBg) {
    #pragma unroll
    for (int ks = 0; ks < 4; ks++) {
        uint32_t a0, a1, a2, a3;
        ldm_x4(a0, a1, a2, a3, suA + SWZ(rowA * 128 + ks * 32 + colAg));
        #pragma unroll
        for (int nt = 0; nt < 8; nt += 2) {
            uint32_t b0, b1, b2, b3;
            int rowB = (nh << 6) + nt * 8 + rowBoff;
            ldm_x4(b0, b1, b2, b3, suB + SWZ(rowB * 128 + ks * 32 + colBg));
            mma16816(cc[nt],     a0, a1, a2, a3, b0, b1);
            mma16816(cc[nt + 1], a0, a1, a2, a3, b2, b3);
        }
    }
}

#define SMEM_MMA2 (49152 + 1024)

// ---------------- K0: folded + split/transposed weights ----------------
// grid 769, block 128
__global__ void k_pre(const float* __restrict__ W_qkv, const float* __restrict__ b_qkv,
                      const float* __restrict__ w_score, const float* __restrict__ b_score,
                      const float* __restrict__ W_out, const float* __restrict__ b_out,
                      const float* __restrict__ W_mix2, const float* __restrict__ b_mix2,
                      const float* __restrict__ W_mix3) {
    int t = threadIdx.x;
    int blk = blockIdx.x;
    if (blk < D) {
        float acc = 0.f;
        #pragma unroll 8
        for (int m = 0; m < D; m++) acc += W_out[blk * D + m] * W_mix2[(D + m) * D + t];
        __nv_bfloat16 h = __float2bfloat16(acc);
        g_W2h[t * 256 + 128 + blk] = h;
        g_W2l[t * 256 + 128 + blk] = __float2bfloat16(acc - __bfloat162float(h));
    } else if (blk == D) {
        float uq = 0.f, uk = 0.f;
        #pragma unroll 8
        for (int c = 0; c < D; c++) {
            uq += W_qkv[t * 3 * D + c] * w_score[c];
            uk += W_qkv[t * 3 * D + D + c] * w_score[D + c];
        }
        g_uq[t] = uq;
        g_uk[t] = uk;
        float bb = b_mix2[t];
        #pragma unroll 8
        for (int m = 0; m < D; m++) bb += b_out[m] * W_mix2[(D + m) * D + t];
        g_bc[t] = bb;
        #pragma unroll
        for (int i = t; i < B * D; i += 128) g_colsum[i] = 0.f;
        __shared__ float s1[D], s2[D];
        s1[t] = b_qkv[t] * w_score[t];
        s2[t] = b_qkv[D + t] * w_score[D + t];
        __syncthreads();
        for (int off = 64; off; off >>= 1) {
            if (t < off) { s1[t] += s1[t + off]; s2[t] += s2[t + off]; }
            __syncthreads();
        }
        if (t == 0) { g_c[0] = s1[0]; g_c[1] = s2[0] + b_score[0]; }
    } else if (blk < 129 + 128) {
        int k = blk - 129;
        float w = W_mix2[k * D + t];
        __nv_bfloat16 h = __float2bfloat16(w);
        g_W2h[t * 256 + k] = h;
        g_W2l[t * 256 + k] = __float2bfloat16(w - __bfloat162float(h));
    } else {
        int n = blk - 257;  // 0..511
        int ng = n >> 7, nl = n & 127;
        float w = (ng < 3) ? W_mix3[(ng * 128 + t) * D + nl]
                           : W_qkv[t * 3 * D + 2 * D + nl];
        __nv_bfloat16 h = __float2bfloat16(w);
        g_Wbh[n * 128 + t] = h;
        g_Wbl[n * 128 + t] = __float2bfloat16(w - __bfloat162float(h));
    }
}

// ---------------- K1: big GEMM ops @ [W3a|W3b|W3c|Wv], 64-row M-tiles ----------------
// grid 1024 (256 Mtiles x 4 Ngroups, ng fastest), block 256, dyn smem 48KB, occ 2
__global__ void __launch_bounds__(256, 2) k_gemm(const float* __restrict__ ops,
                                                 const float* __restrict__ b_qkv) {
    __shared__ float sbv[128];
    __shared__ float suq[128], suk[128];
    extern __shared__ __align__(16) char dsm[];
    char* smb = (char*)((((uintptr_t)dsm) + 1023) & ~(uintptr_t)1023);
    char* smAh = smb;
    char* smAl = smb + 8192;
    char* smBh = smb + 16384;
    char* smBl = smb + 32768;
    uint32_t suAh = smem_u32(smAh), suAl = smem_u32(smAl);
    uint32_t suBh = smem_u32(smBh), suBl = smem_u32(smBl);

    int blk = blockIdx.x;
    int mt = blk >> 2, ng = blk & 3;
    int b = mt >> 5;
    int i0 = (mt & 31) * 64;
    int t = threadIdx.x;
    int w = t >> 5, lane = t & 31;

    if (ng == 3 && t < 128) sbv[t] = b_qkv[2 * D + t];
    if (ng == 0 && t < 128) { suq[t] = g_uq[t]; suk[t] = g_uk[t]; }
    __syncthreads();

    float cc[8][4];
    #pragma unroll
    for (int nt = 0; nt < 8; nt++)
        #pragma unroll
        for (int r = 0; r < 4; r++) cc[nt][r] = 0.f;

    int l8 = lane & 7, grp = lane >> 3;
    int mg = w >> 1, nh = w & 1;
    int rowA = (mg << 4) + l8 + ((grp & 1) << 3);
    int colAg = (grp >> 1) << 4;
    int rowBoff = l8 + ((grp >> 1) << 3);
    int colBg = (grp & 1) << 4;

    int r = t >> 2, h = t & 3;   // 4 threads per A row
    int rowoff = r * 128 + h * 32;
    float dq = 0.f, dk = 0.f;

    #pragma unroll 1
    for (int c = 0; c < 2; c++) {
        if (c) __syncthreads();
        const float4* src = (const float4*)
            (ops + ((size_t)b * C + i0 + r) * D + c * 64 + h * 16);
        #pragma unroll
        for (int q = 0; q < 4; q++) {
            float4 v = src[q];
            if (ng == 0) {
                float4 u4 = *(const float4*)&suq[c * 64 + h * 16 + q * 4];
                float4 k4 = *(const float4*)&suk[c * 64 + h * 16 + q * 4];
                dq += v.x * u4.x + v.y * u4.y + v.z * u4.z + v.w * u4.w;
                dk += v.x * k4.x + v.y * k4.y + v.z * k4.z + v.w * k4.w;
            }
            uint32_t h0, h1, l0, l1;
            split2(v.x, v.y, h0, l0);
            split2(v.z, v.w, h1, l1);
            uint32_t off = rowoff + q * 8;
            *(uint2*)(smAh + SWZ(off)) = make_uint2(h0, h1);
            *(uint2*)(smAl + SWZ(off)) = make_uint2(l0, l1);
        }
        #pragma unroll
        for (int c2 = 0; c2 < 4; c2++) {
            int idx = t + c2 * 256;
            int dd = idx >> 3, ccx = idx & 7;
            uint32_t off = dd * 128 + ccx * 16;
            int gsrc = (ng * 128 + dd) * 128 + c * 64 + ccx * 8;
            *(uint4*)(smBh + SWZ(off)) = *(const uint4*)&g_Wbh[gsrc];
            *(uint4*)(smBl + SWZ(off)) = *(const uint4*)&g_Wbl[gsrc];
        }
        __syncthreads();
        mma_pass64(suAh, suBh, cc, rowA, colAg, nh, rowBoff, colBg);
        mma_pass64(suAh, suBl, cc, rowA, colAg, nh, rowBoff, colBg);
        mma_pass64(suAl, suBh, cc, rowA, colAg, nh, rowBoff, colBg);
    }

    if (ng == 0) {
        dq += __shfl_xor_sync(0xffffffffu, dq, 1);
        dk += __shfl_xor_sync(0xffffffffu, dk, 1);
        dq += __shfl_xor_sync(0xffffffffu, dq, 2);
        dk += __shfl_xor_sync(0xffffffffu, dk, 2);
        if (h == 0) {
            int row = b * C + i0 + r;
            g_sq[row] = dq + g_c[0];
            g_sk[row] = dk + g_c[1];
        }
    }

    int quad = lane >> 2, qt = lane & 3;
    if (ng < 3) {
        float* ob = g_mx + (size_t)ng * BCD + (size_t)b * C * D;
        int r0g = i0 + (mg << 4) + quad;
        #pragma unroll
        for (int nt = 0; nt < 8; nt++) {
            int n0 = (nh << 6) + nt * 8 + 2 * qt;
            *(float2*)&ob[(size_t)r0g * D + n0] = make_float2(cc[nt][0], cc[nt][1]);
            *(float2*)&ob[(size_t)(r0g + 8) * D + n0] = make_float2(cc[nt][2], cc[nt][3]);
        }
    } else {
        // v group: bias, bf16, transpose-stage in smem -> g_vT + colsum
        __syncthreads();
        __nv_bfloat16* vst = (__nv_bfloat16*)smb;   // [128 n][64 m] = 16KB
        int m0 = (mg << 4) + quad, m8 = m0 + 8;
        #pragma unroll
        for (int nt = 0; nt < 8; nt++) {
            int n0 = (nh << 6) + nt * 8 + 2 * qt;
            float vb0 = sbv[n0], vb1 = sbv[n0 + 1];
            vst[n0 * 64 + m0]       = __float2bfloat16(cc[nt][0] + vb0);
            vst[(n0 + 1) * 64 + m0] = __float2bfloat16(cc[nt][1] + vb1);
            vst[n0 * 64 + m8]       = __float2bfloat16(cc[nt][2] + vb0);
            vst[(n0 + 1) * 64 + m8] = __float2bfloat16(cc[nt][3] + vb1);
        }
        __syncthreads();
        int n = t >> 1, hh = t & 1;
        const uint4* srcv = (const uint4*)(vst + n * 64 + hh * 32);
        uint4* dstv = (uint4*)(g_vT + ((size_t)b * D + n) * C + i0 + hh * 32);
        #pragma unroll
        for (int q = 0; q < 4; q++) dstv[q] = srcv[q];
        if (t < 128) {
            float s = 0.f;
            #pragma unroll 16
            for (int m = 0; m < 64; m++) s += __bfloat162float(vst[t * 64 + m]);
            atomicAdd(&g_colsum[b * D + t], s);
        }
    }
}

// ---------------- K2: attention HMMA (64-row tiles) + begin/end side blocks ----------------
// grid 256+16, block 256, occ 2
__global__ void __launch_bounds__(256, 2) k_attn(
    const float* __restrict__ mask, const float* __restrict__ ops,
    const int* __restrict__ bidx, const int* __restrict__ eidx,
    const float* __restrict__ W_begin, const float* __restrict__ b_begin,
    const float* __restrict__ W_end, const float* __restrict__ b_end) {
    __shared__ __align__(128) char smA[64 * 128];
    __shared__ __align__(128) char smB[128 * 128];
    __shared__ float ssq[64];
    __shared__ float srow[64];
    __shared__ float scol[128];

    int t = threadIdx.x;
    int blk = blockIdx.x;

    if (blk >= 256) {
        int e = blk - 256;
        int b = e >> 1, which = e & 1;
        const int* idx = which ? eidx : bidx;
        if (t < 128) {
            float s = 0.f;
            for (int j = 0; j < J; j++)
                s += ops[((size_t)b * C + idx[b * J + j]) * D + t];
            scol[t] = s * (1.0f / (float)J);
        }
        __syncthreads();
        if (t < 128) {
            const float* W = which ? W_end : W_begin;
            const float* bbp = which ? b_end : b_begin;
            float acc = bbp[t];
            #pragma unroll 8
            for (int k = 0; k < D; k++) acc += scol[k] * W[k * D + t];
            g_be[((size_t)b * 2 + which) * D + t] = acc;
        }
        return;
    }

    int w = t >> 5, lane = t & 31;
    int b = blk >> 5;
    int i0 = (blk & 31) * 64;
    int base = b * C;

    uint32_t suA = smem_u32(smA);
    uint32_t suB = smem_u32(smB);

    if (t < 64) ssq[t] = g_sq[base + i0 + t];
    if (t < 128) scol[t] = g_colsum[b * D + t];

    float rowsum[8];
    #pragma unroll
    for (int s = 0; s < 8; s++) rowsum[s] = 0.f;

    float cc[8][4];
    #pragma unroll
    for (int nt = 0; nt < 8; nt++)
        #pragma unroll
        for (int r = 0; r < 4; r++) cc[nt][r] = 0.f;

    const __nv_bfloat16* vTb = g_vT + (size_t)b * D * C;

    int l8 = lane & 7, grp = lane >> 3;
    int mg = w >> 1, nh = w & 1;
    int rowA = (mg << 4) + l8 + ((grp & 1) << 3);
    int colAg = (grp >> 1) << 4;
    int rowBoff = l8 + ((grp >> 1) << 3);
    int colBg = (grp & 1) << 4;

    for (int i = 0; i < C / 64; i++) {
        int jb = i * 64;
        __syncthreads();
        {
            float2 sk2 = *(const float2*)&g_sk[base + jb + 2 * lane];
            const float* mrow0 = mask + (size_t)(base + i0 + w) * C + jb + 2 * lane;
            #pragma unroll
            for (int s = 0; s < 8; s++) {
                int row = w + 8 * s;
                float2 mk = *(const float2*)(mrow0 + (size_t)(8 * s) * C);
                float q = ssq[row];
                float x0 = q + sk2.x; x0 = (x0 >= 0.f) ? x0 : 0.01f * x0; x0 *= mk.x;
                float x1 = q + sk2.y; x1 = (x1 >= 0.f) ? x1 : 0.01f * x1; x1 *= mk.y;
                float p0 = __expf(x0), p1 = __expf(x1);
                rowsum[s] += p0 + p1;
                uint32_t pr; CVT_BF16X2(pr, p0 - 1.f, p1 - 1.f);
                uint32_t off = row * 128 + lane * 4;
                *(uint32_t*)(smA + SWZ(off)) = pr;
            }
        }
        #pragma unroll
        for (int c = 0; c < 4; c++) {
            int idx = t + c * 256;
            int dd = idx >> 3, ccx = idx & 7;
            uint4 val = *(const uint4*)(vTb + (size_t)dd * C + jb + ccx * 8);
            uint32_t off = dd * 128 + ccx * 16;
            *(uint4*)(smB + SWZ(off)) = val;
        }
        __syncthreads();
        mma_pass64(suA, suB, cc, rowA, colAg, nh, rowBoff, colBg);
    }

    #pragma unroll
    for (int s = 0; s < 8; s++) {
        float r = rowsum[s];
        #pragma unroll
        for (int off = 16; off; off >>= 1) r += __shfl_down_sync(0xffffffffu, r, off);
        if (lane == 0) srow[w + 8 * s] = r;
    }
    __syncthreads();

    int quad = lane >> 2, qt = lane & 3;
    int m0 = (mg << 4) + quad;
    float inv0 = 1.0f / srow[m0];
    float inv8 = 1.0f / srow[m0 + 8];
    float* o0 = g_weighted + (size_t)(base + i0 + m0) * D;
    float* o8 = o0 + 8 * D;
    #pragma unroll
    for (int nt = 0; nt < 8; nt++) {
        int n0 = (nh << 6) + nt * 8 + 2 * qt;
        float cs0 = scol[n0], cs1 = scol[n0 + 1];
        *(float2*)(o0 + n0) = make_float2((cs0 + cc[nt][0]) * inv0,
                                          (cs1 + cc[nt][1]) * inv0);
        *(float2*)(o8 + n0) = make_float2((cs0 + cc[nt][2]) * inv8,
                                          (cs1 + cc[nt][3]) * inv8);
    }
}

// ---------------- K3: final mix, 64-row M-tiles, A gather-composed ----------------
// grid 256, block 256, dyn smem 48KB, occ 2
__global__ void __launch_bounds__(256, 2) k_final(const int* __restrict__ rel,
                                                  const float* __restrict__ b_mix3,
                                                  float* __restrict__ out) {
    __shared__ float sb[128];
    __shared__ float sb3[128];
    __shared__ int2 srel[64];
    extern __shared__ __align__(16) char dsm[];
    char* smb = (char*)((((uintptr_t)dsm) + 1023) & ~(uintptr_t)1023);
    char* smAh = smb;
    char* smAl = smb + 8192;
    char* smBh = smb + 16384;
    char* smBl = smb + 32768;
    uint32_t suAh = smem_u32(smAh), suAl = smem_u32(smAl);
    uint32_t suBh = smem_u32(smBh), suBl = smem_u32(smBl);

    int blk = blockIdx.x;
    int t = threadIdx.x;
    int b = blk >> 5;
    int i0 = (blk & 31) * 64;
    int w = t >> 5, lane = t & 31;

    if (t < 128) { sb[t] = g_bc[t]; sb3[t] = b_mix3[t]; }
    if (t < 64) {
        int ig = i0 + t;
        if (ig < CM2) srel[t] = *(const int2*)&rel[((size_t)b * CM2 + ig) * 2];
        else srel[t] = make_int2(0, 0);
    }
    __syncthreads();

    float cc[8][4];
    #pragma unroll
    for (int nt = 0; nt < 8; nt++)
        #pragma unroll
        for (int r = 0; r < 4; r++) cc[nt][r] = 0.f;

    int l8 = lane & 7, grp = lane >> 3;
    int mg = w >> 1, nh = w & 1;
    int rowA = (mg << 4) + l8 + ((grp & 1) << 3);
    int colAg = (grp >> 1) << 4;
    int rowBoff = l8 + ((grp >> 1) << 3);
    int colBg = (grp & 1) << 4;

    int r = t >> 2, h = t & 3;
    int rowoff = r * 128 + h * 32;
    size_t bbase = (size_t)b * C * D;
    const float* m1 = g_mx + bbase;
    const float* m2 = g_mx + BCD + bbase;
    const float* m3 = g_mx + 2 * BCD + bbase;

    #pragma unroll 1
    for (int c = 0; c < 4; c++) {
        if (c) __syncthreads();
        int col0 = (c & 1) * 64 + h * 16;
        if (c < 2) {
            int i = i0 + r;
            if (i < CM2) {
                int2 rr = srel[r];
                const float4* p1 = (const float4*)(m1 + (size_t)i * D + col0);
                const float4* p2 = (const float4*)(m2 + (size_t)rr.x * D + col0);
                const float4* p3 = (const float4*)(m3 + (size_t)rr.y * D + col0);
                const float4* pb = (const float4*)(sb3 + col0);
                #pragma unroll
                for (int q = 0; q < 4; q++) {
                    float4 v = p1[q], v2 = p2[q], v3 = p3[q], vb = pb[q];
                    v.x += v2.x + v3.x + vb.x;
                    v.y += v2.y + v3.y + vb.y;
                    v.z += v2.z + v3.z + vb.z;
                    v.w += v2.w + v3.w + vb.w;
                    uint32_t h0, h1, l0, l1;
                    split2(v.x, v.y, h0, l0);
                    split2(v.z, v.w, h1, l1);
                    uint32_t off = rowoff + q * 8;
                    *(uint2*)(smAh + SWZ(off)) = make_uint2(h0, h1);
                    *(uint2*)(smAl + SWZ(off)) = make_uint2(l0, l1);
                }
            } else {
                const float4* pe = (const float4*)
                    (g_be + ((size_t)b * 2 + (i - CM2)) * D + col0);
                #pragma unroll
                for (int q = 0; q < 4; q++) {
                    float4 v = pe[q];
                    uint32_t h0, h1, l0, l1;
                    split2(v.x, v.y, h0, l0);
                    split2(v.z, v.w, h1, l1);
                    uint32_t off = rowoff + q * 8;
                    *(uint2*)(smAh + SWZ(off)) = make_uint2(h0, h1);
                    *(uint2*)(smAl + SWZ(off)) = make_uint2(l0, l1);
                }
            }
        } else {
            const float4* src = (const float4*)
                (g_weighted + ((size_t)b * C + i0 + r) * D + col0);
            #pragma unroll
            for (int q = 0; q < 4; q++) {
                float4 v = src[q];
                uint32_t h0, h1, l0, l1;
                split2(v.x, v.y, h0, l0);
                split2(v.z, v.w, h1, l1);
                uint32_t off = rowoff + q * 8;
                *(uint2*)(smAh + SWZ(off)) = make_uint2(h0, h1);
                *(uint2*)(smAl + SWZ(off)) = make_uint2(l0, l1);
            }
        }
        #pragma unroll
        for (int c2 = 0; c2 < 4; c2++) {
            int idx = t + c2 * 256;
            int dd = idx >> 3, ccx = idx & 7;
            uint32_t off = dd * 128 + ccx * 16;
            *(uint4*)(smBh + SWZ(off)) = *(const uint4*)&g_W2h[dd * 256 + c * 64 + ccx * 8];
            *(uint4*)(smBl + SWZ(off)) = *(const uint4*)&g_W2l[dd * 256 + c * 64 + ccx * 8];
        }
        __syncthreads();
        mma_pass64(suAh, suBh, cc, rowA, colAg, nh, rowBoff, colBg);
        mma_pass64(suAh, suBl, cc, rowA, colAg, nh, rowBoff, colBg);
        mma_pass64(suAl, suBh, cc, rowA, colAg, nh, rowBoff, colBg);
    }

    int quad = lane >> 2, qt = lane & 3;
    int r0g = i0 + (mg << 4) + quad;
    float* ob = out + (size_t)b * C * D;
    #pragma unroll
    for (int nt = 0; nt < 8; nt++) {
        int n0 = (nh << 6) + nt * 8 + 2 * qt;
        float b0v = sb[n0], b1v = sb[n0 + 1];
        *(float2*)&ob[(size_t)r0g * D + n0] =
            make_float2(cc[nt][0] + b0v, cc[nt][1] + b1v);
        *(float2*)&ob[(size_t)(r0g + 8) * D + n0] =
            make_float2(cc[nt][2] + b0v, cc[nt][3] + b1v);
    }
}

// ---------------- launch ----------------
extern "C" void kernel_launch(void* const* d_in, const int* in_sizes, int n_in,
                              void* d_out, int out_size) {
    const float* ops      = (const float*)d_in[0];
    const int*   rel      = (const int*)d_in[1];
    const int*   bidx     = (const int*)d_in[2];
    const int*   eidx     = (const int*)d_in[3];
    const float* mask     = (const float*)d_in[4];
    const float* W_begin  = (const float*)d_in[5];
    const float* b_begin  = (const float*)d_in[6];
    const float* W_end    = (const float*)d_in[7];
    const float* b_end    = (const float*)d_in[8];
    const float* W_mix3   = (const float*)d_in[9];
    const float* b_mix3   = (const float*)d_in[10];
    const float* W_qkv    = (const float*)d_in[11];
    const float* b_qkv    = (const float*)d_in[12];
    const float* w_score  = (const float*)d_in[13];
    const float* b_score  = (const float*)d_in[14];
    const float* W_out    = (const float*)d_in[15];
    const float* b_out    = (const float*)d_in[16];
    const float* W_mix2   = (const float*)d_in[17];
    const float* b_mix2   = (const float*)d_in[18];
    float* out = (float*)d_out;

    static bool attr_set = false;
    if (!attr_set) {
        cudaFuncSetAttribute(k_gemm, cudaFuncAttributeMaxDynamicSharedMemorySize, SMEM_MMA2);
        cudaFuncSetAttribute(k_final, cudaFuncAttributeMaxDynamicSharedMemorySize, SMEM_MMA2);
        attr_set = true;
    }

    k_pre<<<769, 128>>>(W_qkv, b_qkv, w_score, b_score, W_out, b_out,
                        W_mix2, b_mix2, W_mix3);
    k_gemm<<<1024, 256, SMEM_MMA2>>>(ops, b_qkv);
    k_attn<<<256 + 2 * B, 256>>>(mask, ops, bidx, eidx,
                                 W_begin, b_begin, W_end, b_end);
    k_final<<<256, 256, SMEM_MMA2>>>(rel, b_mix3, out);
}

// round 11
// speedup vs baseline: 4.5716x; 1.0517x over previous
#include <cuda_runtime.h>
#include <cuda_bf16.h>
#include <cstdint>

#define B 8
#define C 2048
#define D 128
#define J 128
#define CM2 (C - 2)   // 2046
#define BCD (B * C * D)

// ---------------- scratch (device globals) ----------------
__device__ __align__(16) __nv_bfloat16 g_vT[B * D * C];   // v bf16 transposed [b][d][j]
__device__ __align__(16) float g_weighted[BCD];
__device__ __align__(16) float g_mx[3 * BCD];             // Pa / Pb / Pc = ops@(W3x@W2a)
__device__ __align__(16) float g_beW[B * 2 * D];          // (begin/end)@W_mix2[:D] + bc0
__device__ float g_colsum[B * D];
__device__ float g_sq[B * C];
__device__ float g_sk[B * C];
__device__ float g_uq[D];
__device__ float g_uk[D];
__device__ float g_c[2];
__device__ float g_bc0[D];                                // b_out@W2b + b_mix2
__device__ float g_bc3[D];                                // bc0 + b_mix3@W2a
// split-bf16 transposed weights
__device__ __align__(16) __nv_bfloat16 g_Wbh[512 * D];    // [W3a'|W3b'|W3c'|Wv] as [n][k]
__device__ __align__(16) __nv_bfloat16 g_Wbl[512 * D];
__device__ __align__(16) __nv_bfloat16 g_Wch[D * D];      // Wc = W_out@W2b as [n][k], hi only

// ---------------- helpers ----------------
__device__ __forceinline__ uint32_t smem_u32(const void* p) {
    uint32_t a;
    asm("{ .reg .u64 tmp; cvta.to.shared.u64 tmp, %1; cvt.u32.u64 %0, tmp; }"
        : "=r"(a) : "l"(p));
    return a;
}
#define CVT_BF16X2(res, a, b) \
    asm("cvt.rn.satfinite.bf16x2.f32 %0, %1, %2;" : "=r"(res) : "f"(b), "f"(a))
#define SWZ(x) ((x) ^ (((x) >> 3) & 0x70))

__device__ __forceinline__ void ldm_x4(uint32_t& r0, uint32_t& r1, uint32_t& r2,
                                       uint32_t& r3, uint32_t addr) {
    asm volatile("ldmatrix.sync.aligned.m8n8.x4.shared.b16 {%0,%1,%2,%3}, [%4];"
                 : "=r"(r0), "=r"(r1), "=r"(r2), "=r"(r3) : "r"(addr));
}
__device__ __forceinline__ void mma16816(float* c, uint32_t a0, uint32_t a1,
                                         uint32_t a2, uint32_t a3,
                                         uint32_t b0, uint32_t b1) {
    asm volatile(
        "mma.sync.aligned.m16n8k16.row.col.f32.bf16.bf16.f32 "
        "{%0,%1,%2,%3}, {%4,%5,%6,%7}, {%8,%9}, {%0,%1,%2,%3};"
        : "+f"(c[0]), "+f"(c[1]), "+f"(c[2]), "+f"(c[3])
        : "r"(a0), "r"(a1), "r"(a2), "r"(a3), "r"(b0), "r"(b1));
}
__device__ __forceinline__ void split2(float x0, float x1, uint32_t& hp, uint32_t& lp) {
    CVT_BF16X2(hp, x0, x1);
    __nv_bfloat162 hv = *reinterpret_cast<__nv_bfloat162*>(&hp);
    float f0 = __bfloat162float(hv.x), f1 = __bfloat162float(hv.y);
    CVT_BF16X2(lp, x0 - f0, x1 - f1);
}
// one K=64 pass: warp (mg, nh) computes 16m x 64n, A tile 64 rows
__device__ __forceinline__ void mma_pass64(uint32_t suA, uint32_t suB, float cc[8][4],
                                           int rowA, int colAg, int nh,
                                           int rowBoff, int colBg) {
    #pragma unroll
    for (int ks = 0; ks < 4; ks++) {
        uint32_t a0, a1, a2, a3;
        ldm_x4(a0, a1, a2, a3, suA + SWZ(rowA * 128 + ks * 32 + colAg));
        #pragma unroll
        for (int nt = 0; nt < 8; nt += 2) {
            uint32_t b0, b1, b2, b3;
            int rowB = (nh << 6) + nt * 8 + rowBoff;
            ldm_x4(b0, b1, b2, b3, suB + SWZ(rowB * 128 + ks * 32 + colBg));
            mma16816(cc[nt],     a0, a1, a2, a3, b0, b1);
            mma16816(cc[nt + 1], a0, a1, a2, a3, b2, b3);
        }
    }
}

#define SMEM_MMA2 (49152 + 1024)

// ---------------- K0: folded + split/transposed weights ----------------
// grid 641, block 128
__global__ void k_pre(const float* __restrict__ W_qkv, const float* __restrict__ b_qkv,
                      const float* __restrict__ w_score, const float* __restrict__ b_score,
                      const float* __restrict__ W_out, const float* __restrict__ b_out,
                      const float* __restrict__ W_mix2, const float* __restrict__ b_mix2,
                      const float* __restrict__ W_mix3, const float* __restrict__ b_mix3) {
    int t = threadIdx.x;
    int blk = blockIdx.x;
    if (blk < D) {
        // Wc[k=blk][n=t] = sum_m W_out[blk][m] * W_mix2[(D+m)][t]
        float acc = 0.f;
        #pragma unroll 8
        for (int m = 0; m < D; m++) acc += W_out[blk * D + m] * W_mix2[(D + m) * D + t];
        g_Wch[t * 128 + blk] = __float2bfloat16(acc);
    } else if (blk == D) {
        float uq = 0.f, uk = 0.f;
        #pragma unroll 8
        for (int c = 0; c < D; c++) {
            uq += W_qkv[t * 3 * D + c] * w_score[c];
            uk += W_qkv[t * 3 * D + D + c] * w_score[D + c];
        }
        g_uq[t] = uq;
        g_uk[t] = uk;
        float bc0 = b_mix2[t];
        #pragma unroll 8
        for (int m = 0; m < D; m++) bc0 += b_out[m] * W_mix2[(D + m) * D + t];
        g_bc0[t] = bc0;
        float bc3 = bc0;
        #pragma unroll 8
        for (int m = 0; m < D; m++) bc3 += b_mix3[m] * W_mix2[m * D + t];
        g_bc3[t] = bc3;
        #pragma unroll
        for (int i = t; i < B * D; i += 128) g_colsum[i] = 0.f;
        __shared__ float s1[D], s2[D];
        s1[t] = b_qkv[t] * w_score[t];
        s2[t] = b_qkv[D + t] * w_score[D + t];
        __syncthreads();
        for (int off = 64; off; off >>= 1) {
            if (t < off) { s1[t] += s1[t + off]; s2[t] += s2[t + off]; }
            __syncthreads();
        }
        if (t == 0) { g_c[0] = s1[0]; g_c[1] = s2[0] + b_score[0]; }
    } else if (blk < 129 + 384) {
        // W3x'[k][n] = sum_m W_mix3[(x*128+k)][m] * W_mix2[m][n]; block=(x,k), t=n
        int e = blk - 129;
        int x = e >> 7, k = e & 127;
        const float* w3row = W_mix3 + (size_t)(x * 128 + k) * D;
        float acc = 0.f;
        #pragma unroll 8
        for (int m = 0; m < D; m++) acc += w3row[m] * W_mix2[m * D + t];
        __nv_bfloat16 h = __float2bfloat16(acc);
        g_Wbh[(x * 128 + t) * 128 + k] = h;
        g_Wbl[(x * 128 + t) * 128 + k] = __float2bfloat16(acc - __bfloat162float(h));
    } else {
        // v weights: B[384+n][k] = W_qkv[k][2D+n]; block k, thread t=n
        int k = blk - 513;
        float w = W_qkv[k * 3 * D + 2 * D + t];
        __nv_bfloat16 h = __float2bfloat16(w);
        g_Wbh[(384 + t) * 128 + k] = h;
        g_Wbl[(384 + t) * 128 + k] = __float2bfloat16(w - __bfloat162float(h));
    }
}

// ---------------- K1: big GEMM ops @ [W3a'|W3b'|W3c'|Wv], 64-row M-tiles ----------------
// grid 1024 (256 Mtiles x 4 Ngroups, ng fastest), block 256, dyn smem 48KB, occ 2
__global__ void __launch_bounds__(256, 2) k_gemm(const float* __restrict__ ops,
                                                 const float* __restrict__ b_qkv) {
    __shared__ float sbv[128];
    __shared__ float suq[128], suk[128];
    extern __shared__ __align__(16) char dsm[];
    char* smb = (char*)((((uintptr_t)dsm) + 1023) & ~(uintptr_t)1023);
    char* smAh = smb;
    char* smAl = smb + 8192;
    char* smBh = smb + 16384;
    char* smBl = smb + 32768;
    uint32_t suAh = smem_u32(smAh), suAl = smem_u32(smAl);
    uint32_t suBh = smem_u32(smBh), suBl = smem_u32(smBl);

    int blk = blockIdx.x;
    int mt = blk >> 2, ng = blk & 3;
    int b = mt >> 5;
    int i0 = (mt & 31) * 64;
    int t = threadIdx.x;
    int w = t >> 5, lane = t & 31;

    if (ng == 3 && t < 128) sbv[t] = b_qkv[2 * D + t];
    if (ng == 0 && t < 128) { suq[t] = g_uq[t]; suk[t] = g_uk[t]; }
    __syncthreads();

    float cc[8][4];
    #pragma unroll
    for (int nt = 0; nt < 8; nt++)
        #pragma unroll
        for (int r = 0; r < 4; r++) cc[nt][r] = 0.f;

    int l8 = lane & 7, grp = lane >> 3;
    int mg = w >> 1, nh = w & 1;
    int rowA = (mg << 4) + l8 + ((grp & 1) << 3);
    int colAg = (grp >> 1) << 4;
    int rowBoff = l8 + ((grp >> 1) << 3);
    int colBg = (grp & 1) << 4;

    int r = t >> 2, h = t & 3;   // 4 threads per A row
    int rowoff = r * 128 + h * 32;
    float dq = 0.f, dk = 0.f;

    #pragma unroll 1
    for (int c = 0; c < 2; c++) {
        if (c) __syncthreads();
        const float4* src = (const float4*)
            (ops + ((size_t)b * C + i0 + r) * D + c * 64 + h * 16);
        #pragma unroll
        for (int q = 0; q < 4; q++) {
            float4 v = src[q];
            if (ng == 0) {
                float4 u4 = *(const float4*)&suq[c * 64 + h * 16 + q * 4];
                float4 k4 = *(const float4*)&suk[c * 64 + h * 16 + q * 4];
                dq += v.x * u4.x + v.y * u4.y + v.z * u4.z + v.w * u4.w;
                dk += v.x * k4.x + v.y * k4.y + v.z * k4.z + v.w * k4.w;
            }
            uint32_t h0, h1, l0, l1;
            split2(v.x, v.y, h0, l0);
            split2(v.z, v.w, h1, l1);
            uint32_t off = rowoff + q * 8;
            *(uint2*)(smAh + SWZ(off)) = make_uint2(h0, h1);
            *(uint2*)(smAl + SWZ(off)) = make_uint2(l0, l1);
        }
        #pragma unroll
        for (int c2 = 0; c2 < 4; c2++) {
            int idx = t + c2 * 256;
            int dd = idx >> 3, ccx = idx & 7;
            uint32_t off = dd * 128 + ccx * 16;
            int gsrc = (ng * 128 + dd) * 128 + c * 64 + ccx * 8;
            *(uint4*)(smBh + SWZ(off)) = *(const uint4*)&g_Wbh[gsrc];
            *(uint4*)(smBl + SWZ(off)) = *(const uint4*)&g_Wbl[gsrc];
        }
        __syncthreads();
        mma_pass64(suAh, suBh, cc, rowA, colAg, nh, rowBoff, colBg);
        mma_pass64(suAh, suBl, cc, rowA, colAg, nh, rowBoff, colBg);
        mma_pass64(suAl, suBh, cc, rowA, colAg, nh, rowBoff, colBg);
    }

    if (ng == 0) {
        dq += __shfl_xor_sync(0xffffffffu, dq, 1);
        dk += __shfl_xor_sync(0xffffffffu, dk, 1);
        dq += __shfl_xor_sync(0xffffffffu, dq, 2);
        dk += __shfl_xor_sync(0xffffffffu, dk, 2);
        if (h == 0) {
            int row = b * C + i0 + r;
            g_sq[row] = dq + g_c[0];
            g_sk[row] = dk + g_c[1];
        }
    }

    int quad = lane >> 2, qt = lane & 3;
    if (ng < 3) {
        float* ob = g_mx + (size_t)ng * BCD + (size_t)b * C * D;
        int r0g = i0 + (mg << 4) + quad;
        #pragma unroll
        for (int nt = 0; nt < 8; nt++) {
            int n0 = (nh << 6) + nt * 8 + 2 * qt;
            *(float2*)&ob[(size_t)r0g * D + n0] = make_float2(cc[nt][0], cc[nt][1]);
            *(float2*)&ob[(size_t)(r0g + 8) * D + n0] = make_float2(cc[nt][2], cc[nt][3]);
        }
    } else {
        // v group: bias, bf16, transpose-stage in smem -> g_vT + colsum
        __syncthreads();
        __nv_bfloat16* vst = (__nv_bfloat16*)smb;   // [128 n][64 m] = 16KB
        int m0 = (mg << 4) + quad, m8 = m0 + 8;
        #pragma unroll
        for (int nt = 0; nt < 8; nt++) {
            int n0 = (nh << 6) + nt * 8 + 2 * qt;
            float vb0 = sbv[n0], vb1 = sbv[n0 + 1];
            vst[n0 * 64 + m0]       = __float2bfloat16(cc[nt][0] + vb0);
            vst[(n0 + 1) * 64 + m0] = __float2bfloat16(cc[nt][1] + vb1);
            vst[n0 * 64 + m8]       = __float2bfloat16(cc[nt][2] + vb0);
            vst[(n0 + 1) * 64 + m8] = __float2bfloat16(cc[nt][3] + vb1);
        }
        __syncthreads();
        int n = t >> 1, hh = t & 1;
        const uint4* srcv = (const uint4*)(vst + n * 64 + hh * 32);
        uint4* dstv = (uint4*)(g_vT + ((size_t)b * D + n) * C + i0 + hh * 32);
        #pragma unroll
        for (int q = 0; q < 4; q++) dstv[q] = srcv[q];
        if (t < 128) {
            float s = 0.f;
            #pragma unroll 16
            for (int m = 0; m < 64; m++) s += __bfloat162float(vst[t * 64 + m]);
            atomicAdd(&g_colsum[b * D + t], s);
        }
    }
}

// ---------------- K2: attention HMMA (64-row tiles) + begin/end side blocks ----------------
// grid 256+16, block 256, occ 2
__global__ void __launch_bounds__(256, 2) k_attn(
    const float* __restrict__ mask, const float* __restrict__ ops,
    const int* __restrict__ bidx, const int* __restrict__ eidx,
    const float* __restrict__ W_begin, const float* __restrict__ b_begin,
    const float* __restrict__ W_end, const float* __restrict__ b_end,
    const float* __restrict__ W_mix2) {
    __shared__ __align__(128) char smA[64 * 128];
    __shared__ __align__(128) char smB[128 * 128];
    __shared__ float ssq[64];
    __shared__ float srow[64];
    __shared__ float scol[128];

    int t = threadIdx.x;
    int blk = blockIdx.x;

    if (blk >= 256) {
        // begin/end: be = mean@W +b; then beW = be@W_mix2[:D] + bc0
        int e = blk - 256;
        int b = e >> 1, which = e & 1;
        const int* idx = which ? eidx : bidx;
        float* sbe = (float*)smA;
        if (t < 128) {
            float s = 0.f;
            for (int j = 0; j < J; j++)
                s += ops[((size_t)b * C + idx[b * J + j]) * D + t];
            scol[t] = s * (1.0f / (float)J);
        }
        __syncthreads();
        if (t < 128) {
            const float* W = which ? W_end : W_begin;
            const float* bbp = which ? b_end : b_begin;
            float acc = bbp[t];
            #pragma unroll 8
            for (int k = 0; k < D; k++) acc += scol[k] * W[k * D + t];
            sbe[t] = acc;
        }
        __syncthreads();
        if (t < 128) {
            float acc2 = g_bc0[t];
            #pragma unroll 8
            for (int k = 0; k < D; k++) acc2 += sbe[k] * W_mix2[k * D + t];
            g_beW[((size_t)b * 2 + which) * D + t] = acc2;
        }
        return;
    }

    int w = t >> 5, lane = t & 31;
    int b = blk >> 5;
    int i0 = (blk & 31) * 64;
    int base = b * C;

    uint32_t suA = smem_u32(smA);
    uint32_t suB = smem_u32(smB);

    if (t < 64) ssq[t] = g_sq[base + i0 + t];
    if (t < 128) scol[t] = g_colsum[b * D + t];

    float rowsum[8];
    #pragma unroll
    for (int s = 0; s < 8; s++) rowsum[s] = 0.f;

    float cc[8][4];
    #pragma unroll
    for (int nt = 0; nt < 8; nt++)
        #pragma unroll
        for (int r = 0; r < 4; r++) cc[nt][r] = 0.f;

    const __nv_bfloat16* vTb = g_vT + (size_t)b * D * C;

    int l8 = lane & 7, grp = lane >> 3;
    int mg = w >> 1, nh = w & 1;
    int rowA = (mg << 4) + l8 + ((grp & 1) << 3);
    int colAg = (grp >> 1) << 4;
    int rowBoff = l8 + ((grp >> 1) << 3);
    int colBg = (grp & 1) << 4;

    for (int i = 0; i < C / 64; i++) {
        int jb = i * 64;
        __syncthreads();
        {
            float2 sk2 = *(const float2*)&g_sk[base + jb + 2 * lane];
            const float* mrow0 = mask + (size_t)(base + i0 + w) * C + jb + 2 * lane;
            #pragma unroll
            for (int s = 0; s < 8; s++) {
                int row = w + 8 * s;
                float2 mk = *(const float2*)(mrow0 + (size_t)(8 * s) * C);
                float q = ssq[row];
                float x0 = q + sk2.x; x0 = (x0 >= 0.f) ? x0 : 0.01f * x0; x0 *= mk.x;
                float x1 = q + sk2.y; x1 = (x1 >= 0.f) ? x1 : 0.01f * x1; x1 *= mk.y;
                float p0 = __expf(x0), p1 = __expf(x1);
                rowsum[s] += p0 + p1;
                uint32_t pr; CVT_BF16X2(pr, p0 - 1.f, p1 - 1.f);
                uint32_t off = row * 128 + lane * 4;
                *(uint32_t*)(smA + SWZ(off)) = pr;
            }
        }
        #pragma unroll
        for (int c = 0; c < 4; c++) {
            int idx = t + c * 256;
            int dd = idx >> 3, ccx = idx & 7;
            uint4 val = *(const uint4*)(vTb + (size_t)dd * C + jb + ccx * 8);
            uint32_t off = dd * 128 + ccx * 16;
            *(uint4*)(smB + SWZ(off)) = val;
        }
        __syncthreads();
        mma_pass64(suA, suB, cc, rowA, colAg, nh, rowBoff, colBg);
    }

    #pragma unroll
    for (int s = 0; s < 8; s++) {
        float r = rowsum[s];
        #pragma unroll
        for (int off = 16; off; off >>= 1) r += __shfl_down_sync(0xffffffffu, r, off);
        if (lane == 0) srow[w + 8 * s] = r;
    }
    __syncthreads();

    int quad = lane >> 2, qt = lane & 3;
    int m0 = (mg << 4) + quad;
    float inv0 = 1.0f / srow[m0];
    float inv8 = 1.0f / srow[m0 + 8];
    float* o0 = g_weighted + (size_t)(base + i0 + m0) * D;
    float* o8 = o0 + 8 * D;
    #pragma unroll
    for (int nt = 0; nt < 8; nt++) {
        int n0 = (nh << 6) + nt * 8 + 2 * qt;
        float cs0 = scol[n0], cs1 = scol[n0 + 1];
        *(float2*)(o0 + n0) = make_float2((cs0 + cc[nt][0]) * inv0,
                                          (cs1 + cc[nt][1]) * inv0);
        *(float2*)(o8 + n0) = make_float2((cs0 + cc[nt][2]) * inv8,
                                          (cs1 + cc[nt][3]) * inv8);
    }
}

// ---------------- K3: weighted@Wc (hi-only) + gather-add epilogue ----------------
// grid 256, block 256, static smem 24KB
__global__ void __launch_bounds__(256, 2) k_final(const int* __restrict__ rel,
                                                  float* __restrict__ out) {
    __shared__ __align__(128) char smA[64 * 128];     // 8 KB
    __shared__ __align__(128) char smB[128 * 128];    // 16 KB
    __shared__ float sb3[128];
    __shared__ int2 srel[64];
    uint32_t suA = smem_u32(smA), suB = smem_u32(smB);

    int blk = blockIdx.x;
    int t = threadIdx.x;
    int b = blk >> 5;
    int i0 = (blk & 31) * 64;
    int w = t >> 5, lane = t & 31;

    if (t < 128) sb3[t] = g_bc3[t];
    if (t < 64) {
        int ig = i0 + t;
        srel[t] = (ig < CM2) ? *(const int2*)&rel[((size_t)b * CM2 + ig) * 2]
                             : make_int2(0, 0);
    }

    float cc[8][4];
    #pragma unroll
    for (int nt = 0; nt < 8; nt++)
        #pragma unroll
        for (int r = 0; r < 4; r++) cc[nt][r] = 0.f;

    int l8 = lane & 7, grp = lane >> 3;
    int mg = w >> 1, nh = w & 1;
    int rowA = (mg << 4) + l8 + ((grp & 1) << 3);
    int colAg = (grp >> 1) << 4;
    int rowBoff = l8 + ((grp >> 1) << 3);
    int colBg = (grp & 1) << 4;

    int r = t >> 2, h = t & 3;
    int rowoff = r * 128 + h * 32;

    #pragma unroll 1
    for (int c = 0; c < 2; c++) {
        if (c) __syncthreads();
        const float4* src = (const float4*)
            (g_weighted + ((size_t)b * C + i0 + r) * D + c * 64 + h * 16);
        #pragma unroll
        for (int q = 0; q < 4; q++) {
            float4 v = src[q];
            uint32_t h0, h1;
            CVT_BF16X2(h0, v.x, v.y);
            CVT_BF16X2(h1, v.z, v.w);
            *(uint2*)(smA + SWZ(rowoff + q * 8)) = make_uint2(h0, h1);
        }
        #pragma unroll
        for (int c2 = 0; c2 < 4; c2++) {
            int idx = t + c2 * 256;
            int dd = idx >> 3, ccx = idx & 7;
            *(uint4*)(smB + SWZ(dd * 128 + ccx * 16)) =
                *(const uint4*)&g_Wch[dd * 128 + c * 64 + ccx * 8];
        }
        __syncthreads();
        mma_pass64(suA, suB, cc, rowA, colAg, nh, rowBoff, colBg);
    }

    // epilogue: out = Pa[i] + Pb[r0] + Pc[r1] + bc3 + cc   (or g_beW + cc)
    int quad = lane >> 2, qt = lane & 3;
    int r0g = i0 + (mg << 4) + quad;
    size_t bb = (size_t)b * C * D;
    const float* m1 = g_mx + bb;
    const float* m2 = g_mx + BCD + bb;
    const float* m3 = g_mx + 2 * BCD + bb;
    float* ob = out + bb;

    #pragma unroll
    for (int half = 0; half < 2; half++) {
        int rg = r0g + half * 8;
        int loc = rg - i0;
        if (rg < CM2) {
            int2 rr = srel[loc];
            const float* pa = m1 + (size_t)rg * D;
            const float* pb = m2 + (size_t)rr.x * D;
            const float* pc = m3 + (size_t)rr.y * D;
            #pragma unroll
            for (int nt = 0; nt < 8; nt++) {
                int n0 = (nh << 6) + nt * 8 + 2 * qt;
                float2 a2 = *(const float2*)(pa + n0);
                float2 b2 = *(const float2*)(pb + n0);
                float2 c2v = *(const float2*)(pc + n0);
                float vx = a2.x + b2.x + c2v.x + sb3[n0] + cc[nt][2 * half];
                float vy = a2.y + b2.y + c2v.y + sb3[n0 + 1] + cc[nt][2 * half + 1];
                *(float2*)&ob[(size_t)rg * D + n0] = make_float2(vx, vy);
            }
        } else {
            const float* pe = g_beW + ((size_t)b * 2 + (rg - CM2)) * D;
            #pragma unroll
            for (int nt = 0; nt < 8; nt++) {
                int n0 = (nh << 6) + nt * 8 + 2 * qt;
                float2 ev = *(const float2*)(pe + n0);
                *(float2*)&ob[(size_t)rg * D + n0] =
                    make_float2(ev.x + cc[nt][2 * half],
                                ev.y + cc[nt][2 * half + 1]);
            }
        }
    }
}

// ---------------- launch ----------------
extern "C" void kernel_launch(void* const* d_in, const int* in_sizes, int n_in,
                              void* d_out, int out_size) {
    const float* ops      = (const float*)d_in[0];
    const int*   rel      = (const int*)d_in[1];
    const int*   bidx     = (const int*)d_in[2];
    const int*   eidx     = (const int*)d_in[3];
    const float* mask     = (const float*)d_in[4];
    const float* W_begin  = (const float*)d_in[5];
    const float* b_begin  = (const float*)d_in[6];
    const float* W_end    = (const float*)d_in[7];
    const float* b_end    = (const float*)d_in[8];
    const float* W_mix3   = (const float*)d_in[9];
    const float* b_mix3   = (const float*)d_in[10];
    const float* W_qkv    = (const float*)d_in[11];
    const float* b_qkv    = (const float*)d_in[12];
    const float* w_score  = (const float*)d_in[13];
    const float* b_score  = (const float*)d_in[14];
    const float* W_out    = (const float*)d_in[15];
    const float* b_out    = (const float*)d_in[16];
    const float* W_mix2   = (const float*)d_in[17];
    const float* b_mix2   = (const float*)d_in[18];
    float* out = (float*)d_out;

    static bool attr_set = false;
    if (!attr_set) {
        cudaFuncSetAttribute(k_gemm, cudaFuncAttributeMaxDynamicSharedMemorySize, SMEM_MMA2);
        attr_set = true;
    }

    k_pre<<<641, 128>>>(W_qkv, b_qkv, w_score, b_score, W_out, b_out,
                        W_mix2, b_mix2, W_mix3, b_mix3);
    k_gemm<<<1024, 256, SMEM_MMA2>>>(ops, b_qkv);
    k_attn<<<256 + 2 * B, 256>>>(mask, ops, bidx, eidx,
                                 W_begin, b_begin, W_end, b_end, W_mix2);
    k_final<<<256, 256>>>(rel, out);
}

// round 12
// speedup vs baseline: 4.6689x; 1.0213x over previous
#include <cuda_runtime.h>
#include <cuda_bf16.h>
#include <cstdint>

#define B 8
#define C 2048
#define D 128
#define J 128
#define CM2 (C - 2)   // 2046
#define BCD (B * C * D)

// ---------------- scratch (device globals) ----------------
__device__ __align__(16) __nv_bfloat16 g_vT[B * D * C];   // v bf16 transposed [b][d][j]
__device__ __align__(16) float g_mx[3 * BCD];             // Pa / Pb / Pc = ops@(W3x@W2a)
__device__ __align__(16) float g_beW[B * 2 * D];          // (begin/end)@W_mix2[:D] + bc0
__device__ float g_colsum[B * D];
__device__ float g_sq[B * C];
__device__ float g_sk[B * C];
__device__ float g_uq[D];
__device__ float g_uk[D];
__device__ float g_c[2];
__device__ float g_bc0[D];                                // b_out@W2b + b_mix2
__device__ float g_bc3[D];                                // bc0 + b_mix3@W2a
// split-bf16 transposed weights
__device__ __align__(16) __nv_bfloat16 g_Wbh[512 * D];    // [W3a'|W3b'|W3c'|Wv] as [n][k]
__device__ __align__(16) __nv_bfloat16 g_Wbl[512 * D];
__device__ __align__(16) __nv_bfloat16 g_Wch[D * D];      // Wc = W_out@W2b as [n][k], hi only

// ---------------- helpers ----------------
__device__ __forceinline__ uint32_t smem_u32(const void* p) {
    uint32_t a;
    asm("{ .reg .u64 tmp; cvta.to.shared.u64 tmp, %1; cvt.u32.u64 %0, tmp; }"
        : "=r"(a) : "l"(p));
    return a;
}
#define CVT_BF16X2(res, a, b) \
    asm("cvt.rn.satfinite.bf16x2.f32 %0, %1, %2;" : "=r"(res) : "f"(b), "f"(a))
#define SWZ(x) ((x) ^ (((x) >> 3) & 0x70))

__device__ __forceinline__ void ldm_x4(uint32_t& r0, uint32_t& r1, uint32_t& r2,
                                       uint32_t& r3, uint32_t addr) {
    asm volatile("ldmatrix.sync.aligned.m8n8.x4.shared.b16 {%0,%1,%2,%3}, [%4];"
                 : "=r"(r0), "=r"(r1), "=r"(r2), "=r"(r3) : "r"(addr));
}
__device__ __forceinline__ void mma16816(float* c, uint32_t a0, uint32_t a1,
                                         uint32_t a2, uint32_t a3,
                                         uint32_t b0, uint32_t b1) {
    asm volatile(
        "mma.sync.aligned.m16n8k16.row.col.f32.bf16.bf16.f32 "
        "{%0,%1,%2,%3}, {%4,%5,%6,%7}, {%8,%9}, {%0,%1,%2,%3};"
        : "+f"(c[0]), "+f"(c[1]), "+f"(c[2]), "+f"(c[3])
        : "r"(a0), "r"(a1), "r"(a2), "r"(a3), "r"(b0), "r"(b1));
}
__device__ __forceinline__ void split2(float x0, float x1, uint32_t& hp, uint32_t& lp) {
    CVT_BF16X2(hp, x0, x1);
    __nv_bfloat162 hv = *reinterpret_cast<__nv_bfloat162*>(&hp);
    float f0 = __bfloat162float(hv.x), f1 = __bfloat162float(hv.y);
    CVT_BF16X2(lp, x0 - f0, x1 - f1);
}
// one K=64 pass: warp (mg, nh) computes 16m x 64n, A tile 64 rows
__device__ __forceinline__ void mma_pass64(uint32_t suA, uint32_t suB, float cc[8][4],
                                           int rowA, int colAg, int nh,
                                           int rowBoff, int colBg) {
    #pragma unroll
    for (int ks = 0; ks < 4; ks++) {
        uint32_t a0, a1, a2, a3;
        ldm_x4(a0, a1, a2, a3, suA + SWZ(rowA * 128 + ks * 32 + colAg));
        #pragma unroll
        for (int nt = 0; nt < 8; nt += 2) {
            uint32_t b0, b1, b2, b3;
            int rowB = (nh << 6) + nt * 8 + rowBoff;
            ldm_x4(b0, b1, b2, b3, suB + SWZ(rowB * 128 + ks * 32 + colBg));
            mma16816(cc[nt],     a0, a1, a2, a3, b0, b1);
            mma16816(cc[nt + 1], a0, a1, a2, a3, b2, b3);
        }
    }
}

#define SMEM_MMA2 (49152 + 1024)

// ---------------- K0: folded + split/transposed weights ----------------
// grid 641, block 128
__global__ void k_pre(const float* __restrict__ W_qkv, const float* __restrict__ b_qkv,
                      const float* __restrict__ w_score, const float* __restrict__ b_score,
                      const float* __restrict__ W_out, const float* __restrict__ b_out,
                      const float* __restrict__ W_mix2, const float* __restrict__ b_mix2,
                      const float* __restrict__ W_mix3, const float* __restrict__ b_mix3) {
    int t = threadIdx.x;
    int blk = blockIdx.x;
    if (blk < D) {
        float acc = 0.f;
        #pragma unroll 8
        for (int m = 0; m < D; m++) acc += W_out[blk * D + m] * W_mix2[(D + m) * D + t];
        g_Wch[t * 128 + blk] = __float2bfloat16(acc);
    } else if (blk == D) {
        float uq = 0.f, uk = 0.f;
        #pragma unroll 8
        for (int c = 0; c < D; c++) {
            uq += W_qkv[t * 3 * D + c] * w_score[c];
            uk += W_qkv[t * 3 * D + D + c] * w_score[D + c];
        }
        g_uq[t] = uq;
        g_uk[t] = uk;
        float bc0 = b_mix2[t];
        #pragma unroll 8
        for (int m = 0; m < D; m++) bc0 += b_out[m] * W_mix2[(D + m) * D + t];
        g_bc0[t] = bc0;
        float bc3 = bc0;
        #pragma unroll 8
        for (int m = 0; m < D; m++) bc3 += b_mix3[m] * W_mix2[m * D + t];
        g_bc3[t] = bc3;
        #pragma unroll
        for (int i = t; i < B * D; i += 128) g_colsum[i] = 0.f;
        __shared__ float s1[D], s2[D];
        s1[t] = b_qkv[t] * w_score[t];
        s2[t] = b_qkv[D + t] * w_score[D + t];
        __syncthreads();
        for (int off = 64; off; off >>= 1) {
            if (t < off) { s1[t] += s1[t + off]; s2[t] += s2[t + off]; }
            __syncthreads();
        }
        if (t == 0) { g_c[0] = s1[0]; g_c[1] = s2[0] + b_score[0]; }
    } else if (blk < 129 + 384) {
        // W3x'[k][n] = sum_m W_mix3[(x*128+k)][m] * W_mix2[m][n]
        int e = blk - 129;
        int x = e >> 7, k = e & 127;
        const float* w3row = W_mix3 + (size_t)(x * 128 + k) * D;
        float acc = 0.f;
        #pragma unroll 8
        for (int m = 0; m < D; m++) acc += w3row[m] * W_mix2[m * D + t];
        __nv_bfloat16 h = __float2bfloat16(acc);
        g_Wbh[(x * 128 + t) * 128 + k] = h;
        g_Wbl[(x * 128 + t) * 128 + k] = __float2bfloat16(acc - __bfloat162float(h));
    } else {
        int k = blk - 513;
        float w = W_qkv[k * 3 * D + 2 * D + t];
        __nv_bfloat16 h = __float2bfloat16(w);
        g_Wbh[(384 + t) * 128 + k] = h;
        g_Wbl[(384 + t) * 128 + k] = __float2bfloat16(w - __bfloat162float(h));
    }
}

// ---------------- K1: big GEMM ops @ [W3a'|W3b'|W3c'|Wv] + begin/end side blocks ----------------
// grid 1024+16, block 256, dyn smem 48KB, occ 2
__global__ void __launch_bounds__(256, 2) k_gemm(
    const float* __restrict__ ops, const float* __restrict__ b_qkv,
    const int* __restrict__ bidx, const int* __restrict__ eidx,
    const float* __restrict__ W_begin, const float* __restrict__ b_begin,
    const float* __restrict__ W_end, const float* __restrict__ b_end,
    const float* __restrict__ W_mix2) {
    __shared__ float sbv[128];
    __shared__ float suq[128], suk[128];
    extern __shared__ __align__(16) char dsm[];
    char* smb = (char*)((((uintptr_t)dsm) + 1023) & ~(uintptr_t)1023);
    char* smAh = smb;
    char* smAl = smb + 8192;
    char* smBh = smb + 16384;
    char* smBl = smb + 32768;
    uint32_t suAh = smem_u32(smAh), suAl = smem_u32(smAl);
    uint32_t suBh = smem_u32(smBh), suBl = smem_u32(smBl);

    int blk = blockIdx.x;
    int t = threadIdx.x;

    if (blk >= 1024) {
        // ---- begin/end: be = mean@W + b; beW = be@W_mix2[:D] + bc0 ----
        int e = blk - 1024;
        int b = e >> 1, which = e & 1;
        const int* idx = which ? eidx : bidx;
        if (t < 128) {
            float s = 0.f;
            for (int j = 0; j < J; j++)
                s += ops[((size_t)b * C + idx[b * J + j]) * D + t];
            suq[t] = s * (1.0f / (float)J);
        }
        __syncthreads();
        if (t < 128) {
            const float* W = which ? W_end : W_begin;
            const float* bbp = which ? b_end : b_begin;
            float acc = bbp[t];
            #pragma unroll 8
            for (int k = 0; k < D; k++) acc += suq[k] * W[k * D + t];
            suk[t] = acc;
        }
        __syncthreads();
        if (t < 128) {
            float acc2 = g_bc0[t];
            #pragma unroll 8
            for (int k = 0; k < D; k++) acc2 += suk[k] * W_mix2[k * D + t];
            g_beW[((size_t)b * 2 + which) * D + t] = acc2;
        }
        return;
    }

    int mt = blk >> 2, ng = blk & 3;
    int b = mt >> 5;
    int i0 = (mt & 31) * 64;
    int w = t >> 5, lane = t & 31;

    if (ng == 3 && t < 128) sbv[t] = b_qkv[2 * D + t];
    if (ng == 0 && t < 128) { suq[t] = g_uq[t]; suk[t] = g_uk[t]; }
    __syncthreads();

    float cc[8][4];
    #pragma unroll
    for (int nt = 0; nt < 8; nt++)
        #pragma unroll
        for (int r = 0; r < 4; r++) cc[nt][r] = 0.f;

    int l8 = lane & 7, grp = lane >> 3;
    int mg = w >> 1, nh = w & 1;
    int rowA = (mg << 4) + l8 + ((grp & 1) << 3);
    int colAg = (grp >> 1) << 4;
    int rowBoff = l8 + ((grp >> 1) << 3);
    int colBg = (grp & 1) << 4;

    int r = t >> 2, h = t & 3;   // 4 threads per A row
    int rowoff = r * 128 + h * 32;
    float dq = 0.f, dk = 0.f;

    #pragma unroll 1
    for (int c = 0; c < 2; c++) {
        if (c) __syncthreads();
        const float4* src = (const float4*)
            (ops + ((size_t)b * C + i0 + r) * D + c * 64 + h * 16);
        #pragma unroll
        for (int q = 0; q < 4; q++) {
            float4 v = src[q];
            if (ng == 0) {
                float4 u4 = *(const float4*)&suq[c * 64 + h * 16 + q * 4];
                float4 k4 = *(const float4*)&suk[c * 64 + h * 16 + q * 4];
                dq += v.x * u4.x + v.y * u4.y + v.z * u4.z + v.w * u4.w;
                dk += v.x * k4.x + v.y * k4.y + v.z * k4.z + v.w * k4.w;
            }
            uint32_t h0, h1, l0, l1;
            split2(v.x, v.y, h0, l0);
            split2(v.z, v.w, h1, l1);
            uint32_t off = rowoff + q * 8;
            *(uint2*)(smAh + SWZ(off)) = make_uint2(h0, h1);
            *(uint2*)(smAl + SWZ(off)) = make_uint2(l0, l1);
        }
        #pragma unroll
        for (int c2 = 0; c2 < 4; c2++) {
            int idx = t + c2 * 256;
            int dd = idx >> 3, ccx = idx & 7;
            uint32_t off = dd * 128 + ccx * 16;
            int gsrc = (ng * 128 + dd) * 128 + c * 64 + ccx * 8;
            *(uint4*)(smBh + SWZ(off)) = *(const uint4*)&g_Wbh[gsrc];
            *(uint4*)(smBl + SWZ(off)) = *(const uint4*)&g_Wbl[gsrc];
        }
        __syncthreads();
        mma_pass64(suAh, suBh, cc, rowA, colAg, nh, rowBoff, colBg);
        mma_pass64(suAh, suBl, cc, rowA, colAg, nh, rowBoff, colBg);
        mma_pass64(suAl, suBh, cc, rowA, colAg, nh, rowBoff, colBg);
    }

    if (ng == 0) {
        dq += __shfl_xor_sync(0xffffffffu, dq, 1);
        dk += __shfl_xor_sync(0xffffffffu, dk, 1);
        dq += __shfl_xor_sync(0xffffffffu, dq, 2);
        dk += __shfl_xor_sync(0xffffffffu, dk, 2);
        if (h == 0) {
            int row = b * C + i0 + r;
            g_sq[row] = dq + g_c[0];
            g_sk[row] = dk + g_c[1];
        }
    }

    int quad = lane >> 2, qt = lane & 3;
    if (ng < 3) {
        float* ob = g_mx + (size_t)ng * BCD + (size_t)b * C * D;
        int r0g = i0 + (mg << 4) + quad;
        #pragma unroll
        for (int nt = 0; nt < 8; nt++) {
            int n0 = (nh << 6) + nt * 8 + 2 * qt;
            *(float2*)&ob[(size_t)r0g * D + n0] = make_float2(cc[nt][0], cc[nt][1]);
            *(float2*)&ob[(size_t)(r0g + 8) * D + n0] = make_float2(cc[nt][2], cc[nt][3]);
        }
    } else {
        // v group: bias, bf16, transpose-stage in smem -> g_vT + colsum
        __syncthreads();
        __nv_bfloat16* vst = (__nv_bfloat16*)smb;   // [128 n][64 m] = 16KB
        int m0 = (mg << 4) + quad, m8 = m0 + 8;
        #pragma unroll
        for (int nt = 0; nt < 8; nt++) {
            int n0 = (nh << 6) + nt * 8 + 2 * qt;
            float vb0 = sbv[n0], vb1 = sbv[n0 + 1];
            vst[n0 * 64 + m0]       = __float2bfloat16(cc[nt][0] + vb0);
            vst[(n0 + 1) * 64 + m0] = __float2bfloat16(cc[nt][1] + vb1);
            vst[n0 * 64 + m8]       = __float2bfloat16(cc[nt][2] + vb0);
            vst[(n0 + 1) * 64 + m8] = __float2bfloat16(cc[nt][3] + vb1);
        }
        __syncthreads();
        int n = t >> 1, hh = t & 1;
        const uint4* srcv = (const uint4*)(vst + n * 64 + hh * 32);
        uint4* dstv = (uint4*)(g_vT + ((size_t)b * D + n) * C + i0 + hh * 32);
        #pragma unroll
        for (int q = 0; q < 4; q++) dstv[q] = srcv[q];
        if (t < 128) {
            float s = 0.f;
            #pragma unroll 16
            for (int m = 0; m < 64; m++) s += __bfloat162float(vst[t * 64 + m]);
            atomicAdd(&g_colsum[b * D + t], s);
        }
    }
}

// ---------------- K2: attention HMMA + fused weighted@Wc + gather-add epilogue ----------------
// grid 256, block 256, occ 2
__global__ void __launch_bounds__(256, 2) k_attn(const float* __restrict__ mask,
                                                 const int* __restrict__ rel,
                                                 float* __restrict__ out) {
    __shared__ __align__(128) char smA[64 * 128];     // probs / weighted chunk 0
    __shared__ __align__(128) char smA2[64 * 128];    // weighted chunk 1
    __shared__ __align__(128) char smB[128 * 128];
    __shared__ float ssq[64];
    __shared__ float srow[64];
    __shared__ float scol[128];
    __shared__ float sb3[128];
    __shared__ int2 srel[64];

    int t = threadIdx.x;
    int blk = blockIdx.x;
    int w = t >> 5, lane = t & 31;
    int b = blk >> 5;
    int i0 = (blk & 31) * 64;
    int base = b * C;

    uint32_t suA = smem_u32(smA);
    uint32_t suA2 = smem_u32(smA2);
    uint32_t suB = smem_u32(smB);

    if (t < 64) {
        ssq[t] = g_sq[base + i0 + t];
        int ig = i0 + t;
        srel[t] = (ig < CM2) ? *(const int2*)&rel[((size_t)b * CM2 + ig) * 2]
                             : make_int2(0, 0);
    }
    if (t < 128) { scol[t] = g_colsum[b * D + t]; sb3[t] = g_bc3[t]; }

    float rowsum[8];
    #pragma unroll
    for (int s = 0; s < 8; s++) rowsum[s] = 0.f;

    float cc[8][4];
    #pragma unroll
    for (int nt = 0; nt < 8; nt++)
        #pragma unroll
        for (int r = 0; r < 4; r++) cc[nt][r] = 0.f;

    const __nv_bfloat16* vTb = g_vT + (size_t)b * D * C;

    int l8 = lane & 7, grp = lane >> 3;
    int mg = w >> 1, nh = w & 1;
    int rowA = (mg << 4) + l8 + ((grp & 1) << 3);
    int colAg = (grp >> 1) << 4;
    int rowBoff = l8 + ((grp >> 1) << 3);
    int colBg = (grp & 1) << 4;

    // ---- attention mainloop ----
    for (int i = 0; i < C / 64; i++) {
        int jb = i * 64;
        __syncthreads();
        {
            float2 sk2 = *(const float2*)&g_sk[base + jb + 2 * lane];
            const float* mrow0 = mask + (size_t)(base + i0 + w) * C + jb + 2 * lane;
            #pragma unroll
            for (int s = 0; s < 8; s++) {
                int row = w + 8 * s;
                float2 mk = *(const float2*)(mrow0 + (size_t)(8 * s) * C);
                float q = ssq[row];
                float x0 = q + sk2.x; x0 = (x0 >= 0.f) ? x0 : 0.01f * x0; x0 *= mk.x;
                float x1 = q + sk2.y; x1 = (x1 >= 0.f) ? x1 : 0.01f * x1; x1 *= mk.y;
                float p0 = __expf(x0), p1 = __expf(x1);
                rowsum[s] += p0 + p1;
                uint32_t pr; CVT_BF16X2(pr, p0 - 1.f, p1 - 1.f);
                uint32_t off = row * 128 + lane * 4;
                *(uint32_t*)(smA + SWZ(off)) = pr;
            }
        }
        #pragma unroll
        for (int c = 0; c < 4; c++) {
            int idx = t + c * 256;
            int dd = idx >> 3, ccx = idx & 7;
            uint4 val = *(const uint4*)(vTb + (size_t)dd * C + jb + ccx * 8);
            uint32_t off = dd * 128 + ccx * 16;
            *(uint4*)(smB + SWZ(off)) = val;
        }
        __syncthreads();
        mma_pass64(suA, suB, cc, rowA, colAg, nh, rowBoff, colBg);
    }

    // ---- rowsum reduce ----
    #pragma unroll
    for (int s = 0; s < 8; s++) {
        float r = rowsum[s];
        #pragma unroll
        for (int off = 16; off; off >>= 1) r += __shfl_down_sync(0xffffffffu, r, off);
        if (lane == 0) srow[w + 8 * s] = r;
    }
    __syncthreads();

    // ---- normalize weighted + stage bf16 into smA (n<64) / smA2 (n>=64) ----
    int quad = lane >> 2, qt = lane & 3;
    int m0 = (mg << 4) + quad;
    float inv0 = 1.0f / srow[m0];
    float inv8 = 1.0f / srow[m0 + 8];
    char* stg = nh ? smA2 : smA;
    #pragma unroll
    for (int nt = 0; nt < 8; nt++) {
        int n0 = (nh << 6) + nt * 8 + 2 * qt;
        float cs0 = scol[n0], cs1 = scol[n0 + 1];
        float w00 = (cs0 + cc[nt][0]) * inv0;
        float w01 = (cs1 + cc[nt][1]) * inv0;
        float w80 = (cs0 + cc[nt][2]) * inv8;
        float w81 = (cs1 + cc[nt][3]) * inv8;
        uint32_t pr0, pr8;
        CVT_BF16X2(pr0, w00, w01);
        CVT_BF16X2(pr8, w80, w81);
        uint32_t col = (nt * 8 + 2 * qt) * 2;   // byte offset within 128B row
        *(uint32_t*)(stg + SWZ(m0 * 128 + col)) = pr0;
        *(uint32_t*)(stg + SWZ((m0 + 8) * 128 + col)) = pr8;
    }

    // ---- weighted @ Wc (hi-only), 2 K-chunks ----
    #pragma unroll
    for (int nt = 0; nt < 8; nt++)
        #pragma unroll
        for (int r = 0; r < 4; r++) cc[nt][r] = 0.f;

    #pragma unroll 1
    for (int c = 0; c < 2; c++) {
        __syncthreads();
        #pragma unroll
        for (int c2 = 0; c2 < 4; c2++) {
            int idx = t + c2 * 256;
            int dd = idx >> 3, ccx = idx & 7;
            *(uint4*)(smB + SWZ(dd * 128 + ccx * 16)) =
                *(const uint4*)&g_Wch[dd * 128 + c * 64 + ccx * 8];
        }
        __syncthreads();
        mma_pass64(c ? suA2 : suA, suB, cc, rowA, colAg, nh, rowBoff, colBg);
    }

    // ---- epilogue: out = Pa[i] + Pb[r0] + Pc[r1] + bc3 + cc  (or g_beW + cc) ----
    int r0g = i0 + m0;
    size_t bb = (size_t)b * C * D;
    const float* m1 = g_mx + bb;
    const float* m2 = g_mx + BCD + bb;
    const float* m3 = g_mx + 2 * BCD + bb;
    float* ob = out + bb;

    #pragma unroll
    for (int half = 0; half < 2; half++) {
        int rg = r0g + half * 8;
        int loc = rg - i0;
        if (rg < CM2) {
            int2 rr = srel[loc];
            const float* pa = m1 + (size_t)rg * D;
            const float* pb = m2 + (size_t)rr.x * D;
            const float* pc = m3 + (size_t)rr.y * D;
            #pragma unroll
            for (int nt = 0; nt < 8; nt++) {
                int n0 = (nh << 6) + nt * 8 + 2 * qt;
                float2 a2 = *(const float2*)(pa + n0);
                float2 b2 = *(const float2*)(pb + n0);
                float2 c2v = *(const float2*)(pc + n0);
                float vx = a2.x + b2.x + c2v.x + sb3[n0] + cc[nt][2 * half];
                float vy = a2.y + b2.y + c2v.y + sb3[n0 + 1] + cc[nt][2 * half + 1];
                *(float2*)&ob[(size_t)rg * D + n0] = make_float2(vx, vy);
            }
        } else {
            const float* pe = g_beW + ((size_t)b * 2 + (rg - CM2)) * D;
            #pragma unroll
            for (int nt = 0; nt < 8; nt++) {
                int n0 = (nh << 6) + nt * 8 + 2 * qt;
                float2 ev = *(const float2*)(pe + n0);
                *(float2*)&ob[(size_t)rg * D + n0] =
                    make_float2(ev.x + cc[nt][2 * half],
                                ev.y + cc[nt][2 * half + 1]);
            }
        }
    }
}

// ---------------- launch ----------------
extern "C" void kernel_launch(void* const* d_in, const int* in_sizes, int n_in,
                              void* d_out, int out_size) {
    const float* ops      = (const float*)d_in[0];
    const int*   rel      = (const int*)d_in[1];
    const int*   bidx     = (const int*)d_in[2];
    const int*   eidx     = (const int*)d_in[3];
    const float* mask     = (const float*)d_in[4];
    const float* W_begin  = (const float*)d_in[5];
    const float* b_begin  = (const float*)d_in[6];
    const float* W_end    = (const float*)d_in[7];
    const float* b_end    = (const float*)d_in[8];
    const float* W_mix3   = (const float*)d_in[9];
    const float* b_mix3   = (const float*)d_in[10];
    const float* W_qkv    = (const float*)d_in[11];
    const float* b_qkv    = (const float*)d_in[12];
    const float* w_score  = (const float*)d_in[13];
    const float* b_score  = (const float*)d_in[14];
    const float* W_out    = (const float*)d_in[15];
    const float* b_out    = (const float*)d_in[16];
    const float* W_mix2   = (const float*)d_in[17];
    const float* b_mix2   = (const float*)d_in[18];
    float* out = (float*)d_out;

    static bool attr_set = false;
    if (!attr_set) {
        cudaFuncSetAttribute(k_gemm, cudaFuncAttributeMaxDynamicSharedMemorySize, SMEM_MMA2);
        attr_set = true;
    }

    k_pre<<<641, 128>>>(W_qkv, b_qkv, w_score, b_score, W_out, b_out,
                        W_mix2, b_mix2, W_mix3, b_mix3);
    k_gemm<<<1024 + 2 * B, 256, SMEM_MMA2>>>(ops, b_qkv, bidx, eidx,
                                             W_begin, b_begin, W_end, b_end, W_mix2);
    k_attn<<<256, 256>>>(mask, rel, out);
}

// round 13
// speedup vs baseline: 4.7307x; 1.0132x over previous
#include <cuda_runtime.h>
#include <cuda_bf16.h>
#include <cstdint>

#define B 8
#define C 2048
#define D 128
#define J 128
#define CM2 (C - 2)   // 2046
#define BCD (B * C * D)

// ---------------- scratch (device globals) ----------------
__device__ __align__(16) __nv_bfloat16 g_vT[B * D * C];   // v bf16 transposed [b][d][j]
__device__ __align__(16) float g_mx[3 * BCD];             // Pa / Pb / Pc = ops@(W3x@W2a)
__device__ __align__(16) float g_beW[B * 2 * D];          // (begin/end)@W_mix2[:D] + bc0
__device__ float g_colsum[B * D];
__device__ float g_sq[B * C];
__device__ float g_sk[B * C];
__device__ float g_uq[D];
__device__ float g_uk[D];
__device__ float g_c[2];
__device__ float g_bc0[D];                                // b_out@W2b + b_mix2
__device__ float g_bc3[D];                                // bc0 + b_mix3@W2a
// split-bf16 transposed weights
__device__ __align__(16) __nv_bfloat16 g_Wbh[512 * D];    // [W3a'|W3b'|W3c'|Wv] as [n][k]
__device__ __align__(16) __nv_bfloat16 g_Wbl[512 * D];
__device__ __align__(16) __nv_bfloat16 g_Wch[D * D];      // Wc = W_out@W2b as [n][k], hi only

// ---------------- helpers ----------------
__device__ __forceinline__ uint32_t smem_u32(const void* p) {
    uint32_t a;
    asm("{ .reg .u64 tmp; cvta.to.shared.u64 tmp, %1; cvt.u32.u64 %0, tmp; }"
        : "=r"(a) : "l"(p));
    return a;
}
#define CVT_BF16X2(res, a, b) \
    asm("cvt.rn.satfinite.bf16x2.f32 %0, %1, %2;" : "=r"(res) : "f"(b), "f"(a))
#define SWZ(x) ((x) ^ (((x) >> 3) & 0x70))

__device__ __forceinline__ void ldm_x4(uint32_t& r0, uint32_t& r1, uint32_t& r2,
                                       uint32_t& r3, uint32_t addr) {
    asm volatile("ldmatrix.sync.aligned.m8n8.x4.shared.b16 {%0,%1,%2,%3}, [%4];"
                 : "=r"(r0), "=r"(r1), "=r"(r2), "=r"(r3) : "r"(addr));
}
__device__ __forceinline__ void mma16816(float* c, uint32_t a0, uint32_t a1,
                                         uint32_t a2, uint32_t a3,
                                         uint32_t b0, uint32_t b1) {
    asm volatile(
        "mma.sync.aligned.m16n8k16.row.col.f32.bf16.bf16.f32 "
        "{%0,%1,%2,%3}, {%4,%5,%6,%7}, {%8,%9}, {%0,%1,%2,%3};"
        : "+f"(c[0]), "+f"(c[1]), "+f"(c[2]), "+f"(c[3])
        : "r"(a0), "r"(a1), "r"(a2), "r"(a3), "r"(b0), "r"(b1));
}
__device__ __forceinline__ void split2(float x0, float x1, uint32_t& hp, uint32_t& lp) {
    CVT_BF16X2(hp, x0, x1);
    __nv_bfloat162 hv = *reinterpret_cast<__nv_bfloat162*>(&hp);
    float f0 = __bfloat162float(hv.x), f1 = __bfloat162float(hv.y);
    CVT_BF16X2(lp, x0 - f0, x1 - f1);
}
// one K=64 pass: warp (mg, nh) computes 16m x 64n, A tile 64 rows
__device__ __forceinline__ void mma_pass64(uint32_t suA, uint32_t suB, float cc[8][4],
                                           int rowA, int colAg, int nh,
                                           int rowBoff, int colBg) {
    #pragma unroll
    for (int ks = 0; ks < 4; ks++) {
        uint32_t a0, a1, a2, a3;
        ldm_x4(a0, a1, a2, a3, suA + SWZ(rowA * 128 + ks * 32 + colAg));
        #pragma unroll
        for (int nt = 0; nt < 8; nt += 2) {
            uint32_t b0, b1, b2, b3;
            int rowB = (nh << 6) + nt * 8 + rowBoff;
            ldm_x4(b0, b1, b2, b3, suB + SWZ(rowB * 128 + ks * 32 + colBg));
            mma16816(cc[nt],     a0, a1, a2, a3, b0, b1);
            mma16816(cc[nt + 1], a0, a1, a2, a3, b2, b3);
        }
    }
}

#define SMEM_MMA2 (49152 + 1024)

// ---------------- K0: folded + split/transposed weights (ILP-restructured) ----------------
// grid 145, block 128
//   blk 0..31   : Wc fold, 4 k-rows/block
//   blk 32      : misc (uq/uk/bc0/bc3/colsum/c)
//   blk 33..128 : W3' fold, 4 k-rows/block (96 blocks x 4 = 384)
//   blk 129..144: v-weight transpose copy, 8 k/block
__global__ void k_pre(const float* __restrict__ W_qkv, const float* __restrict__ b_qkv,
                      const float* __restrict__ w_score, const float* __restrict__ b_score,
                      const float* __restrict__ W_out, const float* __restrict__ b_out,
                      const float* __restrict__ W_mix2, const float* __restrict__ b_mix2,
                      const float* __restrict__ W_mix3, const float* __restrict__ b_mix3) {
    int t = threadIdx.x;
    int blk = blockIdx.x;
    __shared__ __align__(16) float srow[4][D];

    if (blk < 32) {
        // ---- Wc fold: k = blk*4 + j ----
        #pragma unroll
        for (int j = 0; j < 4; j++)
            srow[j][t] = W_out[(size_t)(blk * 4 + j) * D + t];
        __syncthreads();
        float acc0 = 0.f, acc1 = 0.f, acc2 = 0.f, acc3 = 0.f;
        #pragma unroll 8
        for (int m = 0; m < D; m++) {
            float w2 = W_mix2[(D + m) * D + t];
            acc0 += srow[0][m] * w2;
            acc1 += srow[1][m] * w2;
            acc2 += srow[2][m] * w2;
            acc3 += srow[3][m] * w2;
        }
        g_Wch[t * 128 + blk * 4 + 0] = __float2bfloat16(acc0);
        g_Wch[t * 128 + blk * 4 + 1] = __float2bfloat16(acc1);
        g_Wch[t * 128 + blk * 4 + 2] = __float2bfloat16(acc2);
        g_Wch[t * 128 + blk * 4 + 3] = __float2bfloat16(acc3);
    } else if (blk == 32) {
        // ---- misc ----
        float uq = 0.f, uk = 0.f;
        #pragma unroll 8
        for (int c = 0; c < D; c++) {
            uq += W_qkv[t * 3 * D + c] * w_score[c];
            uk += W_qkv[t * 3 * D + D + c] * w_score[D + c];
        }
        g_uq[t] = uq;
        g_uk[t] = uk;
        float bc0 = b_mix2[t];
        float bc3 = 0.f;
        #pragma unroll 8
        for (int m = 0; m < D; m++) {
            bc0 += b_out[m] * W_mix2[(D + m) * D + t];
            bc3 += b_mix3[m] * W_mix2[m * D + t];
        }
        g_bc0[t] = bc0;
        g_bc3[t] = bc3 + bc0;
        #pragma unroll
        for (int i = t; i < B * D; i += 128) g_colsum[i] = 0.f;
        __shared__ float s1[D], s2[D];
        s1[t] = b_qkv[t] * w_score[t];
        s2[t] = b_qkv[D + t] * w_score[D + t];
        __syncthreads();
        for (int off = 64; off; off >>= 1) {
            if (t < off) { s1[t] += s1[t + off]; s2[t] += s2[t + off]; }
            __syncthreads();
        }
        if (t == 0) { g_c[0] = s1[0]; g_c[1] = s2[0] + b_score[0]; }
    } else if (blk < 129) {
        // ---- W3' fold: global rows kr = (blk-33)*4 + j, kr in 0..383 ----
        int kr0 = (blk - 33) * 4;
        #pragma unroll
        for (int j = 0; j < 4; j++)
            srow[j][t] = W_mix3[(size_t)(kr0 + j) * D + t];
        __syncthreads();
        float acc0 = 0.f, acc1 = 0.f, acc2 = 0.f, acc3 = 0.f;
        #pragma unroll 8
        for (int m = 0; m < D; m++) {
            float w2 = W_mix2[m * D + t];
            acc0 += srow[0][m] * w2;
            acc1 += srow[1][m] * w2;
            acc2 += srow[2][m] * w2;
            acc3 += srow[3][m] * w2;
        }
        float accs[4] = {acc0, acc1, acc2, acc3};
        #pragma unroll
        for (int j = 0; j < 4; j++) {
            int kr = kr0 + j;
            int x = kr >> 7, k = kr & 127;
            __nv_bfloat16 h = __float2bfloat16(accs[j]);
            g_Wbh[(x * 128 + t) * 128 + k] = h;
            g_Wbl[(x * 128 + t) * 128 + k] =
                __float2bfloat16(accs[j] - __bfloat162float(h));
        }
    } else {
        // ---- v weights: k = (blk-129)*8 + j ----
        int k0 = (blk - 129) * 8;
        #pragma unroll
        for (int j = 0; j < 8; j++) {
            int k = k0 + j;
            float w = W_qkv[k * 3 * D + 2 * D + t];
            __nv_bfloat16 h = __float2bfloat16(w);
            g_Wbh[(384 + t) * 128 + k] = h;
            g_Wbl[(384 + t) * 128 + k] = __float2bfloat16(w - __bfloat162float(h));
        }
    }
}

// ---------------- K1: big GEMM ops @ [W3a'|W3b'|W3c'|Wv] + begin/end side blocks ----------------
// grid 1024+16, block 256, dyn smem 48KB, occ 2
__global__ void __launch_bounds__(256, 2) k_gemm(
    const float* __restrict__ ops, const float* __restrict__ b_qkv,
    const int* __restrict__ bidx, const int* __restrict__ eidx,
    const float* __restrict__ W_begin, const float* __restrict__ b_begin,
    const float* __restrict__ W_end, const float* __restrict__ b_end,
    const float* __restrict__ W_mix2) {
    __shared__ float sbv[128];
    __shared__ float suq[128], suk[128];
    extern __shared__ __align__(16) char dsm[];
    char* smb = (char*)((((uintptr_t)dsm) + 1023) & ~(uintptr_t)1023);
    char* smAh = smb;
    char* smAl = smb + 8192;
    char* smBh = smb + 16384;
    char* smBl = smb + 32768;
    uint32_t suAh = smem_u32(smAh), suAl = smem_u32(smAl);
    uint32_t suBh = smem_u32(smBh), suBl = smem_u32(smBl);

    int blk = blockIdx.x;
    int t = threadIdx.x;

    if (blk >= 1024) {
        // ---- begin/end: be = mean@W + b; beW = be@W_mix2[:D] + bc0 ----
        int e = blk - 1024;
        int b = e >> 1, which = e & 1;
        const int* idx = which ? eidx : bidx;
        if (t < 128) {
            float s = 0.f;
            for (int j = 0; j < J; j++)
                s += ops[((size_t)b * C + idx[b * J + j]) * D + t];
            suq[t] = s * (1.0f / (float)J);
        }
        __syncthreads();
        if (t < 128) {
            const float* W = which ? W_end : W_begin;
            const float* bbp = which ? b_end : b_begin;
            float acc = bbp[t];
            #pragma unroll 8
            for (int k = 0; k < D; k++) acc += suq[k] * W[k * D + t];
            suk[t] = acc;
        }
        __syncthreads();
        if (t < 128) {
            float acc2 = g_bc0[t];
            #pragma unroll 8
            for (int k = 0; k < D; k++) acc2 += suk[k] * W_mix2[k * D + t];
            g_beW[((size_t)b * 2 + which) * D + t] = acc2;
        }
        return;
    }

    int mt = blk >> 2, ng = blk & 3;
    int b = mt >> 5;
    int i0 = (mt & 31) * 64;
    int w = t >> 5, lane = t & 31;

    if (ng == 3 && t < 128) sbv[t] = b_qkv[2 * D + t];
    if (ng == 0 && t < 128) { suq[t] = g_uq[t]; suk[t] = g_uk[t]; }
    __syncthreads();

    float cc[8][4];
    #pragma unroll
    for (int nt = 0; nt < 8; nt++)
        #pragma unroll
        for (int r = 0; r < 4; r++) cc[nt][r] = 0.f;

    int l8 = lane & 7, grp = lane >> 3;
    int mg = w >> 1, nh = w & 1;
    int rowA = (mg << 4) + l8 + ((grp & 1) << 3);
    int colAg = (grp >> 1) << 4;
    int rowBoff = l8 + ((grp >> 1) << 3);
    int colBg = (grp & 1) << 4;

    int r = t >> 2, h = t & 3;   // 4 threads per A row
    int rowoff = r * 128 + h * 32;
    float dq = 0.f, dk = 0.f;

    #pragma unroll 1
    for (int c = 0; c < 2; c++) {
        if (c) __syncthreads();
        const float4* src = (const float4*)
            (ops + ((size_t)b * C + i0 + r) * D + c * 64 + h * 16);
        #pragma unroll
        for (int q = 0; q < 4; q++) {
            float4 v = src[q];
            if (ng == 0) {
                float4 u4 = *(const float4*)&suq[c * 64 + h * 16 + q * 4];
                float4 k4 = *(const float4*)&suk[c * 64 + h * 16 + q * 4];
                dq += v.x * u4.x + v.y * u4.y + v.z * u4.z + v.w * u4.w;
                dk += v.x * k4.x + v.y * k4.y + v.z * k4.z + v.w * k4.w;
            }
            uint32_t h0, h1, l0, l1;
            split2(v.x, v.y, h0, l0);
            split2(v.z, v.w, h1, l1);
            uint32_t off = rowoff + q * 8;
            *(uint2*)(smAh + SWZ(off)) = make_uint2(h0, h1);
            *(uint2*)(smAl + SWZ(off)) = make_uint2(l0, l1);
        }
        #pragma unroll
        for (int c2 = 0; c2 < 4; c2++) {
            int idx = t + c2 * 256;
            int dd = idx >> 3, ccx = idx & 7;
            uint32_t off = dd * 128 + ccx * 16;
            int gsrc = (ng * 128 + dd) * 128 + c * 64 + ccx * 8;
            *(uint4*)(smBh + SWZ(off)) = *(const uint4*)&g_Wbh[gsrc];
            *(uint4*)(smBl + SWZ(off)) = *(const uint4*)&g_Wbl[gsrc];
        }
        __syncthreads();
        mma_pass64(suAh, suBh, cc, rowA, colAg, nh, rowBoff, colBg);
        mma_pass64(suAh, suBl, cc, rowA, colAg, nh, rowBoff, colBg);
        mma_pass64(suAl, suBh, cc, rowA, colAg, nh, rowBoff, colBg);
    }

    if (ng == 0) {
        dq += __shfl_xor_sync(0xffffffffu, dq, 1);
        dk += __shfl_xor_sync(0xffffffffu, dk, 1);
        dq += __shfl_xor_sync(0xffffffffu, dq, 2);
        dk += __shfl_xor_sync(0xffffffffu, dk, 2);
        if (h == 0) {
            int row = b * C + i0 + r;
            g_sq[row] = dq + g_c[0];
            g_sk[row] = dk + g_c[1];
        }
    }

    int quad = lane >> 2, qt = lane & 3;
    if (ng < 3) {
        float* ob = g_mx + (size_t)ng * BCD + (size_t)b * C * D;
        int r0g = i0 + (mg << 4) + quad;
        #pragma unroll
        for (int nt = 0; nt < 8; nt++) {
            int n0 = (nh << 6) + nt * 8 + 2 * qt;
            *(float2*)&ob[(size_t)r0g * D + n0] = make_float2(cc[nt][0], cc[nt][1]);
            *(float2*)&ob[(size_t)(r0g + 8) * D + n0] = make_float2(cc[nt][2], cc[nt][3]);
        }
    } else {
        // v group: bias, bf16, transpose-stage in smem -> g_vT + colsum
        __syncthreads();
        __nv_bfloat16* vst = (__nv_bfloat16*)smb;   // [128 n][64 m] = 16KB
        int m0 = (mg << 4) + quad, m8 = m0 + 8;
        #pragma unroll
        for (int nt = 0; nt < 8; nt++) {
            int n0 = (nh << 6) + nt * 8 + 2 * qt;
            float vb0 = sbv[n0], vb1 = sbv[n0 + 1];
            vst[n0 * 64 + m0]       = __float2bfloat16(cc[nt][0] + vb0);
            vst[(n0 + 1) * 64 + m0] = __float2bfloat16(cc[nt][1] + vb1);
            vst[n0 * 64 + m8]       = __float2bfloat16(cc[nt][2] + vb0);
            vst[(n0 + 1) * 64 + m8] = __float2bfloat16(cc[nt][3] + vb1);
        }
        __syncthreads();
        int n = t >> 1, hh = t & 1;
        const uint4* srcv = (const uint4*)(vst + n * 64 + hh * 32);
        uint4* dstv = (uint4*)(g_vT + ((size_t)b * D + n) * C + i0 + hh * 32);
        #pragma unroll
        for (int q = 0; q < 4; q++) dstv[q] = srcv[q];
        if (t < 128) {
            float s = 0.f;
            #pragma unroll 16
            for (int m = 0; m < 64; m++) s += __bfloat162float(vst[t * 64 + m]);
            atomicAdd(&g_colsum[b * D + t], s);
        }
    }
}

// ---------------- K2: attention HMMA + fused weighted@Wc + gather-add epilogue ----------------
// grid 256, block 256, occ 2
__global__ void __launch_bounds__(256, 2) k_attn(const float* __restrict__ mask,
                                                 const int* __restrict__ rel,
                                                 float* __restrict__ out) {
    __shared__ __align__(128) char smA[64 * 128];     // probs / weighted chunk 0
    __shared__ __align__(128) char smA2[64 * 128];    // weighted chunk 1
    __shared__ __align__(128) char smB[128 * 128];
    __shared__ float ssq[64];
    __shared__ float srow[64];
    __shared__ float scol[128];
    __shared__ float sb3[128];
    __shared__ int2 srel[64];

    int t = threadIdx.x;
    int blk = blockIdx.x;
    int w = t >> 5, lane = t & 31;
    int b = blk >> 5;
    int i0 = (blk & 31) * 64;
    int base = b * C;

    uint32_t suA = smem_u32(smA);
    uint32_t suA2 = smem_u32(smA2);
    uint32_t suB = smem_u32(smB);

    if (t < 64) {
        ssq[t] = g_sq[base + i0 + t];
        int ig = i0 + t;
        srel[t] = (ig < CM2) ? *(const int2*)&rel[((size_t)b * CM2 + ig) * 2]
                             : make_int2(0, 0);
    }
    if (t < 128) { scol[t] = g_colsum[b * D + t]; sb3[t] = g_bc3[t]; }

    float rowsum[8];
    #pragma unroll
    for (int s = 0; s < 8; s++) rowsum[s] = 0.f;

    float cc[8][4];
    #pragma unroll
    for (int nt = 0; nt < 8; nt++)
        #pragma unroll
        for (int r = 0; r < 4; r++) cc[nt][r] = 0.f;

    const __nv_bfloat16* vTb = g_vT + (size_t)b * D * C;

    int l8 = lane & 7, grp = lane >> 3;
    int mg = w >> 1, nh = w & 1;
    int rowA = (mg << 4) + l8 + ((grp & 1) << 3);
    int colAg = (grp >> 1) << 4;
    int rowBoff = l8 + ((grp >> 1) << 3);
    int colBg = (grp & 1) << 4;

    // ---- attention mainloop ----
    for (int i = 0; i < C / 64; i++) {
        int jb = i * 64;
        __syncthreads();
        {
            float2 sk2 = *(const float2*)&g_sk[base + jb + 2 * lane];
            const float* mrow0 = mask + (size_t)(base + i0 + w) * C + jb + 2 * lane;
            #pragma unroll
            for (int s = 0; s < 8; s++) {
                int row = w + 8 * s;
                float2 mk = *(const float2*)(mrow0 + (size_t)(8 * s) * C);
                float q = ssq[row];
                float x0 = q + sk2.x; x0 = (x0 >= 0.f) ? x0 : 0.01f * x0; x0 *= mk.x;
                float x1 = q + sk2.y; x1 = (x1 >= 0.f) ? x1 : 0.01f * x1; x1 *= mk.y;
                float p0 = __expf(x0), p1 = __expf(x1);
                rowsum[s] += p0 + p1;
                uint32_t pr; CVT_BF16X2(pr, p0 - 1.f, p1 - 1.f);
                uint32_t off = row * 128 + lane * 4;
                *(uint32_t*)(smA + SWZ(off)) = pr;
            }
        }
        #pragma unroll
        for (int c = 0; c < 4; c++) {
            int idx = t + c * 256;
            int dd = idx >> 3, ccx = idx & 7;
            uint4 val = *(const uint4*)(vTb + (size_t)dd * C + jb + ccx * 8);
            uint32_t off = dd * 128 + ccx * 16;
            *(uint4*)(smB + SWZ(off)) = val;
        }
        __syncthreads();
        mma_pass64(suA, suB, cc, rowA, colAg, nh, rowBoff, colBg);
    }

    // ---- rowsum reduce ----
    #pragma unroll
    for (int s = 0; s < 8; s++) {
        float r = rowsum[s];
        #pragma unroll
        for (int off = 16; off; off >>= 1) r += __shfl_down_sync(0xffffffffu, r, off);
        if (lane == 0) srow[w + 8 * s] = r;
    }
    __syncthreads();

    // ---- normalize weighted + stage bf16 into smA (n<64) / smA2 (n>=64) ----
    int quad = lane >> 2, qt = lane & 3;
    int m0 = (mg << 4) + quad;
    float inv0 = 1.0f / srow[m0];
    float inv8 = 1.0f / srow[m0 + 8];
    char* stg = nh ? smA2 : smA;
    #pragma unroll
    for (int nt = 0; nt < 8; nt++) {
        int n0 = (nh << 6) + nt * 8 + 2 * qt;
        float cs0 = scol[n0], cs1 = scol[n0 + 1];
        float w00 = (cs0 + cc[nt][0]) * inv0;
        float w01 = (cs1 + cc[nt][1]) * inv0;
        float w80 = (cs0 + cc[nt][2]) * inv8;
        float w81 = (cs1 + cc[nt][3]) * inv8;
        uint32_t pr0, pr8;
        CVT_BF16X2(pr0, w00, w01);
        CVT_BF16X2(pr8, w80, w81);
        uint32_t col = (nt * 8 + 2 * qt) * 2;   // byte offset within 128B row
        *(uint32_t*)(stg + SWZ(m0 * 128 + col)) = pr0;
        *(uint32_t*)(stg + SWZ((m0 + 8) * 128 + col)) = pr8;
    }

    // ---- weighted @ Wc (hi-only), 2 K-chunks ----
    #pragma unroll
    for (int nt = 0; nt < 8; nt++)
        #pragma unroll
        for (int r = 0; r < 4; r++) cc[nt][r] = 0.f;

    #pragma unroll 1
    for (int c = 0; c < 2; c++) {
        __syncthreads();
        #pragma unroll
        for (int c2 = 0; c2 < 4; c2++) {
            int idx = t + c2 * 256;
            int dd = idx >> 3, ccx = idx & 7;
            *(uint4*)(smB + SWZ(dd * 128 + ccx * 16)) =
                *(const uint4*)&g_Wch[dd * 128 + c * 64 + ccx * 8];
        }
        __syncthreads();
        mma_pass64(c ? suA2 : suA, suB, cc, rowA, colAg, nh, rowBoff, colBg);
    }

    // ---- epilogue: out = Pa[i] + Pb[r0] + Pc[r1] + bc3 + cc  (or g_beW + cc) ----
    int r0g = i0 + m0;
    size_t bb = (size_t)b * C * D;
    const float* m1 = g_mx + bb;
    const float* m2 = g_mx + BCD + bb;
    const float* m3 = g_mx + 2 * BCD + bb;
    float* ob = out + bb;

    #pragma unroll
    for (int half = 0; half < 2; half++) {
        int rg = r0g + half * 8;
        int loc = rg - i0;
        if (rg < CM2) {
            int2 rr = srel[loc];
            const float* pa = m1 + (size_t)rg * D;
            const float* pb = m2 + (size_t)rr.x * D;
            const float* pc = m3 + (size_t)rr.y * D;
            #pragma unroll
            for (int nt = 0; nt < 8; nt++) {
                int n0 = (nh << 6) + nt * 8 + 2 * qt;
                float2 a2 = *(const float2*)(pa + n0);
                float2 b2 = *(const float2*)(pb + n0);
                float2 c2v = *(const float2*)(pc + n0);
                float vx = a2.x + b2.x + c2v.x + sb3[n0] + cc[nt][2 * half];
                float vy = a2.y + b2.y + c2v.y + sb3[n0 + 1] + cc[nt][2 * half + 1];
                *(float2*)&ob[(size_t)rg * D + n0] = make_float2(vx, vy);
            }
        } else {
            const float* pe = g_beW + ((size_t)b * 2 + (rg - CM2)) * D;
            #pragma unroll
            for (int nt = 0; nt < 8; nt++) {
                int n0 = (nh << 6) + nt * 8 + 2 * qt;
                float2 ev = *(const float2*)(pe + n0);
                *(float2*)&ob[(size_t)rg * D + n0] =
                    make_float2(ev.x + cc[nt][2 * half],
                                ev.y + cc[nt][2 * half + 1]);
            }
        }
    }
}

// ---------------- launch ----------------
extern "C" void kernel_launch(void* const* d_in, const int* in_sizes, int n_in,
                              void* d_out, int out_size) {
    const float* ops      = (const float*)d_in[0];
    const int*   rel      = (const int*)d_in[1];
    const int*   bidx     = (const int*)d_in[2];
    const int*   eidx     = (const int*)d_in[3];
    const float* mask     = (const float*)d_in[4];
    const float* W_begin  = (const float*)d_in[5];
    const float* b_begin  = (const float*)d_in[6];
    const float* W_end    = (const float*)d_in[7];
    const float* b_end    = (const float*)d_in[8];
    const float* W_mix3   = (const float*)d_in[9];
    const float* b_mix3   = (const float*)d_in[10];
    const float* W_qkv    = (const float*)d_in[11];
    const float* b_qkv    = (const float*)d_in[12];
    const float* w_score  = (const float*)d_in[13];
    const float* b_score  = (const float*)d_in[14];
    const float* W_out    = (const float*)d_in[15];
    const float* b_out    = (const float*)d_in[16];
    const float* W_mix2   = (const float*)d_in[17];
    const float* b_mix2   = (const float*)d_in[18];
    float* out = (float*)d_out;

    static bool attr_set = false;
    if (!attr_set) {
        cudaFuncSetAttribute(k_gemm, cudaFuncAttributeMaxDynamicSharedMemorySize, SMEM_MMA2);
        attr_set = true;
    }

    k_pre<<<145, 128>>>(W_qkv, b_qkv, w_score, b_score, W_out, b_out,
                        W_mix2, b_mix2, W_mix3, b_mix3);
    k_gemm<<<1024 + 2 * B, 256, SMEM_MMA2>>>(ops, b_qkv, bidx, eidx,
                                             W_begin, b_begin, W_end, b_end, W_mix2);
    k_attn<<<256, 256>>>(mask, rel, out);
}

// round 14
// speedup vs baseline: 4.8927x; 1.0342x over previous
#include <cuda_runtime.h>
#include <cuda_bf16.h>
#include <cstdint>

#define B 8
#define C 2048
#define D 128
#define J 128
#define CM2 (C - 2)   // 2046
#define BCD (B * C * D)

// ---------------- scratch (device globals) ----------------
__device__ __align__(16) __nv_bfloat16 g_vT[B * D * C];   // v bf16 transposed [b][d][j]
__device__ __align__(16) float g_mx[3 * BCD];             // Pa / Pb / Pc = ops@(W3x@W2a)
__device__ __align__(16) float g_beW[B * 2 * D];          // (begin/end)@W_mix2[:D] + bc0
__device__ float g_colsum[B * D];
__device__ float g_sq[B * C];
__device__ float g_sk[B * C];
__device__ float g_uq[D];
__device__ float g_uk[D];
__device__ float g_c[2];
__device__ float g_bc0[D];                                // b_out@W2b + b_mix2
__device__ float g_bc3[D];                                // bc0 + b_mix3@W2a
// split-bf16 transposed weights
__device__ __align__(16) __nv_bfloat16 g_Wbh[512 * D];    // [W3a'|W3b'|W3c'|Wv] as [n][k]
__device__ __align__(16) __nv_bfloat16 g_Wbl[512 * D];
__device__ __align__(16) __nv_bfloat16 g_Wch[D * D];      // Wc = W_out@W2b as [n][k], hi only

// ---------------- helpers ----------------
__device__ __forceinline__ uint32_t smem_u32(const void* p) {
    uint32_t a;
    asm("{ .reg .u64 tmp; cvta.to.shared.u64 tmp, %1; cvt.u32.u64 %0, tmp; }"
        : "=r"(a) : "l"(p));
    return a;
}
#define CVT_BF16X2(res, a, b) \
    asm("cvt.rn.satfinite.bf16x2.f32 %0, %1, %2;" : "=r"(res) : "f"(b), "f"(a))
#define SWZ(x) ((x) ^ (((x) >> 3) & 0x70))

__device__ __forceinline__ void ldm_x4(uint32_t& r0, uint32_t& r1, uint32_t& r2,
                                       uint32_t& r3, uint32_t addr) {
    asm volatile("ldmatrix.sync.aligned.m8n8.x4.shared.b16 {%0,%1,%2,%3}, [%4];"
                 : "=r"(r0), "=r"(r1), "=r"(r2), "=r"(r3) : "r"(addr));
}
__device__ __forceinline__ void mma16816(float* c, uint32_t a0, uint32_t a1,
                                         uint32_t a2, uint32_t a3,
                                         uint32_t b0, uint32_t b1) {
    asm volatile(
        "mma.sync.aligned.m16n8k16.row.col.f32.bf16.bf16.f32 "
        "{%0,%1,%2,%3}, {%4,%5,%6,%7}, {%8,%9}, {%0,%1,%2,%3};"
        : "+f"(c[0]), "+f"(c[1]), "+f"(c[2]), "+f"(c[3])
        : "r"(a0), "r"(a1), "r"(a2), "r"(a3), "r"(b0), "r"(b1));
}
__device__ __forceinline__ void split2(float x0, float x1, uint32_t& hp, uint32_t& lp) {
    CVT_BF16X2(hp, x0, x1);
    __nv_bfloat162 hv = *reinterpret_cast<__nv_bfloat162*>(&hp);
    float f0 = __bfloat162float(hv.x), f1 = __bfloat162float(hv.y);
    CVT_BF16X2(lp, x0 - f0, x1 - f1);
}
// one K=64 pass: warp (mg, nh) computes 16m x 64n, A tile 64 rows
__device__ __forceinline__ void mma_pass64(uint32_t suA, uint32_t suB, float cc[8][4],
                                           int rowA, int colAg, int nh,
                                           int rowBoff, int colBg) {
    #pragma unroll
    for (int ks = 0; ks < 4; ks++) {
        uint32_t a0, a1, a2, a3;
        ldm_x4(a0, a1, a2, a3, suA + SWZ(rowA * 128 + ks * 32 + colAg));
        #pragma unroll
        for (int nt = 0; nt < 8; nt += 2) {
            uint32_t b0, b1, b2, b3;
            int rowB = (nh << 6) + nt * 8 + rowBoff;
            ldm_x4(b0, b1, b2, b3, suB + SWZ(rowB * 128 + ks * 32 + colBg));
            mma16816(cc[nt],     a0, a1, a2, a3, b0, b1);
            mma16816(cc[nt + 1], a0, a1, a2, a3, b2, b3);
        }
    }
}

#define SMEM_MMA2 (49152 + 1024)

// ---------------- K0: folded + split/transposed weights (MLP-forced) ----------------
// grid 145, block 128
//   blk 0..31   : Wc fold, 4 k-rows/block
//   blk 32      : misc (uq/uk/bc0/bc3/colsum/c)
//   blk 33..128 : W3' fold, 4 k-rows/block (96 blocks x 4 = 384)
//   blk 129..144: v-weight transpose copy, 8 k/block
__global__ void k_pre(const float* __restrict__ W_qkv, const float* __restrict__ b_qkv,
                      const float* __restrict__ w_score, const float* __restrict__ b_score,
                      const float* __restrict__ W_out, const float* __restrict__ b_out,
                      const float* __restrict__ W_mix2, const float* __restrict__ b_mix2,
                      const float* __restrict__ W_mix3, const float* __restrict__ b_mix3) {
    int t = threadIdx.x;
    int blk = blockIdx.x;
    __shared__ __align__(16) float srow[4][D];

    if (blk < 32 || (blk >= 33 && blk < 129)) {
        // ---- unified fold: acc[j] = sum_m src[kr0+j][m] * W2base[m][t] ----
        bool isWc = (blk < 32);
        int kr0 = isWc ? blk * 4 : (blk - 33) * 4;
        const float* Wsrc = isWc ? W_out : W_mix3;
        const float* W2base = isWc ? (W_mix2 + (size_t)D * D) : W_mix2;
        #pragma unroll
        for (int j = 0; j < 4; j++)
            srow[j][t] = Wsrc[(size_t)(kr0 + j) * D + t];
        __syncthreads();
        float a0 = 0.f, a1 = 0.f, a2 = 0.f, a3 = 0.f;
        #pragma unroll
        for (int m0 = 0; m0 < 128; m0 += 16) {
            float wbuf[16];
            #pragma unroll
            for (int j = 0; j < 16; j++)
                wbuf[j] = W2base[(size_t)(m0 + j) * D + t];
            #pragma unroll
            for (int j = 0; j < 16; j++) {
                float w2 = wbuf[j];
                a0 += srow[0][m0 + j] * w2;
                a1 += srow[1][m0 + j] * w2;
                a2 += srow[2][m0 + j] * w2;
                a3 += srow[3][m0 + j] * w2;
            }
        }
        float accs[4] = {a0, a1, a2, a3};
        if (isWc) {
            #pragma unroll
            for (int j = 0; j < 4; j++)
                g_Wch[t * 128 + kr0 + j] = __float2bfloat16(accs[j]);
        } else {
            #pragma unroll
            for (int j = 0; j < 4; j++) {
                int kr = kr0 + j;
                int x = kr >> 7, k = kr & 127;
                __nv_bfloat16 h = __float2bfloat16(accs[j]);
                g_Wbh[(x * 128 + t) * 128 + k] = h;
                g_Wbl[(x * 128 + t) * 128 + k] =
                    __float2bfloat16(accs[j] - __bfloat162float(h));
            }
        }
    } else if (blk == 32) {
        // ---- misc: uq/uk via float4 row loads, bc0/bc3 batched ----
        __shared__ float sws[2 * D];
        __shared__ float sbm[D], sbo[D];
        sws[t] = w_score[t];
        sws[D + t] = w_score[D + t];
        sbm[t] = b_mix3[t];
        sbo[t] = b_out[t];
        __syncthreads();
        const float4* qrow = (const float4*)(W_qkv + (size_t)t * 3 * D);
        float uq = 0.f, uk = 0.f;
        #pragma unroll
        for (int i = 0; i < 32; i++) {
            float4 q4 = qrow[i];
            float4 w4 = *(const float4*)&sws[4 * i];
            uq += q4.x * w4.x + q4.y * w4.y + q4.z * w4.z + q4.w * w4.w;
            float4 k4 = qrow[32 + i];
            float4 v4 = *(const float4*)&sws[D + 4 * i];
            uk += k4.x * v4.x + k4.y * v4.y + k4.z * v4.z + k4.w * v4.w;
        }
        g_uq[t] = uq;
        g_uk[t] = uk;
        float bc0 = b_mix2[t];
        float bc3 = 0.f;
        #pragma unroll
        for (int m0 = 0; m0 < 128; m0 += 8) {
            float wa[8], wb[8];
            #pragma unroll
            for (int j = 0; j < 8; j++) {
                wa[j] = W_mix2[(size_t)(m0 + j) * D + t];
                wb[j] = W_mix2[(size_t)(D + m0 + j) * D + t];
            }
            #pragma unroll
            for (int j = 0; j < 8; j++) {
                bc3 += sbm[m0 + j] * wa[j];
                bc0 += sbo[m0 + j] * wb[j];
            }
        }
        g_bc0[t] = bc0;
        g_bc3[t] = bc3 + bc0;
        #pragma unroll
        for (int i = t; i < B * D; i += 128) g_colsum[i] = 0.f;
        __shared__ float s1[D], s2[D];
        s1[t] = b_qkv[t] * sws[t];
        s2[t] = b_qkv[D + t] * sws[D + t];
        __syncthreads();
        for (int off = 64; off; off >>= 1) {
            if (t < off) { s1[t] += s1[t + off]; s2[t] += s2[t + off]; }
            __syncthreads();
        }
        if (t == 0) { g_c[0] = s1[0]; g_c[1] = s2[0] + b_score[0]; }
    } else {
        // ---- v weights: k = (blk-129)*8 + j ----
        int k0 = (blk - 129) * 8;
        float wv[8];
        #pragma unroll
        for (int j = 0; j < 8; j++)
            wv[j] = W_qkv[(k0 + j) * 3 * D + 2 * D + t];
        #pragma unroll
        for (int j = 0; j < 8; j++) {
            int k = k0 + j;
            __nv_bfloat16 h = __float2bfloat16(wv[j]);
            g_Wbh[(384 + t) * 128 + k] = h;
            g_Wbl[(384 + t) * 128 + k] = __float2bfloat16(wv[j] - __bfloat162float(h));
        }
    }
}

// ---------------- K1: big GEMM ops @ [W3a'|W3b'|W3c'|Wv] + begin/end side blocks ----------------
// grid 1024+16, block 256, dyn smem 48KB, occ 2
__global__ void __launch_bounds__(256, 2) k_gemm(
    const float* __restrict__ ops, const float* __restrict__ b_qkv,
    const int* __restrict__ bidx, const int* __restrict__ eidx,
    const float* __restrict__ W_begin, const float* __restrict__ b_begin,
    const float* __restrict__ W_end, const float* __restrict__ b_end,
    const float* __restrict__ W_mix2) {
    __shared__ float sbv[128];
    __shared__ float suq[128], suk[128];
    extern __shared__ __align__(16) char dsm[];
    char* smb = (char*)((((uintptr_t)dsm) + 1023) & ~(uintptr_t)1023);
    char* smAh = smb;
    char* smAl = smb + 8192;
    char* smBh = smb + 16384;
    char* smBl = smb + 32768;
    uint32_t suAh = smem_u32(smAh), suAl = smem_u32(smAl);
    uint32_t suBh = smem_u32(smBh), suBl = smem_u32(smBl);

    int blk = blockIdx.x;
    int t = threadIdx.x;

    if (blk >= 1024) {
        // ---- begin/end: be = mean@W + b; beW = be@W_mix2[:D] + bc0 ----
        int e = blk - 1024;
        int b = e >> 1, which = e & 1;
        const int* idx = which ? eidx : bidx;
        if (t < 128) {
            float s = 0.f;
            for (int j = 0; j < J; j++)
                s += ops[((size_t)b * C + idx[b * J + j]) * D + t];
            suq[t] = s * (1.0f / (float)J);
        }
        __syncthreads();
        if (t < 128) {
            const float* W = which ? W_end : W_begin;
            const float* bbp = which ? b_end : b_begin;
            float acc = bbp[t];
            #pragma unroll 8
            for (int k = 0; k < D; k++) acc += suq[k] * W[k * D + t];
            suk[t] = acc;
        }
        __syncthreads();
        if (t < 128) {
            float acc2 = g_bc0[t];
            #pragma unroll 8
            for (int k = 0; k < D; k++) acc2 += suk[k] * W_mix2[k * D + t];
            g_beW[((size_t)b * 2 + which) * D + t] = acc2;
        }
        return;
    }

    int mt = blk >> 2, ng = blk & 3;
    int b = mt >> 5;
    int i0 = (mt & 31) * 64;
    int w = t >> 5, lane = t & 31;

    if (ng == 3 && t < 128) sbv[t] = b_qkv[2 * D + t];
    if (ng == 0 && t < 128) { suq[t] = g_uq[t]; suk[t] = g_uk[t]; }
    __syncthreads();

    float cc[8][4];
    #pragma unroll
    for (int nt = 0; nt < 8; nt++)
        #pragma unroll
        for (int r = 0; r < 4; r++) cc[nt][r] = 0.f;

    int l8 = lane & 7, grp = lane >> 3;
    int mg = w >> 1, nh = w & 1;
    int rowA = (mg << 4) + l8 + ((grp & 1) << 3);
    int colAg = (grp >> 1) << 4;
    int rowBoff = l8 + ((grp >> 1) << 3);
    int colBg = (grp & 1) << 4;

    int r = t >> 2, h = t & 3;   // 4 threads per A row
    int rowoff = r * 128 + h * 32;
    float dq = 0.f, dk = 0.f;

    #pragma unroll 1
    for (int c = 0; c < 2; c++) {
        if (c) __syncthreads();
        const float4* src = (const float4*)
            (ops + ((size_t)b * C + i0 + r) * D + c * 64 + h * 16);
        #pragma unroll
        for (int q = 0; q < 4; q++) {
            float4 v = src[q];
            if (ng == 0) {
                float4 u4 = *(const float4*)&suq[c * 64 + h * 16 + q * 4];
                float4 k4 = *(const float4*)&suk[c * 64 + h * 16 + q * 4];
                dq += v.x * u4.x + v.y * u4.y + v.z * u4.z + v.w * u4.w;
                dk += v.x * k4.x + v.y * k4.y + v.z * k4.z + v.w * k4.w;
            }
            uint32_t h0, h1, l0, l1;
            split2(v.x, v.y, h0, l0);
            split2(v.z, v.w, h1, l1);
            uint32_t off = rowoff + q * 8;
            *(uint2*)(smAh + SWZ(off)) = make_uint2(h0, h1);
            *(uint2*)(smAl + SWZ(off)) = make_uint2(l0, l1);
        }
        #pragma unroll
        for (int c2 = 0; c2 < 4; c2++) {
            int idx = t + c2 * 256;
            int dd = idx >> 3, ccx = idx & 7;
            uint32_t off = dd * 128 + ccx * 16;
            int gsrc = (ng * 128 + dd) * 128 + c * 64 + ccx * 8;
            *(uint4*)(smBh + SWZ(off)) = *(const uint4*)&g_Wbh[gsrc];
            *(uint4*)(smBl + SWZ(off)) = *(const uint4*)&g_Wbl[gsrc];
        }
        __syncthreads();
        mma_pass64(suAh, suBh, cc, rowA, colAg, nh, rowBoff, colBg);
        mma_pass64(suAh, suBl, cc, rowA, colAg, nh, rowBoff, colBg);
        mma_pass64(suAl, suBh, cc, rowA, colAg, nh, rowBoff, colBg);
    }

    if (ng == 0) {
        dq += __shfl_xor_sync(0xffffffffu, dq, 1);
        dk += __shfl_xor_sync(0xffffffffu, dk, 1);
        dq += __shfl_xor_sync(0xffffffffu, dq, 2);
        dk += __shfl_xor_sync(0xffffffffu, dk, 2);
        if (h == 0) {
            int row = b * C + i0 + r;
            g_sq[row] = dq + g_c[0];
            g_sk[row] = dk + g_c[1];
        }
    }

    int quad = lane >> 2, qt = lane & 3;
    if (ng < 3) {
        float* ob = g_mx + (size_t)ng * BCD + (size_t)b * C * D;
        int r0g = i0 + (mg << 4) + quad;
        #pragma unroll
        for (int nt = 0; nt < 8; nt++) {
            int n0 = (nh << 6) + nt * 8 + 2 * qt;
            *(float2*)&ob[(size_t)r0g * D + n0] = make_float2(cc[nt][0], cc[nt][1]);
            *(float2*)&ob[(size_t)(r0g + 8) * D + n0] = make_float2(cc[nt][2], cc[nt][3]);
        }
    } else {
        // v group: bias, bf16, transpose-stage in smem -> g_vT + colsum
        __syncthreads();
        __nv_bfloat16* vst = (__nv_bfloat16*)smb;   // [128 n][64 m] = 16KB
        int m0 = (mg << 4) + quad, m8 = m0 + 8;
        #pragma unroll
        for (int nt = 0; nt < 8; nt++) {
            int n0 = (nh << 6) + nt * 8 + 2 * qt;
            float vb0 = sbv[n0], vb1 = sbv[n0 + 1];
            vst[n0 * 64 + m0]       = __float2bfloat16(cc[nt][0] + vb0);
            vst[(n0 + 1) * 64 + m0] = __float2bfloat16(cc[nt][1] + vb1);
            vst[n0 * 64 + m8]       = __float2bfloat16(cc[nt][2] + vb0);
            vst[(n0 + 1) * 64 + m8] = __float2bfloat16(cc[nt][3] + vb1);
        }
        __syncthreads();
        int n = t >> 1, hh = t & 1;
        const uint4* srcv = (const uint4*)(vst + n * 64 + hh * 32);
        uint4* dstv = (uint4*)(g_vT + ((size_t)b * D + n) * C + i0 + hh * 32);
        #pragma unroll
        for (int q = 0; q < 4; q++) dstv[q] = srcv[q];
        if (t < 128) {
            float s = 0.f;
            #pragma unroll 16
            for (int m = 0; m < 64; m++) s += __bfloat162float(vst[t * 64 + m]);
            atomicAdd(&g_colsum[b * D + t], s);
        }
    }
}

// ---------------- K2: attention HMMA + fused weighted@Wc + gather-add epilogue ----------------
// grid 256, block 256, occ 2
__global__ void __launch_bounds__(256, 2) k_attn(const float* __restrict__ mask,
                                                 const int* __restrict__ rel,
                                                 float* __restrict__ out) {
    __shared__ __align__(128) char smA[64 * 128];     // probs / weighted chunk 0
    __shared__ __align__(128) char smA2[64 * 128];    // weighted chunk 1
    __shared__ __align__(128) char smB[128 * 128];
    __shared__ float ssq[64];
    __shared__ float srow[64];
    __shared__ float scol[128];
    __shared__ float sb3[128];
    __shared__ int2 srel[64];

    int t = threadIdx.x;
    int blk = blockIdx.x;
    int w = t >> 5, lane = t & 31;
    int b = blk >> 5;
    int i0 = (blk & 31) * 64;
    int base = b * C;

    uint32_t suA = smem_u32(smA);
    uint32_t suA2 = smem_u32(smA2);
    uint32_t suB = smem_u32(smB);

    if (t < 64) {
        ssq[t] = g_sq[base + i0 + t];
        int ig = i0 + t;
        srel[t] = (ig < CM2) ? *(const int2*)&rel[((size_t)b * CM2 + ig) * 2]
                             : make_int2(0, 0);
    }
    if (t < 128) { scol[t] = g_colsum[b * D + t]; sb3[t] = g_bc3[t]; }

    float rowsum[8];
    #pragma unroll
    for (int s = 0; s < 8; s++) rowsum[s] = 0.f;

    float cc[8][4];
    #pragma unroll
    for (int nt = 0; nt < 8; nt++)
        #pragma unroll
        for (int r = 0; r < 4; r++) cc[nt][r] = 0.f;

    const __nv_bfloat16* vTb = g_vT + (size_t)b * D * C;

    int l8 = lane & 7, grp = lane >> 3;
    int mg = w >> 1, nh = w & 1;
    int rowA = (mg << 4) + l8 + ((grp & 1) << 3);
    int colAg = (grp >> 1) << 4;
    int rowBoff = l8 + ((grp >> 1) << 3);
    int colBg = (grp & 1) << 4;

    // ---- attention mainloop ----
    for (int i = 0; i < C / 64; i++) {
        int jb = i * 64;
        __syncthreads();
        {
            float2 sk2 = *(const float2*)&g_sk[base + jb + 2 * lane];
            const float* mrow0 = mask + (size_t)(base + i0 + w) * C + jb + 2 * lane;
            #pragma unroll
            for (int s = 0; s < 8; s++) {
                int row = w + 8 * s;
                float2 mk = *(const float2*)(mrow0 + (size_t)(8 * s) * C);
                float q = ssq[row];
                float x0 = q + sk2.x; x0 = (x0 >= 0.f) ? x0 : 0.01f * x0; x0 *= mk.x;
                float x1 = q + sk2.y; x1 = (x1 >= 0.f) ? x1 : 0.01f * x1; x1 *= mk.y;
                float p0 = __expf(x0), p1 = __expf(x1);
                rowsum[s] += p0 + p1;
                uint32_t pr; CVT_BF16X2(pr, p0 - 1.f, p1 - 1.f);
                uint32_t off = row * 128 + lane * 4;
                *(uint32_t*)(smA + SWZ(off)) = pr;
            }
        }
        #pragma unroll
        for (int c = 0; c < 4; c++) {
            int idx = t + c * 256;
            int dd = idx >> 3, ccx = idx & 7;
            uint4 val = *(const uint4*)(vTb + (size_t)dd * C + jb + ccx * 8);
            uint32_t off = dd * 128 + ccx * 16;
            *(uint4*)(smB + SWZ(off)) = val;
        }
        __syncthreads();
        mma_pass64(suA, suB, cc, rowA, colAg, nh, rowBoff, colBg);
    }

    // ---- rowsum reduce ----
    #pragma unroll
    for (int s = 0; s < 8; s++) {
        float r = rowsum[s];
        #pragma unroll
        for (int off = 16; off; off >>= 1) r += __shfl_down_sync(0xffffffffu, r, off);
        if (lane == 0) srow[w + 8 * s] = r;
    }
    __syncthreads();

    // ---- normalize weighted + stage bf16 into smA (n<64) / smA2 (n>=64) ----
    int quad = lane >> 2, qt = lane & 3;
    int m0 = (mg << 4) + quad;
    float inv0 = 1.0f / srow[m0];
    float inv8 = 1.0f / srow[m0 + 8];
    char* stg = nh ? smA2 : smA;
    #pragma unroll
    for (int nt = 0; nt < 8; nt++) {
        int n0 = (nh << 6) + nt * 8 + 2 * qt;
        float cs0 = scol[n0], cs1 = scol[n0 + 1];
        float w00 = (cs0 + cc[nt][0]) * inv0;
        float w01 = (cs1 + cc[nt][1]) * inv0;
        float w80 = (cs0 + cc[nt][2]) * inv8;
        float w81 = (cs1 + cc[nt][3]) * inv8;
        uint32_t pr0, pr8;
        CVT_BF16X2(pr0, w00, w01);
        CVT_BF16X2(pr8, w80, w81);
        uint32_t col = (nt * 8 + 2 * qt) * 2;   // byte offset within 128B row
        *(uint32_t*)(stg + SWZ(m0 * 128 + col)) = pr0;
        *(uint32_t*)(stg + SWZ((m0 + 8) * 128 + col)) = pr8;
    }

    // ---- weighted @ Wc (hi-only), 2 K-chunks ----
    #pragma unroll
    for (int nt = 0; nt < 8; nt++)
        #pragma unroll
        for (int r = 0; r < 4; r++) cc[nt][r] = 0.f;

    #pragma unroll 1
    for (int c = 0; c < 2; c++) {
        __syncthreads();
        #pragma unroll
        for (int c2 = 0; c2 < 4; c2++) {
            int idx = t + c2 * 256;
            int dd = idx >> 3, ccx = idx & 7;
            *(uint4*)(smB + SWZ(dd * 128 + ccx * 16)) =
                *(const uint4*)&g_Wch[dd * 128 + c * 64 + ccx * 8];
        }
        __syncthreads();
        mma_pass64(c ? suA2 : suA, suB, cc, rowA, colAg, nh, rowBoff, colBg);
    }

    // ---- epilogue: out = Pa[i] + Pb[r0] + Pc[r1] + bc3 + cc  (or g_beW + cc) ----
    int r0g = i0 + m0;
    size_t bb = (size_t)b * C * D;
    const float* m1 = g_mx + bb;
    const float* m2 = g_mx + BCD + bb;
    const float* m3 = g_mx + 2 * BCD + bb;
    float* ob = out + bb;

    #pragma unroll
    for (int half = 0; half < 2; half++) {
        int rg = r0g + half * 8;
        int loc = rg - i0;
        if (rg < CM2) {
            int2 rr = srel[loc];
            const float* pa = m1 + (size_t)rg * D;
            const float* pb = m2 + (size_t)rr.x * D;
            const float* pc = m3 + (size_t)rr.y * D;
            #pragma unroll
            for (int nt = 0; nt < 8; nt++) {
                int n0 = (nh << 6) + nt * 8 + 2 * qt;
                float2 a2 = *(const float2*)(pa + n0);
                float2 b2 = *(const float2*)(pb + n0);
                float2 c2v = *(const float2*)(pc + n0);
                float vx = a2.x + b2.x + c2v.x + sb3[n0] + cc[nt][2 * half];
                float vy = a2.y + b2.y + c2v.y + sb3[n0 + 1] + cc[nt][2 * half + 1];
                *(float2*)&ob[(size_t)rg * D + n0] = make_float2(vx, vy);
            }
        } else {
            const float* pe = g_beW + ((size_t)b * 2 + (rg - CM2)) * D;
            #pragma unroll
            for (int nt = 0; nt < 8; nt++) {
                int n0 = (nh << 6) + nt * 8 + 2 * qt;
                float2 ev = *(const float2*)(pe + n0);
                *(float2*)&ob[(size_t)rg * D + n0] =
                    make_float2(ev.x + cc[nt][2 * half],
                                ev.y + cc[nt][2 * half + 1]);
            }
        }
    }
}

// ---------------- launch ----------------
extern "C" void kernel_launch(void* const* d_in, const int* in_sizes, int n_in,
                              void* d_out, int out_size) {
    const float* ops      = (const float*)d_in[0];
    const int*   rel      = (const int*)d_in[1];
    const int*   bidx     = (const int*)d_in[2];
    const int*   eidx     = (const int*)d_in[3];
    const float* mask     = (const float*)d_in[4];
    const float* W_begin  = (const float*)d_in[5];
    const float* b_begin  = (const float*)d_in[6];
    const float* W_end    = (const float*)d_in[7];
    const float* b_end    = (const float*)d_in[8];
    const float* W_mix3   = (const float*)d_in[9];
    const float* b_mix3   = (const float*)d_in[10];
    const float* W_qkv    = (const float*)d_in[11];
    const float* b_qkv    = (const float*)d_in[12];
    const float* w_score  = (const float*)d_in[13];
    const float* b_score  = (const float*)d_in[14];
    const float* W_out    = (const float*)d_in[15];
    const float* b_out    = (const float*)d_in[16];
    const float* W_mix2   = (const float*)d_in[17];
    const float* b_mix2   = (const float*)d_in[18];
    float* out = (float*)d_out;

    static bool attr_set = false;
    if (!attr_set) {
        cudaFuncSetAttribute(k_gemm, cudaFuncAttributeMaxDynamicSharedMemorySize, SMEM_MMA2);
        attr_set = true;
    }

    k_pre<<<145, 128>>>(W_qkv, b_qkv, w_score, b_score, W_out, b_out,
                        W_mix2, b_mix2, W_mix3, b_mix3);
    k_gemm<<<1024 + 2 * B, 256, SMEM_MMA2>>>(ops, b_qkv, bidx, eidx,
                                             W_begin, b_begin, W_end, b_end, W_mix2);
    k_attn<<<256, 256>>>(mask, rel, out);
}

// round 15
// speedup vs baseline: 5.1600x; 1.0546x over previous
#include <cuda_runtime.h>
#include <cuda_bf16.h>
#include <cstdint>

#define B 8
#define C 2048
#define D 128
#define J 128
#define CM2 (C - 2)   // 2046
#define BCD (B * C * D)

// ---------------- scratch (device globals) ----------------
__device__ __align__(16) __nv_bfloat16 g_vT[B * D * C];   // v bf16 transposed [b][d][j]
__device__ __align__(16) float g_mx[3 * BCD];             // Pa / Pb / Pc = ops@(W3x@W2a)
__device__ __align__(16) float g_beW[B * 2 * D];          // (begin/end)@W_mix2[:D] + bc0
__device__ float g_colsum[B * D];
__device__ float g_sq[B * C];
__device__ float g_sk[B * C];
__device__ float g_uq[D];
__device__ float g_uk[D];
__device__ float g_c[2];
__device__ float g_bc0[D];                                // b_out@W2b + b_mix2
__device__ float g_bc3[D];                                // bc0 + b_mix3@W2a
// split-bf16 transposed weights
__device__ __align__(16) __nv_bfloat16 g_Wbh[512 * D];    // [W3a'|W3b'|W3c'|Wv] as [n][k]
__device__ __align__(16) __nv_bfloat16 g_Wbl[512 * D];
__device__ __align__(16) __nv_bfloat16 g_Wch[D * D];      // Wc = W_out@W2b as [n][k], hi only

// ---------------- helpers ----------------
__device__ __forceinline__ uint32_t smem_u32(const void* p) {
    uint32_t a;
    asm("{ .reg .u64 tmp; cvta.to.shared.u64 tmp, %1; cvt.u32.u64 %0, tmp; }"
        : "=r"(a) : "l"(p));
    return a;
}
#define CVT_BF16X2(res, a, b) \
    asm("cvt.rn.satfinite.bf16x2.f32 %0, %1, %2;" : "=r"(res) : "f"(b), "f"(a))
#define SWZ(x) ((x) ^ (((x) >> 3) & 0x70))

__device__ __forceinline__ void ldm_x4(uint32_t& r0, uint32_t& r1, uint32_t& r2,
                                       uint32_t& r3, uint32_t addr) {
    asm volatile("ldmatrix.sync.aligned.m8n8.x4.shared.b16 {%0,%1,%2,%3}, [%4];"
                 : "=r"(r0), "=r"(r1), "=r"(r2), "=r"(r3) : "r"(addr));
}
__device__ __forceinline__ void mma16816(float* c, uint32_t a0, uint32_t a1,
                                         uint32_t a2, uint32_t a3,
                                         uint32_t b0, uint32_t b1) {
    asm volatile(
        "mma.sync.aligned.m16n8k16.row.col.f32.bf16.bf16.f32 "
        "{%0,%1,%2,%3}, {%4,%5,%6,%7}, {%8,%9}, {%0,%1,%2,%3};"
        : "+f"(c[0]), "+f"(c[1]), "+f"(c[2]), "+f"(c[3])
        : "r"(a0), "r"(a1), "r"(a2), "r"(a3), "r"(b0), "r"(b1));
}
__device__ __forceinline__ void split2(float x0, float x1, uint32_t& hp, uint32_t& lp) {
    CVT_BF16X2(hp, x0, x1);
    __nv_bfloat162 hv = *reinterpret_cast<__nv_bfloat162*>(&hp);
    float f0 = __bfloat162float(hv.x), f1 = __bfloat162float(hv.y);
    CVT_BF16X2(lp, x0 - f0, x1 - f1);
}
// one K=64 pass: warp (mg, nh) computes 16m x 64n, A tile 64 rows
__device__ __forceinline__ void mma_pass64(uint32_t suA, uint32_t suB, float cc[8][4],
                                           int rowA, int colAg, int nh,
                                           int rowBoff, int colBg) {
    #pragma unroll
    for (int ks = 0; ks < 4; ks++) {
        uint32_t a0, a1, a2, a3;
        ldm_x4(a0, a1, a2, a3, suA + SWZ(rowA * 128 + ks * 32 + colAg));
        #pragma unroll
        for (int nt = 0; nt < 8; nt += 2) {
            uint32_t b0, b1, b2, b3;
            int rowB = (nh << 6) + nt * 8 + rowBoff;
            ldm_x4(b0, b1, b2, b3, suB + SWZ(rowB * 128 + ks * 32 + colBg));
            mma16816(cc[nt],     a0, a1, a2, a3, b0, b1);
            mma16816(cc[nt + 1], a0, a1, a2, a3, b2, b3);
        }
    }
}

#define SMEM_MMA2 (49152 + 1024)

// ---------------- K0: folded + split/transposed weights ----------------
// grid 161, block 128
//   blk 0..31   : Wc fold, 4 k-rows/block
//   blk 32      : bc0/bc3 + colsum zero + g_c
//   blk 33..128 : W3' fold, 4 k-rows/block (96 blocks x 4 = 384)
//   blk 129..144: v-weight transpose copy, 8 k/block
//   blk 145..160: uq/uk, 8 rows/block (16 threads per row)
__global__ void k_pre(const float* __restrict__ W_qkv, const float* __restrict__ b_qkv,
                      const float* __restrict__ w_score, const float* __restrict__ b_score,
                      const float* __restrict__ W_out, const float* __restrict__ b_out,
                      const float* __restrict__ W_mix2, const float* __restrict__ b_mix2,
                      const float* __restrict__ W_mix3, const float* __restrict__ b_mix3) {
    int t = threadIdx.x;
    int blk = blockIdx.x;
    __shared__ __align__(16) float srow[4][D];

    if (blk < 32 || (blk >= 33 && blk < 129)) {
        // ---- unified fold: acc[j] = sum_m src[kr0+j][m] * W2base[m][t] ----
        bool isWc = (blk < 32);
        int kr0 = isWc ? blk * 4 : (blk - 33) * 4;
        const float* Wsrc = isWc ? W_out : W_mix3;
        const float* W2base = isWc ? (W_mix2 + (size_t)D * D) : W_mix2;
        #pragma unroll
        for (int j = 0; j < 4; j++)
            srow[j][t] = Wsrc[(size_t)(kr0 + j) * D + t];
        __syncthreads();
        float a0 = 0.f, a1 = 0.f, a2 = 0.f, a3 = 0.f;
        #pragma unroll
        for (int m0 = 0; m0 < 128; m0 += 16) {
            float wbuf[16];
            #pragma unroll
            for (int j = 0; j < 16; j++)
                wbuf[j] = W2base[(size_t)(m0 + j) * D + t];
            #pragma unroll
            for (int j = 0; j < 16; j++) {
                float w2 = wbuf[j];
                a0 += srow[0][m0 + j] * w2;
                a1 += srow[1][m0 + j] * w2;
                a2 += srow[2][m0 + j] * w2;
                a3 += srow[3][m0 + j] * w2;
            }
        }
        float accs[4] = {a0, a1, a2, a3};
        if (isWc) {
            #pragma unroll
            for (int j = 0; j < 4; j++)
                g_Wch[t * 128 + kr0 + j] = __float2bfloat16(accs[j]);
        } else {
            #pragma unroll
            for (int j = 0; j < 4; j++) {
                int kr = kr0 + j;
                int x = kr >> 7, k = kr & 127;
                __nv_bfloat16 h = __float2bfloat16(accs[j]);
                g_Wbh[(x * 128 + t) * 128 + k] = h;
                g_Wbl[(x * 128 + t) * 128 + k] =
                    __float2bfloat16(accs[j] - __bfloat162float(h));
            }
        }
    } else if (blk == 32) {
        // ---- bc0/bc3 + colsum zero + g_c ----
        __shared__ float sbm[D], sbo[D];
        sbm[t] = b_mix3[t];
        sbo[t] = b_out[t];
        __syncthreads();
        float bc0 = b_mix2[t];
        float bc3 = 0.f;
        #pragma unroll
        for (int m0 = 0; m0 < 128; m0 += 8) {
            float wa[8], wb[8];
            #pragma unroll
            for (int j = 0; j < 8; j++) {
                wa[j] = W_mix2[(size_t)(m0 + j) * D + t];
                wb[j] = W_mix2[(size_t)(D + m0 + j) * D + t];
            }
            #pragma unroll
            for (int j = 0; j < 8; j++) {
                bc3 += sbm[m0 + j] * wa[j];
                bc0 += sbo[m0 + j] * wb[j];
            }
        }
        g_bc0[t] = bc0;
        g_bc3[t] = bc3 + bc0;
        #pragma unroll
        for (int i = t; i < B * D; i += 128) g_colsum[i] = 0.f;
        __shared__ float s1[D], s2[D];
        s1[t] = b_qkv[t] * w_score[t];
        s2[t] = b_qkv[D + t] * w_score[D + t];
        __syncthreads();
        for (int off = 64; off; off >>= 1) {
            if (t < off) { s1[t] += s1[t + off]; s2[t] += s2[t + off]; }
            __syncthreads();
        }
        if (t == 0) { g_c[0] = s1[0]; g_c[1] = s2[0] + b_score[0]; }
    } else if (blk < 145) {
        // ---- v weights: k = (blk-129)*8 + j ----
        int k0 = (blk - 129) * 8;
        float wv[8];
        #pragma unroll
        for (int j = 0; j < 8; j++)
            wv[j] = W_qkv[(k0 + j) * 3 * D + 2 * D + t];
        #pragma unroll
        for (int j = 0; j < 8; j++) {
            int k = k0 + j;
            __nv_bfloat16 h = __float2bfloat16(wv[j]);
            g_Wbh[(384 + t) * 128 + k] = h;
            g_Wbl[(384 + t) * 128 + k] = __float2bfloat16(wv[j] - __bfloat162float(h));
        }
    } else {
        // ---- uq/uk: 8 rows per block, 16 threads per row ----
        __shared__ float sws[2 * D];
        sws[t] = w_score[t];
        sws[D + t] = w_score[D + t];
        __syncthreads();
        int row = (blk - 145) * 8 + (t >> 4);
        int seg = t & 15;
        const float* qr = W_qkv + (size_t)row * 3 * D;
        float4 qa = *(const float4*)(qr + seg * 8);
        float4 qb = *(const float4*)(qr + seg * 8 + 4);
        float4 ka = *(const float4*)(qr + D + seg * 8);
        float4 kb = *(const float4*)(qr + D + seg * 8 + 4);
        float4 w0 = *(const float4*)&sws[seg * 8];
        float4 w1 = *(const float4*)&sws[seg * 8 + 4];
        float4 w2 = *(const float4*)&sws[D + seg * 8];
        float4 w3 = *(const float4*)&sws[D + seg * 8 + 4];
        float uq = qa.x * w0.x + qa.y * w0.y + qa.z * w0.z + qa.w * w0.w
                 + qb.x * w1.x + qb.y * w1.y + qb.z * w1.z + qb.w * w1.w;
        float uk = ka.x * w2.x + ka.y * w2.y + ka.z * w2.z + ka.w * w2.w
                 + kb.x * w3.x + kb.y * w3.y + kb.z * w3.z + kb.w * w3.w;
        #pragma unroll
        for (int off = 8; off; off >>= 1) {
            uq += __shfl_down_sync(0xffffffffu, uq, off);
            uk += __shfl_down_sync(0xffffffffu, uk, off);
        }
        if (seg == 0) { g_uq[row] = uq; g_uk[row] = uk; }
    }
}

// ---------------- K1: big GEMM ops @ [W3a'|W3b'|W3c'|Wv] + begin/end side blocks ----------------
// grid 1024+16, block 256, dyn smem 48KB, occ 2
__global__ void __launch_bounds__(256, 2) k_gemm(
    const float* __restrict__ ops, const float* __restrict__ b_qkv,
    const int* __restrict__ bidx, const int* __restrict__ eidx,
    const float* __restrict__ W_begin, const float* __restrict__ b_begin,
    const float* __restrict__ W_end, const float* __restrict__ b_end,
    const float* __restrict__ W_mix2) {
    __shared__ float sbv[128];
    __shared__ float suq[128], suk[128];
    extern __shared__ __align__(16) char dsm[];
    char* smb = (char*)((((uintptr_t)dsm) + 1023) & ~(uintptr_t)1023);
    char* smAh = smb;
    char* smAl = smb + 8192;
    char* smBh = smb + 16384;
    char* smBl = smb + 32768;
    uint32_t suAh = smem_u32(smAh), suAl = smem_u32(smAl);
    uint32_t suBh = smem_u32(smBh), suBl = smem_u32(smBl);

    int blk = blockIdx.x;
    int t = threadIdx.x;

    if (blk >= 1024) {
        // ---- begin/end: be = mean@W + b; beW = be@W_mix2[:D] + bc0 ----
        int e = blk - 1024;
        int b = e >> 1, which = e & 1;
        const int* idx = which ? eidx : bidx;
        if (t < 128) {
            float s = 0.f;
            for (int j = 0; j < J; j++)
                s += ops[((size_t)b * C + idx[b * J + j]) * D + t];
            suq[t] = s * (1.0f / (float)J);
        }
        __syncthreads();
        if (t < 128) {
            const float* W = which ? W_end : W_begin;
            const float* bbp = which ? b_end : b_begin;
            float acc = bbp[t];
            #pragma unroll 8
            for (int k = 0; k < D; k++) acc += suq[k] * W[k * D + t];
            suk[t] = acc;
        }
        __syncthreads();
        if (t < 128) {
            float acc2 = g_bc0[t];
            #pragma unroll 8
            for (int k = 0; k < D; k++) acc2 += suk[k] * W_mix2[k * D + t];
            g_beW[((size_t)b * 2 + which) * D + t] = acc2;
        }
        return;
    }

    int mt = blk >> 2, ng = blk & 3;
    int b = mt >> 5;
    int i0 = (mt & 31) * 64;
    int w = t >> 5, lane = t & 31;

    if (ng == 3 && t < 128) sbv[t] = b_qkv[2 * D + t];
    if (ng == 0 && t < 128) { suq[t] = g_uq[t]; suk[t] = g_uk[t]; }
    __syncthreads();

    float cc[8][4];
    #pragma unroll
    for (int nt = 0; nt < 8; nt++)
        #pragma unroll
        for (int r = 0; r < 4; r++) cc[nt][r] = 0.f;

    int l8 = lane & 7, grp = lane >> 3;
    int mg = w >> 1, nh = w & 1;
    int rowA = (mg << 4) + l8 + ((grp & 1) << 3);
    int colAg = (grp >> 1) << 4;
    int rowBoff = l8 + ((grp >> 1) << 3);
    int colBg = (grp & 1) << 4;

    int r = t >> 2, h = t & 3;   // 4 threads per A row
    int rowoff = r * 128 + h * 32;
    float dq = 0.f, dk = 0.f;

    #pragma unroll 1
    for (int c = 0; c < 2; c++) {
        if (c) __syncthreads();
        const float4* src = (const float4*)
            (ops + ((size_t)b * C + i0 + r) * D + c * 64 + h * 16);
        #pragma unroll
        for (int q = 0; q < 4; q++) {
            float4 v = src[q];
            if (ng == 0) {
                float4 u4 = *(const float4*)&suq[c * 64 + h * 16 + q * 4];
                float4 k4 = *(const float4*)&suk[c * 64 + h * 16 + q * 4];
                dq += v.x * u4.x + v.y * u4.y + v.z * u4.z + v.w * u4.w;
                dk += v.x * k4.x + v.y * k4.y + v.z * k4.z + v.w * k4.w;
            }
            uint32_t h0, h1, l0, l1;
            split2(v.x, v.y, h0, l0);
            split2(v.z, v.w, h1, l1);
            uint32_t off = rowoff + q * 8;
            *(uint2*)(smAh + SWZ(off)) = make_uint2(h0, h1);
            *(uint2*)(smAl + SWZ(off)) = make_uint2(l0, l1);
        }
        #pragma unroll
        for (int c2 = 0; c2 < 4; c2++) {
            int idx = t + c2 * 256;
            int dd = idx >> 3, ccx = idx & 7;
            uint32_t off = dd * 128 + ccx * 16;
            int gsrc = (ng * 128 + dd) * 128 + c * 64 + ccx * 8;
            *(uint4*)(smBh + SWZ(off)) = *(const uint4*)&g_Wbh[gsrc];
            *(uint4*)(smBl + SWZ(off)) = *(const uint4*)&g_Wbl[gsrc];
        }
        __syncthreads();
        mma_pass64(suAh, suBh, cc, rowA, colAg, nh, rowBoff, colBg);
        mma_pass64(suAh, suBl, cc, rowA, colAg, nh, rowBoff, colBg);
        mma_pass64(suAl, suBh, cc, rowA, colAg, nh, rowBoff, colBg);
    }

    if (ng == 0) {
        dq += __shfl_xor_sync(0xffffffffu, dq, 1);
        dk += __shfl_xor_sync(0xffffffffu, dk, 1);
        dq += __shfl_xor_sync(0xffffffffu, dq, 2);
        dk += __shfl_xor_sync(0xffffffffu, dk, 2);
        if (h == 0) {
            int row = b * C + i0 + r;
            g_sq[row] = dq + g_c[0];
            g_sk[row] = dk + g_c[1];
        }
    }

    int quad = lane >> 2, qt = lane & 3;
    if (ng < 3) {
        float* ob = g_mx + (size_t)ng * BCD + (size_t)b * C * D;
        int r0g = i0 + (mg << 4) + quad;
        #pragma unroll
        for (int nt = 0; nt < 8; nt++) {
            int n0 = (nh << 6) + nt * 8 + 2 * qt;
            *(float2*)&ob[(size_t)r0g * D + n0] = make_float2(cc[nt][0], cc[nt][1]);
            *(float2*)&ob[(size_t)(r0g + 8) * D + n0] = make_float2(cc[nt][2], cc[nt][3]);
        }
    } else {
        // v group: bias, bf16, transpose-stage in smem -> g_vT + colsum
        __syncthreads();
        __nv_bfloat16* vst = (__nv_bfloat16*)smb;   // [128 n][64 m] = 16KB
        int m0 = (mg << 4) + quad, m8 = m0 + 8;
        #pragma unroll
        for (int nt = 0; nt < 8; nt++) {
            int n0 = (nh << 6) + nt * 8 + 2 * qt;
            float vb0 = sbv[n0], vb1 = sbv[n0 + 1];
            vst[n0 * 64 + m0]       = __float2bfloat16(cc[nt][0] + vb0);
            vst[(n0 + 1) * 64 + m0] = __float2bfloat16(cc[nt][1] + vb1);
            vst[n0 * 64 + m8]       = __float2bfloat16(cc[nt][2] + vb0);
            vst[(n0 + 1) * 64 + m8] = __float2bfloat16(cc[nt][3] + vb1);
        }
        __syncthreads();
        int n = t >> 1, hh = t & 1;
        const uint4* srcv = (const uint4*)(vst + n * 64 + hh * 32);
        uint4* dstv = (uint4*)(g_vT + ((size_t)b * D + n) * C + i0 + hh * 32);
        #pragma unroll
        for (int q = 0; q < 4; q++) dstv[q] = srcv[q];
        if (t < 128) {
            float s = 0.f;
            #pragma unroll 16
            for (int m = 0; m < 64; m++) s += __bfloat162float(vst[t * 64 + m]);
            atomicAdd(&g_colsum[b * D + t], s);
        }
    }
}

// ---------------- K2: attention HMMA + fused weighted@Wc + gather-add epilogue ----------------
// grid 256, block 256, occ 2
__global__ void __launch_bounds__(256, 2) k_attn(const float* __restrict__ mask,
                                                 const int* __restrict__ rel,
                                                 float* __restrict__ out) {
    __shared__ __align__(128) char smA[64 * 128];     // probs / weighted chunk 0
    __shared__ __align__(128) char smA2[64 * 128];    // weighted chunk 1
    __shared__ __align__(128) char smB[128 * 128];
    __shared__ float ssq[64];
    __shared__ float srow[64];
    __shared__ float scol[128];
    __shared__ float sb3[128];
    __shared__ int2 srel[64];

    int t = threadIdx.x;
    int blk = blockIdx.x;
    int w = t >> 5, lane = t & 31;
    int b = blk >> 5;
    int i0 = (blk & 31) * 64;
    int base = b * C;

    uint32_t suA = smem_u32(smA);
    uint32_t suA2 = smem_u32(smA2);
    uint32_t suB = smem_u32(smB);

    if (t < 64) {
        ssq[t] = g_sq[base + i0 + t];
        int ig = i0 + t;
        srel[t] = (ig < CM2) ? *(const int2*)&rel[((size_t)b * CM2 + ig) * 2]
                             : make_int2(0, 0);
    }
    if (t < 128) { scol[t] = g_colsum[b * D + t]; sb3[t] = g_bc3[t]; }

    float rowsum[8];
    #pragma unroll
    for (int s = 0; s < 8; s++) rowsum[s] = 0.f;

    float cc[8][4];
    #pragma unroll
    for (int nt = 0; nt < 8; nt++)
        #pragma unroll
        for (int r = 0; r < 4; r++) cc[nt][r] = 0.f;

    const __nv_bfloat16* vTb = g_vT + (size_t)b * D * C;

    int l8 = lane & 7, grp = lane >> 3;
    int mg = w >> 1, nh = w & 1;
    int rowA = (mg << 4) + l8 + ((grp & 1) << 3);
    int colAg = (grp >> 1) << 4;
    int rowBoff = l8 + ((grp >> 1) << 3);
    int colBg = (grp & 1) << 4;

    // ---- attention mainloop ----
    for (int i = 0; i < C / 64; i++) {
        int jb = i * 64;
        __syncthreads();
        {
            float2 sk2 = *(const float2*)&g_sk[base + jb + 2 * lane];
            const float* mrow0 = mask + (size_t)(base + i0 + w) * C + jb + 2 * lane;
            #pragma unroll
            for (int s = 0; s < 8; s++) {
                int row = w + 8 * s;
                float2 mk = *(const float2*)(mrow0 + (size_t)(8 * s) * C);
                float q = ssq[row];
                float x0 = q + sk2.x; x0 = (x0 >= 0.f) ? x0 : 0.01f * x0; x0 *= mk.x;
                float x1 = q + sk2.y; x1 = (x1 >= 0.f) ? x1 : 0.01f * x1; x1 *= mk.y;
                float p0 = __expf(x0), p1 = __expf(x1);
                rowsum[s] += p0 + p1;
                uint32_t pr; CVT_BF16X2(pr, p0 - 1.f, p1 - 1.f);
                uint32_t off = row * 128 + lane * 4;
                *(uint32_t*)(smA + SWZ(off)) = pr;
            }
        }
        #pragma unroll
        for (int c = 0; c < 4; c++) {
            int idx = t + c * 256;
            int dd = idx >> 3, ccx = idx & 7;
            uint4 val = *(const uint4*)(vTb + (size_t)dd * C + jb + ccx * 8);
            uint32_t off = dd * 128 + ccx * 16;
            *(uint4*)(smB + SWZ(off)) = val;
        }
        __syncthreads();
        mma_pass64(suA, suB, cc, rowA, colAg, nh, rowBoff, colBg);
    }

    // ---- rowsum reduce ----
    #pragma unroll
    for (int s = 0; s < 8; s++) {
        float r = rowsum[s];
        #pragma unroll
        for (int off = 16; off; off >>= 1) r += __shfl_down_sync(0xffffffffu, r, off);
        if (lane == 0) srow[w + 8 * s] = r;
    }
    __syncthreads();

    // ---- normalize weighted + stage bf16 into smA (n<64) / smA2 (n>=64) ----
    int quad = lane >> 2, qt = lane & 3;
    int m0 = (mg << 4) + quad;
    float inv0 = 1.0f / srow[m0];
    float inv8 = 1.0f / srow[m0 + 8];
    char* stg = nh ? smA2 : smA;
    #pragma unroll
    for (int nt = 0; nt < 8; nt++) {
        int n0 = (nh << 6) + nt * 8 + 2 * qt;
        float cs0 = scol[n0], cs1 = scol[n0 + 1];
        float w00 = (cs0 + cc[nt][0]) * inv0;
        float w01 = (cs1 + cc[nt][1]) * inv0;
        float w80 = (cs0 + cc[nt][2]) * inv8;
        float w81 = (cs1 + cc[nt][3]) * inv8;
        uint32_t pr0, pr8;
        CVT_BF16X2(pr0, w00, w01);
        CVT_BF16X2(pr8, w80, w81);
        uint32_t col = (nt * 8 + 2 * qt) * 2;   // byte offset within 128B row
        *(uint32_t*)(stg + SWZ(m0 * 128 + col)) = pr0;
        *(uint32_t*)(stg + SWZ((m0 + 8) * 128 + col)) = pr8;
    }

    // ---- weighted @ Wc (hi-only), 2 K-chunks ----
    #pragma unroll
    for (int nt = 0; nt < 8; nt++)
        #pragma unroll
        for (int r = 0; r < 4; r++) cc[nt][r] = 0.f;

    #pragma unroll 1
    for (int c = 0; c < 2; c++) {
        __syncthreads();
        #pragma unroll
        for (int c2 = 0; c2 < 4; c2++) {
            int idx = t + c2 * 256;
            int dd = idx >> 3, ccx = idx & 7;
            *(uint4*)(smB + SWZ(dd * 128 + ccx * 16)) =
                *(const uint4*)&g_Wch[dd * 128 + c * 64 + ccx * 8];
        }
        __syncthreads();
        mma_pass64(c ? suA2 : suA, suB, cc, rowA, colAg, nh, rowBoff, colBg);
    }

    // ---- epilogue: out = Pa[i] + Pb[r0] + Pc[r1] + bc3 + cc  (or g_beW + cc) ----
    int r0g = i0 + m0;
    size_t bb = (size_t)b * C * D;
    const float* m1 = g_mx + bb;
    const float* m2 = g_mx + BCD + bb;
    const float* m3 = g_mx + 2 * BCD + bb;
    float* ob = out + bb;

    #pragma unroll
    for (int half = 0; half < 2; half++) {
        int rg = r0g + half * 8;
        int loc = rg - i0;
        if (rg < CM2) {
            int2 rr = srel[loc];
            const float* pa = m1 + (size_t)rg * D;
            const float* pb = m2 + (size_t)rr.x * D;
            const float* pc = m3 + (size_t)rr.y * D;
            #pragma unroll
            for (int nt = 0; nt < 8; nt++) {
                int n0 = (nh << 6) + nt * 8 + 2 * qt;
                float2 a2 = *(const float2*)(pa + n0);
                float2 b2 = *(const float2*)(pb + n0);
                float2 c2v = *(const float2*)(pc + n0);
                float vx = a2.x + b2.x + c2v.x + sb3[n0] + cc[nt][2 * half];
                float vy = a2.y + b2.y + c2v.y + sb3[n0 + 1] + cc[nt][2 * half + 1];
                *(float2*)&ob[(size_t)rg * D + n0] = make_float2(vx, vy);
            }
        } else {
            const float* pe = g_beW + ((size_t)b * 2 + (rg - CM2)) * D;
            #pragma unroll
            for (int nt = 0; nt < 8; nt++) {
                int n0 = (nh << 6) + nt * 8 + 2 * qt;
                float2 ev = *(const float2*)(pe + n0);
                *(float2*)&ob[(size_t)rg * D + n0] =
                    make_float2(ev.x + cc[nt][2 * half],
                                ev.y + cc[nt][2 * half + 1]);
            }
        }
    }
}

// ---------------- launch ----------------
extern "C" void kernel_launch(void* const* d_in, const int* in_sizes, int n_in,
                              void* d_out, int out_size) {
    const float* ops      = (const float*)d_in[0];
    const int*   rel      = (const int*)d_in[1];
    const int*   bidx     = (const int*)d_in[2];
    const int*   eidx     = (const int*)d_in[3];
    const float* mask     = (const float*)d_in[4];
    const float* W_begin  = (const float*)d_in[5];
    const float* b_begin  = (const float*)d_in[6];
    const float* W_end    = (const float*)d_in[7];
    const float* b_end    = (const float*)d_in[8];
    const float* W_mix3   = (const float*)d_in[9];
    const float* b_mix3   = (const float*)d_in[10];
    const float* W_qkv    = (const float*)d_in[11];
    const float* b_qkv    = (const float*)d_in[12];
    const float* w_score  = (const float*)d_in[13];
    const float* b_score  = (const float*)d_in[14];
    const float* W_out    = (const float*)d_in[15];
    const float* b_out    = (const float*)d_in[16];
    const float* W_mix2   = (const float*)d_in[17];
    const float* b_mix2   = (const float*)d_in[18];
    float* out = (float*)d_out;

    static bool attr_set = false;
    if (!attr_set) {
        cudaFuncSetAttribute(k_gemm, cudaFuncAttributeMaxDynamicSharedMemorySize, SMEM_MMA2);
        attr_set = true;
    }

    k_pre<<<161, 128>>>(W_qkv, b_qkv, w_score, b_score, W_out, b_out,
                        W_mix2, b_mix2, W_mix3, b_mix3);
    k_gemm<<<1024 + 2 * B, 256, SMEM_MMA2>>>(ops, b_qkv, bidx, eidx,
                                             W_begin, b_begin, W_end, b_end, W_mix2);
    k_attn<<<256, 256>>>(mask, rel, out);
}

// round 16
// speedup vs baseline: 5.2524x; 1.0179x over previous
#include <cuda_runtime.h>
#include <cuda_bf16.h>
#include <cstdint>

#define B 8
#define C 2048
#define D 128
#define J 128
#define CM2 (C - 2)   // 2046
#define BCD (B * C * D)

// ---------------- scratch (device globals) ----------------
__device__ __align__(16) __nv_bfloat16 g_vT[B * D * C];   // v bf16 transposed [b][d][j]
__device__ __align__(16) float g_mx[3 * BCD];             // Pa / Pb / Pc = ops@(W3x@W2a)
__device__ __align__(16) float g_beW[B * 2 * D];          // (begin/end)@W_mix2[:D] + bc0
__device__ float g_colsum[B * D];
__device__ float g_sq[B * C];
__device__ float g_sk[B * C];
__device__ float g_uq[D];
__device__ float g_uk[D];
__device__ float g_c[2];
__device__ float g_bc0[D];
__device__ float g_bc3[D];
// split-bf16 transposed weights
__device__ __align__(16) __nv_bfloat16 g_Wbh[512 * D];    // [W3a'|W3b'|W3c'|Wv] as [n][k]
__device__ __align__(16) __nv_bfloat16 g_Wbl[512 * D];
__device__ __align__(16) __nv_bfloat16 g_Wch[D * D];      // Wc as [n][k], hi only

// ---------------- helpers ----------------
__device__ __forceinline__ uint32_t smem_u32(const void* p) {
    uint32_t a;
    asm("{ .reg .u64 tmp; cvta.to.shared.u64 tmp, %1; cvt.u32.u64 %0, tmp; }"
        : "=r"(a) : "l"(p));
    return a;
}
#define CVT_BF16X2(res, a, b) \
    asm("cvt.rn.satfinite.bf16x2.f32 %0, %1, %2;" : "=r"(res) : "f"(b), "f"(a))
#define SWZ(x) ((x) ^ (((x) >> 3) & 0x70))

__device__ __forceinline__ void ldm_x4(uint32_t& r0, uint32_t& r1, uint32_t& r2,
                                       uint32_t& r3, uint32_t addr) {
    asm volatile("ldmatrix.sync.aligned.m8n8.x4.shared.b16 {%0,%1,%2,%3}, [%4];"
                 : "=r"(r0), "=r"(r1), "=r"(r2), "=r"(r3) : "r"(addr));
}
__device__ __forceinline__ void mma16816(float* c, uint32_t a0, uint32_t a1,
                                         uint32_t a2, uint32_t a3,
                                         uint32_t b0, uint32_t b1) {
    asm volatile(
        "mma.sync.aligned.m16n8k16.row.col.f32.bf16.bf16.f32 "
        "{%0,%1,%2,%3}, {%4,%5,%6,%7}, {%8,%9}, {%0,%1,%2,%3};"
        : "+f"(c[0]), "+f"(c[1]), "+f"(c[2]), "+f"(c[3])
        : "r"(a0), "r"(a1), "r"(a2), "r"(a3), "r"(b0), "r"(b1));
}
__device__ __forceinline__ void split2(float x0, float x1, uint32_t& hp, uint32_t& lp) {
    CVT_BF16X2(hp, x0, x1);
    __nv_bfloat162 hv = *reinterpret_cast<__nv_bfloat162*>(&hp);
    float f0 = __bfloat162float(hv.x), f1 = __bfloat162float(hv.y);
    CVT_BF16X2(lp, x0 - f0, x1 - f1);
}
// one K=64 pass: warp (mg, nh) computes 16m x 64n, A tile 64 rows
__device__ __forceinline__ void mma_pass64(uint32_t suA, uint32_t suB, float cc[8][4],
                                           int rowA, int colAg, int nh,
                                           int rowBoff, int colBg) {
    #pragma unroll
    for (int ks = 0; ks < 4; ks++) {
        uint32_t a0, a1, a2, a3;
        ldm_x4(a0, a1, a2, a3, suA + SWZ(rowA * 128 + ks * 32 + colAg));
        #pragma unroll
        for (int nt = 0; nt < 8; nt += 2) {
            uint32_t b0, b1, b2, b3;
            int rowB = (nh << 6) + nt * 8 + rowBoff;
            ldm_x4(b0, b1, b2, b3, suB + SWZ(rowB * 128 + ks * 32 + colBg));
            mma16816(cc[nt],     a0, a1, a2, a3, b0, b1);
            mma16816(cc[nt + 1], a0, a1, a2, a3, b2, b3);
        }
    }
}

#define SMEM_MMA2 (49152 + 1024)

// ---------------- K0: folded + split/transposed weights ----------------
// grid 161, block 128
__global__ void k_pre(const float* __restrict__ W_qkv, const float* __restrict__ b_qkv,
                      const float* __restrict__ w_score, const float* __restrict__ b_score,
                      const float* __restrict__ W_out, const float* __restrict__ b_out,
                      const float* __restrict__ W_mix2, const float* __restrict__ b_mix2,
                      const float* __restrict__ W_mix3, const float* __restrict__ b_mix3) {
    int t = threadIdx.x;
    int blk = blockIdx.x;
    __shared__ __align__(16) float srow[4][D];

    if (blk < 32 || (blk >= 33 && blk < 129)) {
        bool isWc = (blk < 32);
        int kr0 = isWc ? blk * 4 : (blk - 33) * 4;
        const float* Wsrc = isWc ? W_out : W_mix3;
        const float* W2base = isWc ? (W_mix2 + (size_t)D * D) : W_mix2;
        #pragma unroll
        for (int j = 0; j < 4; j++)
            srow[j][t] = Wsrc[(size_t)(kr0 + j) * D + t];
        __syncthreads();
        float a0 = 0.f, a1 = 0.f, a2 = 0.f, a3 = 0.f;
        #pragma unroll
        for (int m0 = 0; m0 < 128; m0 += 16) {
            float wbuf[16];
            #pragma unroll
            for (int j = 0; j < 16; j++)
                wbuf[j] = W2base[(size_t)(m0 + j) * D + t];
            #pragma unroll
            for (int j = 0; j < 16; j++) {
                float w2 = wbuf[j];
                a0 += srow[0][m0 + j] * w2;
                a1 += srow[1][m0 + j] * w2;
                a2 += srow[2][m0 + j] * w2;
                a3 += srow[3][m0 + j] * w2;
            }
        }
        float accs[4] = {a0, a1, a2, a3};
        if (isWc) {
            #pragma unroll
            for (int j = 0; j < 4; j++)
                g_Wch[t * 128 + kr0 + j] = __float2bfloat16(accs[j]);
        } else {
            #pragma unroll
            for (int j = 0; j < 4; j++) {
                int kr = kr0 + j;
                int x = kr >> 7, k = kr & 127;
                __nv_bfloat16 h = __float2bfloat16(accs[j]);
                g_Wbh[(x * 128 + t) * 128 + k] = h;
                g_Wbl[(x * 128 + t) * 128 + k] =
                    __float2bfloat16(accs[j] - __bfloat162float(h));
            }
        }
    } else if (blk == 32) {
        __shared__ float sbm[D], sbo[D];
        sbm[t] = b_mix3[t];
        sbo[t] = b_out[t];
        __syncthreads();
        float bc0 = b_mix2[t];
        float bc3 = 0.f;
        #pragma unroll
        for (int m0 = 0; m0 < 128; m0 += 8) {
            float wa[8], wb[8];
            #pragma unroll
            for (int j = 0; j < 8; j++) {
                wa[j] = W_mix2[(size_t)(m0 + j) * D + t];
                wb[j] = W_mix2[(size_t)(D + m0 + j) * D + t];
            }
            #pragma unroll
            for (int j = 0; j < 8; j++) {
                bc3 += sbm[m0 + j] * wa[j];
                bc0 += sbo[m0 + j] * wb[j];
            }
        }
        g_bc0[t] = bc0;
        g_bc3[t] = bc3 + bc0;
        #pragma unroll
        for (int i = t; i < B * D; i += 128) g_colsum[i] = 0.f;
        __shared__ float s1[D], s2[D];
        s1[t] = b_qkv[t] * w_score[t];
        s2[t] = b_qkv[D + t] * w_score[D + t];
        __syncthreads();
        for (int off = 64; off; off >>= 1) {
            if (t < off) { s1[t] += s1[t + off]; s2[t] += s2[t + off]; }
            __syncthreads();
        }
        if (t == 0) { g_c[0] = s1[0]; g_c[1] = s2[0] + b_score[0]; }
    } else if (blk < 145) {
        int k0 = (blk - 129) * 8;
        float wv[8];
        #pragma unroll
        for (int j = 0; j < 8; j++)
            wv[j] = W_qkv[(k0 + j) * 3 * D + 2 * D + t];
        #pragma unroll
        for (int j = 0; j < 8; j++) {
            int k = k0 + j;
            __nv_bfloat16 h = __float2bfloat16(wv[j]);
            g_Wbh[(384 + t) * 128 + k] = h;
            g_Wbl[(384 + t) * 128 + k] = __float2bfloat16(wv[j] - __bfloat162float(h));
        }
    } else {
        __shared__ float sws[2 * D];
        sws[t] = w_score[t];
        sws[D + t] = w_score[D + t];
        __syncthreads();
        int row = (blk - 145) * 8 + (t >> 4);
        int seg = t & 15;
        const float* qr = W_qkv + (size_t)row * 3 * D;
        float4 qa = *(const float4*)(qr + seg * 8);
        float4 qb = *(const float4*)(qr + seg * 8 + 4);
        float4 ka = *(const float4*)(qr + D + seg * 8);
        float4 kb = *(const float4*)(qr + D + seg * 8 + 4);
        float4 w0 = *(const float4*)&sws[seg * 8];
        float4 w1 = *(const float4*)&sws[seg * 8 + 4];
        float4 w2 = *(const float4*)&sws[D + seg * 8];
        float4 w3 = *(const float4*)&sws[D + seg * 8 + 4];
        float uq = qa.x * w0.x + qa.y * w0.y + qa.z * w0.z + qa.w * w0.w
                 + qb.x * w1.x + qb.y * w1.y + qb.z * w1.z + qb.w * w1.w;
        float uk = ka.x * w2.x + ka.y * w2.y + ka.z * w2.z + ka.w * w2.w
                 + kb.x * w3.x + kb.y * w3.y + kb.z * w3.z + kb.w * w3.w;
        #pragma unroll
        for (int off = 8; off; off >>= 1) {
            uq += __shfl_down_sync(0xffffffffu, uq, off);
            uk += __shfl_down_sync(0xffffffffu, uk, off);
        }
        if (seg == 0) { g_uq[row] = uq; g_uk[row] = uk; }
    }
}

// ---------------- K1: big GEMM ops @ [W3a'|W3b'|W3c'|Wv] + begin/end side blocks ----------------
// grid 1024+16, block 256, dyn smem 48KB, occ 2
__global__ void __launch_bounds__(256, 2) k_gemm(
    const float* __restrict__ ops, const float* __restrict__ b_qkv,
    const int* __restrict__ bidx, const int* __restrict__ eidx,
    const float* __restrict__ W_begin, const float* __restrict__ b_begin,
    const float* __restrict__ W_end, const float* __restrict__ b_end,
    const float* __restrict__ W_mix2) {
    __shared__ float sbv[128];
    __shared__ float suq[128], suk[128];
    extern __shared__ __align__(16) char dsm[];
    char* smb = (char*)((((uintptr_t)dsm) + 1023) & ~(uintptr_t)1023);
    char* smAh = smb;
    char* smAl = smb + 8192;
    char* smBh = smb + 16384;
    char* smBl = smb + 32768;
    uint32_t suAh = smem_u32(smAh), suAl = smem_u32(smAl);
    uint32_t suBh = smem_u32(smBh), suBl = smem_u32(smBl);

    int blk = blockIdx.x;
    int t = threadIdx.x;

    if (blk >= 1024) {
        int e = blk - 1024;
        int b = e >> 1, which = e & 1;
        const int* idx = which ? eidx : bidx;
        if (t < 128) {
            float s = 0.f;
            for (int j = 0; j < J; j++)
                s += ops[((size_t)b * C + idx[b * J + j]) * D + t];
            suq[t] = s * (1.0f / (float)J);
        }
        __syncthreads();
        if (t < 128) {
            const float* W = which ? W_end : W_begin;
            const float* bbp = which ? b_end : b_begin;
            float acc = bbp[t];
            #pragma unroll 8
            for (int k = 0; k < D; k++) acc += suq[k] * W[k * D + t];
            suk[t] = acc;
        }
        __syncthreads();
        if (t < 128) {
            float acc2 = g_bc0[t];
            #pragma unroll 8
            for (int k = 0; k < D; k++) acc2 += suk[k] * W_mix2[k * D + t];
            g_beW[((size_t)b * 2 + which) * D + t] = acc2;
        }
        return;
    }

    int mt = blk >> 2, ng = blk & 3;
    int b = mt >> 5;
    int i0 = (mt & 31) * 64;
    int w = t >> 5, lane = t & 31;

    if (ng == 3 && t < 128) sbv[t] = b_qkv[2 * D + t];
    if (ng == 0 && t < 128) { suq[t] = g_uq[t]; suk[t] = g_uk[t]; }
    __syncthreads();

    float cc[8][4];
    #pragma unroll
    for (int nt = 0; nt < 8; nt++)
        #pragma unroll
        for (int r = 0; r < 4; r++) cc[nt][r] = 0.f;

    int l8 = lane & 7, grp = lane >> 3;
    int mg = w >> 1, nh = w & 1;
    int rowA = (mg << 4) + l8 + ((grp & 1) << 3);
    int colAg = (grp >> 1) << 4;
    int rowBoff = l8 + ((grp >> 1) << 3);
    int colBg = (grp & 1) << 4;

    int r = t >> 2, h = t & 3;   // 4 threads per A row
    int rowoff = r * 128 + h * 32;
    float dq = 0.f, dk = 0.f;

    #pragma unroll 1
    for (int c = 0; c < 2; c++) {
        if (c) __syncthreads();
        const float4* src = (const float4*)
            (ops + ((size_t)b * C + i0 + r) * D + c * 64 + h * 16);
        #pragma unroll
        for (int q = 0; q < 4; q++) {
            float4 v = src[q];
            if (ng == 0) {
                float4 u4 = *(const float4*)&suq[c * 64 + h * 16 + q * 4];
                float4 k4 = *(const float4*)&suk[c * 64 + h * 16 + q * 4];
                dq += v.x * u4.x + v.y * u4.y + v.z * u4.z + v.w * u4.w;
                dk += v.x * k4.x + v.y * k4.y + v.z * k4.z + v.w * k4.w;
            }
            uint32_t h0, h1, l0, l1;
            split2(v.x, v.y, h0, l0);
            split2(v.z, v.w, h1, l1);
            uint32_t off = rowoff + q * 8;
            *(uint2*)(smAh + SWZ(off)) = make_uint2(h0, h1);
            *(uint2*)(smAl + SWZ(off)) = make_uint2(l0, l1);
        }
        #pragma unroll
        for (int c2 = 0; c2 < 4; c2++) {
            int idx = t + c2 * 256;
            int dd = idx >> 3, ccx = idx & 7;
            uint32_t off = dd * 128 + ccx * 16;
            int gsrc = (ng * 128 + dd) * 128 + c * 64 + ccx * 8;
            *(uint4*)(smBh + SWZ(off)) = *(const uint4*)&g_Wbh[gsrc];
            if (ng < 3)
                *(uint4*)(smBl + SWZ(off)) = *(const uint4*)&g_Wbl[gsrc];
        }
        __syncthreads();
        mma_pass64(suAh, suBh, cc, rowA, colAg, nh, rowBoff, colBg);
        if (ng < 3) {
            mma_pass64(suAh, suBl, cc, rowA, colAg, nh, rowBoff, colBg);
            mma_pass64(suAl, suBh, cc, rowA, colAg, nh, rowBoff, colBg);
        }
    }

    if (ng == 0) {
        dq += __shfl_xor_sync(0xffffffffu, dq, 1);
        dk += __shfl_xor_sync(0xffffffffu, dk, 1);
        dq += __shfl_xor_sync(0xffffffffu, dq, 2);
        dk += __shfl_xor_sync(0xffffffffu, dk, 2);
        if (h == 0) {
            int row = b * C + i0 + r;
            g_sq[row] = dq + g_c[0];
            g_sk[row] = dk + g_c[1];
        }
    }

    int quad = lane >> 2, qt = lane & 3;
    if (ng < 3) {
        float* ob = g_mx + (size_t)ng * BCD + (size_t)b * C * D;
        int r0g = i0 + (mg << 4) + quad;
        #pragma unroll
        for (int nt = 0; nt < 8; nt++) {
            int n0 = (nh << 6) + nt * 8 + 2 * qt;
            *(float2*)&ob[(size_t)r0g * D + n0] = make_float2(cc[nt][0], cc[nt][1]);
            *(float2*)&ob[(size_t)(r0g + 8) * D + n0] = make_float2(cc[nt][2], cc[nt][3]);
        }
    } else {
        __syncthreads();
        __nv_bfloat16* vst = (__nv_bfloat16*)smb;   // [128 n][64 m] = 16KB
        int m0 = (mg << 4) + quad, m8 = m0 + 8;
        #pragma unroll
        for (int nt = 0; nt < 8; nt++) {
            int n0 = (nh << 6) + nt * 8 + 2 * qt;
            float vb0 = sbv[n0], vb1 = sbv[n0 + 1];
            vst[n0 * 64 + m0]       = __float2bfloat16(cc[nt][0] + vb0);
            vst[(n0 + 1) * 64 + m0] = __float2bfloat16(cc[nt][1] + vb1);
            vst[n0 * 64 + m8]       = __float2bfloat16(cc[nt][2] + vb0);
            vst[(n0 + 1) * 64 + m8] = __float2bfloat16(cc[nt][3] + vb1);
        }
        __syncthreads();
        int n = t >> 1, hh = t & 1;
        const uint4* srcv = (const uint4*)(vst + n * 64 + hh * 32);
        uint4* dstv = (uint4*)(g_vT + ((size_t)b * D + n) * C + i0 + hh * 32);
        #pragma unroll
        for (int q = 0; q < 4; q++) dstv[q] = srcv[q];
        if (t < 128) {
            float s = 0.f;
            #pragma unroll 16
            for (int m = 0; m < 64; m++) s += __bfloat162float(vst[t * 64 + m]);
            atomicAdd(&g_colsum[b * D + t], s);
        }
    }
}

// ---------------- K2: attention HMMA + fused weighted@Wc + gather-add epilogue ----------------
// grid 256, block 256, occ 2; mask loads software-pipelined
__global__ void __launch_bounds__(256, 2) k_attn(const float* __restrict__ mask,
                                                 const int* __restrict__ rel,
                                                 float* __restrict__ out) {
    __shared__ __align__(128) char smA[64 * 128];
    __shared__ __align__(128) char smA2[64 * 128];
    __shared__ __align__(128) char smB[128 * 128];
    __shared__ float ssq[64];
    __shared__ float srow[64];
    __shared__ float scol[128];
    __shared__ float sb3[128];
    __shared__ int2 srel[64];

    int t = threadIdx.x;
    int blk = blockIdx.x;
    int w = t >> 5, lane = t & 31;
    int b = blk >> 5;
    int i0 = (blk & 31) * 64;
    int base = b * C;

    uint32_t suA = smem_u32(smA);
    uint32_t suA2 = smem_u32(smA2);
    uint32_t suB = smem_u32(smB);

    if (t < 64) {
        ssq[t] = g_sq[base + i0 + t];
        int ig = i0 + t;
        srel[t] = (ig < CM2) ? *(const int2*)&rel[((size_t)b * CM2 + ig) * 2]
                             : make_int2(0, 0);
    }
    if (t < 128) { scol[t] = g_colsum[b * D + t]; sb3[t] = g_bc3[t]; }

    float rowsum[8];
    #pragma unroll
    for (int s = 0; s < 8; s++) rowsum[s] = 0.f;

    float cc[8][4];
    #pragma unroll
    for (int nt = 0; nt < 8; nt++)
        #pragma unroll
        for (int r = 0; r < 4; r++) cc[nt][r] = 0.f;

    const __nv_bfloat16* vTb = g_vT + (size_t)b * D * C;

    int l8 = lane & 7, grp = lane >> 3;
    int mg = w >> 1, nh = w & 1;
    int rowA = (mg << 4) + l8 + ((grp & 1) << 3);
    int colAg = (grp >> 1) << 4;
    int rowBoff = l8 + ((grp >> 1) << 3);
    int colBg = (grp & 1) << 4;

    // ---- pipelined preload of mask/sk for tile 0 ----
    const float* mbase = mask + (size_t)(base + i0 + w) * C + 2 * lane;
    float2 sk2 = *(const float2*)&g_sk[base + 2 * lane];
    float2 mk[8];
    #pragma unroll
    for (int s = 0; s < 8; s++)
        mk[s] = *(const float2*)(mbase + (size_t)(8 * s) * C);

    // ---- attention mainloop ----
    for (int i = 0; i < C / 64; i++) {
        __syncthreads();
        // probs from prefetched regs
        #pragma unroll
        for (int s = 0; s < 8; s++) {
            int row = w + 8 * s;
            float q = ssq[row];
            float x0 = q + sk2.x; x0 = (x0 >= 0.f) ? x0 : 0.01f * x0; x0 *= mk[s].x;
            float x1 = q + sk2.y; x1 = (x1 >= 0.f) ? x1 : 0.01f * x1; x1 *= mk[s].y;
            float p0 = __expf(x0), p1 = __expf(x1);
            rowsum[s] += p0 + p1;
            uint32_t pr; CVT_BF16X2(pr, p0 - 1.f, p1 - 1.f);
            uint32_t off = row * 128 + lane * 4;
            *(uint32_t*)(smA + SWZ(off)) = pr;
        }
        // B tile: vT [128 d][64 j]
        int jb = i * 64;
        #pragma unroll
        for (int c = 0; c < 4; c++) {
            int idx = t + c * 256;
            int dd = idx >> 3, ccx = idx & 7;
            uint4 val = *(const uint4*)(vTb + (size_t)dd * C + jb + ccx * 8);
            uint32_t off = dd * 128 + ccx * 16;
            *(uint4*)(smB + SWZ(off)) = val;
        }
        __syncthreads();
        // prefetch next tile's mask + sk (overlaps with MMA below)
        if (i + 1 < C / 64) {
            int jn = (i + 1) * 64;
            sk2 = *(const float2*)&g_sk[base + jn + 2 * lane];
            #pragma unroll
            for (int s = 0; s < 8; s++)
                mk[s] = *(const float2*)(mbase + jn + (size_t)(8 * s) * C);
        }
        mma_pass64(suA, suB, cc, rowA, colAg, nh, rowBoff, colBg);
    }

    // ---- rowsum reduce ----
    #pragma unroll
    for (int s = 0; s < 8; s++) {
        float r = rowsum[s];
        #pragma unroll
        for (int off = 16; off; off >>= 1) r += __shfl_down_sync(0xffffffffu, r, off);
        if (lane == 0) srow[w + 8 * s] = r;
    }
    __syncthreads();

    // ---- normalize weighted + stage bf16 into smA (n<64) / smA2 (n>=64) ----
    int quad = lane >> 2, qt = lane & 3;
    int m0 = (mg << 4) + quad;
    float inv0 = 1.0f / srow[m0];
    float inv8 = 1.0f / srow[m0 + 8];
    char* stg = nh ? smA2 : smA;
    #pragma unroll
    for (int nt = 0; nt < 8; nt++) {
        int n0 = (nh << 6) + nt * 8 + 2 * qt;
        float cs0 = scol[n0], cs1 = scol[n0 + 1];
        float w00 = (cs0 + cc[nt][0]) * inv0;
        float w01 = (cs1 + cc[nt][1]) * inv0;
        float w80 = (cs0 + cc[nt][2]) * inv8;
        float w81 = (cs1 + cc[nt][3]) * inv8;
        uint32_t pr0, pr8;
        CVT_BF16X2(pr0, w00, w01);
        CVT_BF16X2(pr8, w80, w81);
        uint32_t col = (nt * 8 + 2 * qt) * 2;
        *(uint32_t*)(stg + SWZ(m0 * 128 + col)) = pr0;
        *(uint32_t*)(stg + SWZ((m0 + 8) * 128 + col)) = pr8;
    }

    // ---- weighted @ Wc (hi-only), 2 K-chunks ----
    #pragma unroll
    for (int nt = 0; nt < 8; nt++)
        #pragma unroll
        for (int r = 0; r < 4; r++) cc[nt][r] = 0.f;

    #pragma unroll 1
    for (int c = 0; c < 2; c++) {
        __syncthreads();
        #pragma unroll
        for (int c2 = 0; c2 < 4; c2++) {
            int idx = t + c2 * 256;
            int dd = idx >> 3, ccx = idx & 7;
            *(uint4*)(smB + SWZ(dd * 128 + ccx * 16)) =
                *(const uint4*)&g_Wch[dd * 128 + c * 64 + ccx * 8];
        }
        __syncthreads();
        mma_pass64(c ? suA2 : suA, suB, cc, rowA, colAg, nh, rowBoff, colBg);
    }

    // ---- epilogue ----
    int r0g = i0 + m0;
    size_t bb = (size_t)b * C * D;
    const float* m1 = g_mx + bb;
    const float* m2 = g_mx + BCD + bb;
    const float* m3 = g_mx + 2 * BCD + bb;
    float* ob = out + bb;

    #pragma unroll
    for (int half = 0; half < 2; half++) {
        int rg = r0g + half * 8;
        int loc = rg - i0;
        if (rg < CM2) {
            int2 rr = srel[loc];
            const float* pa = m1 + (size_t)rg * D;
            const float* pb = m2 + (size_t)rr.x * D;
            const float* pc = m3 + (size_t)rr.y * D;
            #pragma unroll
            for (int nt = 0; nt < 8; nt++) {
                int n0 = (nh << 6) + nt * 8 + 2 * qt;
                float2 a2 = *(const float2*)(pa + n0);
                float2 b2 = *(const float2*)(pb + n0);
                float2 c2v = *(const float2*)(pc + n0);
                float vx = a2.x + b2.x + c2v.x + sb3[n0] + cc[nt][2 * half];
                float vy = a2.y + b2.y + c2v.y + sb3[n0 + 1] + cc[nt][2 * half + 1];
                *(float2*)&ob[(size_t)rg * D + n0] = make_float2(vx, vy);
            }
        } else {
            const float* pe = g_beW + ((size_t)b * 2 + (rg - CM2)) * D;
            #pragma unroll
            for (int nt = 0; nt < 8; nt++) {
                int n0 = (nh << 6) + nt * 8 + 2 * qt;
                float2 ev = *(const float2*)(pe + n0);
                *(float2*)&ob[(size_t)rg * D + n0] =
                    make_float2(ev.x + cc[nt][2 * half],
                                ev.y + cc[nt][2 * half + 1]);
            }
        }
    }
}

// ---------------- launch ----------------
extern "C" void kernel_launch(void* const* d_in, const int* in_sizes, int n_in,
                              void* d_out, int out_size) {
    const float* ops      = (const float*)d_in[0];
    const int*   rel      = (const int*)d_in[1];
    const int*   bidx     = (const int*)d_in[2];
    const int*   eidx     = (const int*)d_in[3];
    const float* mask     = (const float*)d_in[4];
    const float* W_begin  = (const float*)d_in[5];
    const float* b_begin  = (const float*)d_in[6];
    const float* W_end    = (const float*)d_in[7];
    const float* b_end    = (const float*)d_in[8];
    const float* W_mix3   = (const float*)d_in[9];
    const float* b_mix3   = (const float*)d_in[10];
    const float* W_qkv    = (const float*)d_in[11];
    const float* b_qkv    = (const float*)d_in[12];
    const float* w_score  = (const float*)d_in[13];
    const float* b_score  = (const float*)d_in[14];
    const float* W_out    = (const float*)d_in[15];
    const float* b_out    = (const float*)d_in[16];
    const float* W_mix2   = (const float*)d_in[17];
    const float* b_mix2   = (const float*)d_in[18];
    float* out = (float*)d_out;

    static bool attr_set = false;
    if (!attr_set) {
        cudaFuncSetAttribute(k_gemm, cudaFuncAttributeMaxDynamicSharedMemorySize, SMEM_MMA2);
        attr_set = true;
    }

    k_pre<<<161, 128>>>(W_qkv, b_qkv, w_score, b_score, W_out, b_out,
                        W_mix2, b_mix2, W_mix3, b_mix3);
    k_gemm<<<1024 + 2 * B, 256, SMEM_MMA2>>>(ops, b_qkv, bidx, eidx,
                                             W_begin, b_begin, W_end, b_end, W_mix2);
    k_attn<<<256, 256>>>(mask, rel, out);
}